// round 1
// baseline (speedup 1.0000x reference)
#include <cuda_runtime.h>
#include <cstdint>
#include <math.h>

#define BB 8
#define NN 2048
#define FIN 256
#define FOUT 128
#define BN (BB*NN)   // 16384 rows total

// Scratch (static device arrays; allocation is forbidden)
__device__ float g_Wh[(size_t)BN * FOUT];           // 8.4 MB
__device__ float g_s1[BN], g_s2[BN];
__device__ float g_E1[BN], g_E2[BN], g_F1[BN], g_F2[BN];

// ---------------------------------------------------------------------------
// Kernel 1: Wh = h @ W   [BN,256] x [256,128] -> [BN,128]
// Block: 128 threads (one per output column), 16 rows per block.
// ---------------------------------------------------------------------------
__global__ __launch_bounds__(128) void k_wh(const float* __restrict__ h,
                                            const float* __restrict__ W) {
    __shared__ float hs[16][FIN];
    const int t = threadIdx.x;
    const size_t row0 = (size_t)blockIdx.x * 16;

    // stage h tile: 16*256 floats = 1024 float4, 128 threads x 8
    const float4* hp = (const float4*)(h + row0 * FIN);
    float4* hs4 = (float4*)hs;
#pragma unroll
    for (int v = 0; v < 8; v++) hs4[t + v * 128] = hp[t + v * 128];
    __syncthreads();

    float acc[16];
#pragma unroll
    for (int r = 0; r < 16; r++) acc[r] = 0.f;

    for (int k = 0; k < FIN; k += 4) {
        const float w0 = W[(k + 0) * FOUT + t];
        const float w1 = W[(k + 1) * FOUT + t];
        const float w2 = W[(k + 2) * FOUT + t];
        const float w3 = W[(k + 3) * FOUT + t];
#pragma unroll
        for (int r = 0; r < 16; r++) {
            float4 hv = *(const float4*)&hs[r][k];
            acc[r] = fmaf(hv.x, w0, acc[r]);
            acc[r] = fmaf(hv.y, w1, acc[r]);
            acc[r] = fmaf(hv.z, w2, acc[r]);
            acc[r] = fmaf(hv.w, w3, acc[r]);
        }
    }
#pragma unroll
    for (int r = 0; r < 16; r++) g_Wh[(row0 + r) * FOUT + t] = acc[r];
}

// ---------------------------------------------------------------------------
// Kernel 2: s1 = Wh@a1, s2 = Wh@a2, plus E1=exp(s1), F1=exp(.2*s1), E2, F2.
// One warp per row (lane l owns float4 #l of the 128-float row).
// ---------------------------------------------------------------------------
__global__ __launch_bounds__(256) void k_scores(const float* __restrict__ a) {
    const int gw = (blockIdx.x * 256 + threadIdx.x) >> 5;   // row id
    const int lane = threadIdx.x & 31;

    const float4 v  = ((const float4*)g_Wh)[(size_t)gw * 32 + lane];
    const float4 a1 = ((const float4*)a)[lane];         // a[0:128]
    const float4 a2 = ((const float4*)a)[32 + lane];    // a[128:256]

    float s1 = v.x * a1.x + v.y * a1.y + v.z * a1.z + v.w * a1.w;
    float s2 = v.x * a2.x + v.y * a2.y + v.z * a2.z + v.w * a2.w;
#pragma unroll
    for (int o = 16; o; o >>= 1) {
        s1 += __shfl_xor_sync(0xFFFFFFFFu, s1, o);
        s2 += __shfl_xor_sync(0xFFFFFFFFu, s2, o);
    }
    if (lane == 0) {
        g_s1[gw] = s1;
        g_s2[gw] = s2;
        g_E1[gw] = expf(s1);
        g_F1[gw] = expf(0.2f * s1);
        g_E2[gw] = expf(s2);
        g_F2[gw] = expf(0.2f * s2);
    }
}

// ---------------------------------------------------------------------------
// Kernel 3: fused masked-softmax attention + matmul + ELU.
// Grid (NN/128, BB). 256 threads. Each CTA: 128 i-rows x 128 f-cols.
// Thread (tx,ty): tx=t&15 -> f block [8], ty=t>>4 -> i block [8].
// Weight tile c[128][32] built per j-tile; acc in packed f32x2 registers.
// ---------------------------------------------------------------------------
__global__ __launch_bounds__(256) void k_attn(const int* __restrict__ adj,
                                              float* __restrict__ out) {
    __shared__ float whs[32][FOUT];       // 16 KB
    __shared__ float cs[128][33];         // padded: stride 33 avoids conflicts
    __shared__ float Zp[128][2];

    const int b  = blockIdx.y;
    const int i0 = blockIdx.x * 128;
    const int t  = threadIdx.x;
    const int tx = t & 15, ty = t >> 4;
    const int crow = t >> 1, jh = t & 1;   // c-phase: row, j-half
    const size_t bn = (size_t)b * NN;

    // per-row constants for c-phase
    const float s1r = g_s1[bn + i0 + crow];
    const float E1r = g_E1[bn + i0 + crow];
    const float F1r = g_F1[bn + i0 + crow];
    const float* __restrict__ s2p = g_s2 + bn;
    const float* __restrict__ E2p = g_E2 + bn;
    const float* __restrict__ F2p = g_F2 + bn;

    const int4* __restrict__ adjr =
        (const int4*)(adj + (bn + i0 + crow) * (size_t)NN) + jh * 4;
    const float4* __restrict__ whp = (const float4*)(g_Wh + bn * FOUT);

    unsigned long long acc[8][4];
#pragma unroll
    for (int r = 0; r < 8; r++)
#pragma unroll
        for (int p = 0; p < 4; p++) acc[r][p] = 0ull;

    float Zreg = 0.f;

    for (int jt = 0; jt < NN / 32; jt++) {
        const int j0 = jt * 32;
        __syncthreads();   // previous FMA phase done with whs/cs

        // stage Wh tile [32][128]: 1024 float4, 256 threads x 4
#pragma unroll
        for (int v = 0; v < 4; v++) {
            const int idx = t + v * 256;               // = jr*32 + c4
            ((float4*)whs)[idx] = whp[(size_t)j0 * 32 + idx];
        }

        // compute weight tile c[crow][jh*16 .. jh*16+15]
#pragma unroll
        for (int q = 0; q < 4; q++) {
            const int4 m = adjr[jt * 8 + q];
            const int jb = jh * 16 + q * 4;
            {
                const int j = jb + 0, jg = j0 + j;
                const float w = (s1r + s2p[jg] > 0.f) ? E1r * E2p[jg] : F1r * F2p[jg];
                const float c = (m.x > 0) ? w : 0.f;
                cs[crow][j] = c; Zreg += c;
            }
            {
                const int j = jb + 1, jg = j0 + j;
                const float w = (s1r + s2p[jg] > 0.f) ? E1r * E2p[jg] : F1r * F2p[jg];
                const float c = (m.y > 0) ? w : 0.f;
                cs[crow][j] = c; Zreg += c;
            }
            {
                const int j = jb + 2, jg = j0 + j;
                const float w = (s1r + s2p[jg] > 0.f) ? E1r * E2p[jg] : F1r * F2p[jg];
                const float c = (m.z > 0) ? w : 0.f;
                cs[crow][j] = c; Zreg += c;
            }
            {
                const int j = jb + 3, jg = j0 + j;
                const float w = (s1r + s2p[jg] > 0.f) ? E1r * E2p[jg] : F1r * F2p[jg];
                const float c = (m.w > 0) ? w : 0.f;
                cs[crow][j] = c; Zreg += c;
            }
        }
        __syncthreads();

        // accumulate: acc[r][:] += c[i][jj] * Wh[jj][f]  (packed f32x2)
#pragma unroll 4
        for (int jj = 0; jj < 32; jj++) {
            const ulonglong2 wa = *(const ulonglong2*)&whs[jj][tx * 8];
            const ulonglong2 wb = *(const ulonglong2*)&whs[jj][tx * 8 + 4];
            const unsigned long long wp0 = wa.x, wp1 = wa.y, wp2 = wb.x, wp3 = wb.y;
#pragma unroll
            for (int r = 0; r < 8; r++) {
                const float cv = cs[ty * 8 + r][jj];
                unsigned long long cd;
                asm("mov.b64 %0, {%1, %1};" : "=l"(cd) : "f"(cv));
                asm("fma.rn.f32x2 %0, %1, %2, %0;" : "+l"(acc[r][0]) : "l"(cd), "l"(wp0));
                asm("fma.rn.f32x2 %0, %1, %2, %0;" : "+l"(acc[r][1]) : "l"(cd), "l"(wp1));
                asm("fma.rn.f32x2 %0, %1, %2, %0;" : "+l"(acc[r][2]) : "l"(cd), "l"(wp2));
                asm("fma.rn.f32x2 %0, %1, %2, %0;" : "+l"(acc[r][3]) : "l"(cd), "l"(wp3));
            }
        }
    }

    // row-sum combine (2 partials per row), then normalize + ELU + store
    Zp[crow][jh] = Zreg;
    __syncthreads();

#pragma unroll
    for (int r = 0; r < 8; r++) {
        const int row = ty * 8 + r;
        const float Z = Zp[row][0] + Zp[row][1];
        const float zi = 1.0f / Z;
        float o[8];
#pragma unroll
        for (int p = 0; p < 4; p++) {
            float lo, hi;
            asm("mov.b64 {%0, %1}, %2;" : "=f"(lo), "=f"(hi) : "l"(acc[r][p]));
            lo *= zi; hi *= zi;
            o[2 * p]     = lo > 0.f ? lo : expm1f(lo);
            o[2 * p + 1] = hi > 0.f ? hi : expm1f(hi);
        }
        float4* op = (float4*)(out + (bn + i0 + row) * (size_t)FOUT + tx * 8);
        op[0] = make_float4(o[0], o[1], o[2], o[3]);
        op[1] = make_float4(o[4], o[5], o[6], o[7]);
    }
}

// ---------------------------------------------------------------------------
extern "C" void kernel_launch(void* const* d_in, const int* in_sizes, int n_in,
                              void* d_out, int out_size) {
    // Identify inputs by element count (robust to ordering):
    // h: 4194304, adj: 33554432, W: 32768, a: 256
    const float* h = nullptr; const int* adj = nullptr;
    const float* W = nullptr; const float* a = nullptr;
    for (int i = 0; i < n_in; i++) {
        switch (in_sizes[i]) {
            case 4194304:  h   = (const float*)d_in[i]; break;
            case 33554432: adj = (const int*)d_in[i];   break;
            case 32768:    W   = (const float*)d_in[i]; break;
            case 256:      a   = (const float*)d_in[i]; break;
        }
    }
    float* out = (float*)d_out;

    k_wh<<<BN / 16, 128>>>(h, W);
    k_scores<<<(BN * 32) / 256, 256>>>(a);
    k_attn<<<dim3(NN / 128, BB), 256>>>(adj, out);
}

// round 3
// speedup vs baseline: 1.9219x; 1.9219x over previous
#include <cuda_runtime.h>
#include <cuda_bf16.h>
#include <cstdint>
#include <math.h>

#define BB 8
#define NN 2048
#define FIN 256
#define FOUT 128
#define BN (BB*NN)   // 16384 rows total

#define JT 64                 // j-tile (K of the mma loop)
#define NTILES (NN/JT)        // 32
#define STRIDE 72             // bf16 elems per smem row (144 B) - conflict-free ldmatrix
#define TILE_BYTES (128*STRIDE*2)      // 18432 per tile
#define DSMEM_BYTES (4*TILE_BYTES)     // A_hi, A_lo, B_hi, B_lo = 73728

// Scratch (static device arrays; allocation is forbidden)
__device__ float g_Wh[(size_t)BN * FOUT];                    // fp32, row-major [row][f]
__device__ __nv_bfloat16 g_WhT_hi[(size_t)BB * FOUT * NN];   // [b][f][n] split hi
__device__ __nv_bfloat16 g_WhT_lo[(size_t)BB * FOUT * NN];   // [b][f][n] split lo
__device__ float g_s1[BN], g_s2[BN];
__device__ float g_E1[BN], g_E2[BN], g_F1[BN], g_F2[BN];

// ---------------------------------------------------------------------------
__device__ __forceinline__ uint32_t smem_u32(const void* p) {
    uint32_t a;
    asm("{ .reg .u64 t; cvta.to.shared.u64 t, %1; cvt.u32.u64 %0, t; }"
        : "=r"(a) : "l"(p));
    return a;
}

#define LDSM_X4(r, addr) \
    asm volatile("ldmatrix.sync.aligned.m8n8.x4.shared.b16 {%0,%1,%2,%3}, [%4];" \
        : "=r"((r)[0]), "=r"((r)[1]), "=r"((r)[2]), "=r"((r)[3]) : "r"(addr))

__device__ __forceinline__ void mma16816(float* c, const uint32_t* a, const uint32_t* b) {
    asm volatile(
        "mma.sync.aligned.m16n8k16.row.col.f32.bf16.bf16.f32 "
        "{%0,%1,%2,%3}, {%4,%5,%6,%7}, {%8,%9}, {%0,%1,%2,%3};"
        : "+f"(c[0]), "+f"(c[1]), "+f"(c[2]), "+f"(c[3])
        : "r"(a[0]), "r"(a[1]), "r"(a[2]), "r"(a[3]), "r"(b[0]), "r"(b[1]));
}

// ---------------------------------------------------------------------------
// Kernel 1: Wh = h @ W. Also emits transposed split-bf16 copy for the MMA.
// ---------------------------------------------------------------------------
__global__ __launch_bounds__(128) void k_wh(const float* __restrict__ h,
                                            const float* __restrict__ W) {
    __shared__ float hs[16][FIN];
    const int t = threadIdx.x;
    const size_t row0 = (size_t)blockIdx.x * 16;

    const float4* hp = (const float4*)(h + row0 * FIN);
    float4* hs4 = (float4*)hs;
#pragma unroll
    for (int v = 0; v < 8; v++) hs4[t + v * 128] = hp[t + v * 128];
    __syncthreads();

    float acc[16];
#pragma unroll
    for (int r = 0; r < 16; r++) acc[r] = 0.f;

    for (int k = 0; k < FIN; k += 4) {
        const float w0 = W[(k + 0) * FOUT + t];
        const float w1 = W[(k + 1) * FOUT + t];
        const float w2 = W[(k + 2) * FOUT + t];
        const float w3 = W[(k + 3) * FOUT + t];
#pragma unroll
        for (int r = 0; r < 16; r++) {
            float4 hv = *(const float4*)&hs[r][k];
            acc[r] = fmaf(hv.x, w0, acc[r]);
            acc[r] = fmaf(hv.y, w1, acc[r]);
            acc[r] = fmaf(hv.z, w2, acc[r]);
            acc[r] = fmaf(hv.w, w3, acc[r]);
        }
    }
#pragma unroll
    for (int r = 0; r < 16; r++) g_Wh[(row0 + r) * FOUT + t] = acc[r];

    // transposed split-bf16: g_WhT_*[b][f=t][n0+r]
    const int b  = (int)(row0 >> 11);
    const int n0 = (int)(row0 & 2047);
    const size_t tidx = ((size_t)b * FOUT + t) * NN + n0;
#pragma unroll
    for (int g = 0; g < 2; g++) {
        uint4 hv, lv;
#pragma unroll
        for (int p = 0; p < 4; p++) {
            float a0 = acc[g * 8 + 2 * p], a1 = acc[g * 8 + 2 * p + 1];
            __nv_bfloat162 hb = __floats2bfloat162_rn(a0, a1);
            float r0 = a0 - __bfloat162float(hb.x);
            float r1 = a1 - __bfloat162float(hb.y);
            __nv_bfloat162 lb = __floats2bfloat162_rn(r0, r1);
            ((unsigned*)&hv)[p] = *(unsigned*)&hb;
            ((unsigned*)&lv)[p] = *(unsigned*)&lb;
        }
        *(uint4*)&g_WhT_hi[tidx + g * 8] = hv;
        *(uint4*)&g_WhT_lo[tidx + g * 8] = lv;
    }
}

// ---------------------------------------------------------------------------
// Kernel 2: scores + factored exponentials
// ---------------------------------------------------------------------------
__global__ __launch_bounds__(256) void k_scores(const float* __restrict__ a) {
    const int gw = (blockIdx.x * 256 + threadIdx.x) >> 5;
    const int lane = threadIdx.x & 31;

    const float4 v  = ((const float4*)g_Wh)[(size_t)gw * 32 + lane];
    const float4 a1 = ((const float4*)a)[lane];
    const float4 a2 = ((const float4*)a)[32 + lane];

    float s1 = v.x * a1.x + v.y * a1.y + v.z * a1.z + v.w * a1.w;
    float s2 = v.x * a2.x + v.y * a2.y + v.z * a2.z + v.w * a2.w;
#pragma unroll
    for (int o = 16; o; o >>= 1) {
        s1 += __shfl_xor_sync(0xFFFFFFFFu, s1, o);
        s2 += __shfl_xor_sync(0xFFFFFFFFu, s2, o);
    }
    if (lane == 0) {
        g_s1[gw] = s1;
        g_s2[gw] = s2;
        g_E1[gw] = expf(s1);
        g_F1[gw] = expf(0.2f * s1);
        g_E2[gw] = expf(s2);
        g_F2[gw] = expf(0.2f * s2);
    }
}

// ---------------------------------------------------------------------------
// Kernel 3: fused attention via mma.sync (HMMA) bf16 split 3-product.
// Grid (16, 8), 256 threads. CTA: 128 i x 128 f, 32 j-tiles of 64.
// Warps: wm = w&1 (row 64-half), wn = w>>1 (col 32-group). Warp tile 64x32.
// ---------------------------------------------------------------------------
__global__ __launch_bounds__(256, 1) void k_attn(const int* __restrict__ adj,
                                                 float* __restrict__ out) {
    extern __shared__ char dsm[];
    __shared__ float s_Z[128][2];
    __shared__ float s_Zc[128];

    const int t = threadIdx.x, w = t >> 5, lane = t & 31;
    const int b = blockIdx.y, i0 = blockIdx.x * 128;
    const size_t bn = (size_t)b * NN;

    char* A_hi = dsm;
    char* A_lo = dsm + TILE_BYTES;
    char* B_hi = dsm + 2 * TILE_BYTES;
    char* B_lo = dsm + 3 * TILE_BYTES;
    const uint32_t sA_hi = smem_u32(A_hi);
    const uint32_t sA_lo = smem_u32(A_lo);
    const uint32_t sB_hi = smem_u32(B_hi);
    const uint32_t sB_lo = smem_u32(B_lo);

    // ---- c-phase mapping: row = t>>1 (both i and f role), jh = (t&1)*32 ----
    const int row = t >> 1;
    const int jh  = (t & 1) * 32;

    const float s1r = g_s1[bn + i0 + row];
    const float E1r = g_E1[bn + i0 + row];
    const float F1r = g_F1[bn + i0 + row];
    const float* __restrict__ s2p = g_s2 + bn;
    const float* __restrict__ E2p = g_E2 + bn;
    const float* __restrict__ F2p = g_F2 + bn;
    const int* __restrict__ adjrow = adj + (bn + i0 + row) * (size_t)NN;
    const __nv_bfloat16* __restrict__ whh = g_WhT_hi + ((size_t)b * FOUT + row) * NN;
    const __nv_bfloat16* __restrict__ whl = g_WhT_lo + ((size_t)b * FOUT + row) * NN;

    // ---- mma-phase addressing ----
    const int wm = w & 1, wn = w >> 1;
    // ldmatrix x4 lane address: row (lane&15), k-half (lane>>4)*16B
    const uint32_t aRow = (uint32_t)((wm * 64 + (lane & 15)) * (STRIDE * 2) + (lane >> 4) * 16);
    const uint32_t bRow = (uint32_t)((wn * 32 + (lane & 15)) * (STRIDE * 2) + (lane >> 4) * 16);

    float c[4][4][4];   // [mt][nt][reg]
#pragma unroll
    for (int mt = 0; mt < 4; mt++)
#pragma unroll
        for (int nt = 0; nt < 4; nt++)
#pragma unroll
            for (int r = 0; r < 4; r++) c[mt][nt][r] = 0.f;

    float Zreg = 0.f;

    for (int jt = 0; jt < NTILES; jt++) {
        const int jg0 = jt * JT + jh;
        __syncthreads();   // previous mma phase done reading smem

        // ---- stage B (WhT split, pre-converted) ----
        {
            const uint4* sh = (const uint4*)(whh + jg0);
            const uint4* sl = (const uint4*)(whl + jg0);
            char* bh = B_hi + row * (STRIDE * 2) + jh * 2;
            char* bl = B_lo + row * (STRIDE * 2) + jh * 2;
#pragma unroll
            for (int g = 0; g < 4; g++) {
                *(uint4*)(bh + g * 16) = sh[g];
                *(uint4*)(bl + g * 16) = sl[g];
            }
        }
        // ---- build c tile (fp32), split to bf16 pair ----
        {
            const int4*   am  = (const int4*)(adjrow + jg0);
            const float4* s2v = (const float4*)(s2p + jg0);
            const float4* e2v = (const float4*)(E2p + jg0);
            const float4* f2v = (const float4*)(F2p + jg0);
            float c32[32];
#pragma unroll
            for (int q = 0; q < 8; q++) {
                const int4 m = am[q];
                const float4 s2 = s2v[q], e2 = e2v[q], f2 = f2v[q];
                c32[4*q+0] = (m.x > 0) ? ((s1r + s2.x > 0.f) ? E1r * e2.x : F1r * f2.x) : 0.f;
                c32[4*q+1] = (m.y > 0) ? ((s1r + s2.y > 0.f) ? E1r * e2.y : F1r * f2.y) : 0.f;
                c32[4*q+2] = (m.z > 0) ? ((s1r + s2.z > 0.f) ? E1r * e2.z : F1r * f2.z) : 0.f;
                c32[4*q+3] = (m.w > 0) ? ((s1r + s2.w > 0.f) ? E1r * e2.w : F1r * f2.w) : 0.f;
            }
#pragma unroll
            for (int k = 0; k < 32; k++) Zreg += c32[k];
            char* ah = A_hi + row * (STRIDE * 2) + jh * 2;
            char* al = A_lo + row * (STRIDE * 2) + jh * 2;
#pragma unroll
            for (int g = 0; g < 4; g++) {
                uint4 hv, lv;
#pragma unroll
                for (int p = 0; p < 4; p++) {
                    const float a0 = c32[g*8 + 2*p], a1 = c32[g*8 + 2*p + 1];
                    __nv_bfloat162 hb = __floats2bfloat162_rn(a0, a1);
                    const float r0 = a0 - __bfloat162float(hb.x);
                    const float r1 = a1 - __bfloat162float(hb.y);
                    __nv_bfloat162 lb = __floats2bfloat162_rn(r0, r1);
                    ((unsigned*)&hv)[p] = *(unsigned*)&hb;
                    ((unsigned*)&lv)[p] = *(unsigned*)&lb;
                }
                *(uint4*)(ah + g * 16) = hv;
                *(uint4*)(al + g * 16) = lv;
            }
        }
        __syncthreads();

        // ---- mma phase: 4 k-steps of 16 ----
#pragma unroll
        for (int ks = 0; ks < 4; ks++) {
            const uint32_t kOff = ks * 32;
            uint32_t ah[4][4], al[4][4], bh[4][2], bl[4][2];
#pragma unroll
            for (int mt = 0; mt < 4; mt++) {
                const uint32_t mOff = aRow + mt * 16 * (STRIDE * 2) + kOff;
                LDSM_X4(ah[mt], sA_hi + mOff);
                LDSM_X4(al[mt], sA_lo + mOff);
            }
#pragma unroll
            for (int np = 0; np < 2; np++) {
                const uint32_t nOff = bRow + np * 16 * (STRIDE * 2) + kOff;
                uint32_t q[4];
                LDSM_X4(q, sB_hi + nOff);
                bh[2*np][0] = q[0]; bh[2*np][1] = q[2];
                bh[2*np+1][0] = q[1]; bh[2*np+1][1] = q[3];
                LDSM_X4(q, sB_lo + nOff);
                bl[2*np][0] = q[0]; bl[2*np][1] = q[2];
                bl[2*np+1][0] = q[1]; bl[2*np+1][1] = q[3];
            }
#pragma unroll
            for (int mt = 0; mt < 4; mt++)
#pragma unroll
                for (int nt = 0; nt < 4; nt++) {
                    mma16816(c[mt][nt], ah[mt], bh[nt]);
                    mma16816(c[mt][nt], ah[mt], bl[nt]);
                    mma16816(c[mt][nt], al[mt], bh[nt]);
                }
        }
    }

    // ---- combine Z, then normalize + ELU + store ----
    s_Z[row][t & 1] = Zreg;
    __syncthreads();
    if (t < 128) s_Zc[t] = s_Z[t][0] + s_Z[t][1];
    __syncthreads();

    const int qrow = lane >> 2, qcol = 2 * (lane & 3);
#pragma unroll
    for (int mt = 0; mt < 4; mt++) {
        const int r0 = wm * 64 + mt * 16 + qrow;
        const int r1 = r0 + 8;
        const float zi0 = 1.0f / s_Zc[r0];
        const float zi1 = 1.0f / s_Zc[r1];
        float* op0 = out + (bn + i0 + r0) * (size_t)FOUT;
        float* op1 = out + (bn + i0 + r1) * (size_t)FOUT;
#pragma unroll
        for (int nt = 0; nt < 4; nt++) {
            const int col = wn * 32 + nt * 8 + qcol;
            float x0 = c[mt][nt][0] * zi0;
            float x1 = c[mt][nt][1] * zi0;
            float x2 = c[mt][nt][2] * zi1;
            float x3 = c[mt][nt][3] * zi1;
            float2 v0, v1;
            v0.x = x0 > 0.f ? x0 : expm1f(x0);
            v0.y = x1 > 0.f ? x1 : expm1f(x1);
            v1.x = x2 > 0.f ? x2 : expm1f(x2);
            v1.y = x3 > 0.f ? x3 : expm1f(x3);
            *(float2*)(op0 + col) = v0;
            *(float2*)(op1 + col) = v1;
        }
    }
}

// ---------------------------------------------------------------------------
extern "C" void kernel_launch(void* const* d_in, const int* in_sizes, int n_in,
                              void* d_out, int out_size) {
    const float* h = nullptr; const int* adj = nullptr;
    const float* W = nullptr; const float* a = nullptr;
    for (int i = 0; i < n_in; i++) {
        switch (in_sizes[i]) {
            case 4194304:  h   = (const float*)d_in[i]; break;
            case 33554432: adj = (const int*)d_in[i];   break;
            case 32768:    W   = (const float*)d_in[i]; break;
            case 256:      a   = (const float*)d_in[i]; break;
        }
    }
    float* out = (float*)d_out;

    static bool attr_set = false;
    if (!attr_set) {
        cudaFuncSetAttribute(k_attn, cudaFuncAttributeMaxDynamicSharedMemorySize,
                             DSMEM_BYTES);
        attr_set = true;
    }

    k_wh<<<BN / 16, 128>>>(h, W);
    k_scores<<<(BN * 32) / 256, 256>>>(a);
    k_attn<<<dim3(NN / 128, BB), 256, DSMEM_BYTES>>>(adj, out);
}

// round 4
// speedup vs baseline: 2.2335x; 1.1621x over previous
#include <cuda_runtime.h>
#include <cuda_bf16.h>
#include <cstdint>
#include <math.h>

#define BB 8
#define NN 2048
#define FIN 256
#define FOUT 128
#define BN (BB*NN)   // 16384 rows total

#define JT 64                 // j-tile (K of the mma loop)
#define NTILES (NN/JT)        // 32
#define STRIDE 72             // bf16 elems per smem row (144 B) - conflict-free ldmatrix
#define TILE_BYTES (128*STRIDE*2)        // 18432 per tile
#define STAGE_BYTES (4*TILE_BYTES)       // A_hi, A_lo, B_hi, B_lo = 73728
#define DSMEM_BYTES (2*STAGE_BYTES)      // double buffered = 147456

// Scratch (static device arrays; allocation is forbidden)
__device__ float g_Wh[(size_t)BN * FOUT];                    // fp32, row-major [row][f]
__device__ __nv_bfloat16 g_WhT_hi[(size_t)BB * FOUT * NN];   // [b][f][n] split hi
__device__ __nv_bfloat16 g_WhT_lo[(size_t)BB * FOUT * NN];   // [b][f][n] split lo
__device__ float g_s1[BN], g_s2[BN];
__device__ float g_E1[BN], g_E2[BN], g_F1[BN], g_F2[BN];

// ---------------------------------------------------------------------------
__device__ __forceinline__ uint32_t smem_u32(const void* p) {
    uint32_t a;
    asm("{ .reg .u64 t; cvta.to.shared.u64 t, %1; cvt.u32.u64 %0, t; }"
        : "=r"(a) : "l"(p));
    return a;
}

#define LDSM_X4(r, addr) \
    asm volatile("ldmatrix.sync.aligned.m8n8.x4.shared.b16 {%0,%1,%2,%3}, [%4];" \
        : "=r"((r)[0]), "=r"((r)[1]), "=r"((r)[2]), "=r"((r)[3]) : "r"(addr))

__device__ __forceinline__ void mma16816(float* c, const uint32_t* a, const uint32_t* b) {
    asm volatile(
        "mma.sync.aligned.m16n8k16.row.col.f32.bf16.bf16.f32 "
        "{%0,%1,%2,%3}, {%4,%5,%6,%7}, {%8,%9}, {%0,%1,%2,%3};"
        : "+f"(c[0]), "+f"(c[1]), "+f"(c[2]), "+f"(c[3])
        : "r"(a[0]), "r"(a[1]), "r"(a[2]), "r"(a[3]), "r"(b[0]), "r"(b[1]));
}

// ---------------------------------------------------------------------------
// Kernel 1: Wh = h @ W, register-blocked 4x4. Also emits transposed
// split-bf16 copy for the MMA B operand.
// 128 threads: fq = t&31 -> cols [4fq..4fq+3], rq = t>>5 -> rows [4rq..4rq+3].
// ---------------------------------------------------------------------------
__global__ __launch_bounds__(128) void k_wh(const float* __restrict__ h,
                                            const float* __restrict__ W) {
    __shared__ float hs[16][FIN];
    const int t = threadIdx.x;
    const int fq = t & 31, rq = t >> 5;
    const size_t row0 = (size_t)blockIdx.x * 16;

    const float4* hp = (const float4*)(h + row0 * FIN);
    float4* hs4 = (float4*)hs;
#pragma unroll
    for (int v = 0; v < 8; v++) hs4[t + v * 128] = hp[t + v * 128];
    __syncthreads();

    float acc[4][4];   // [row][col]
#pragma unroll
    for (int r = 0; r < 4; r++)
#pragma unroll
        for (int c = 0; c < 4; c++) acc[r][c] = 0.f;

#pragma unroll 4
    for (int k = 0; k < FIN; k += 4) {
        float4 w0 = *(const float4*)&W[(k + 0) * FOUT + 4 * fq];
        float4 w1 = *(const float4*)&W[(k + 1) * FOUT + 4 * fq];
        float4 w2 = *(const float4*)&W[(k + 2) * FOUT + 4 * fq];
        float4 w3 = *(const float4*)&W[(k + 3) * FOUT + 4 * fq];
#pragma unroll
        for (int r = 0; r < 4; r++) {
            const float4 hv = *(const float4*)&hs[rq * 4 + r][k];
            acc[r][0] = fmaf(hv.x, w0.x, acc[r][0]);
            acc[r][1] = fmaf(hv.x, w0.y, acc[r][1]);
            acc[r][2] = fmaf(hv.x, w0.z, acc[r][2]);
            acc[r][3] = fmaf(hv.x, w0.w, acc[r][3]);
            acc[r][0] = fmaf(hv.y, w1.x, acc[r][0]);
            acc[r][1] = fmaf(hv.y, w1.y, acc[r][1]);
            acc[r][2] = fmaf(hv.y, w1.z, acc[r][2]);
            acc[r][3] = fmaf(hv.y, w1.w, acc[r][3]);
            acc[r][0] = fmaf(hv.z, w2.x, acc[r][0]);
            acc[r][1] = fmaf(hv.z, w2.y, acc[r][1]);
            acc[r][2] = fmaf(hv.z, w2.z, acc[r][2]);
            acc[r][3] = fmaf(hv.z, w2.w, acc[r][3]);
            acc[r][0] = fmaf(hv.w, w3.x, acc[r][0]);
            acc[r][1] = fmaf(hv.w, w3.y, acc[r][1]);
            acc[r][2] = fmaf(hv.w, w3.z, acc[r][2]);
            acc[r][3] = fmaf(hv.w, w3.w, acc[r][3]);
        }
    }

    // fp32 Wh: 4 rows x float4, coalesced per warp
#pragma unroll
    for (int r = 0; r < 4; r++) {
        float4 v = make_float4(acc[r][0], acc[r][1], acc[r][2], acc[r][3]);
        *(float4*)&g_Wh[(row0 + rq * 4 + r) * FOUT + 4 * fq] = v;
    }

    // transposed split-bf16: g_WhT_*[b][f][n0..n0+3]
    const int b  = (int)(row0 >> 11);
    const int n0 = (int)(row0 & 2047) + 4 * rq;
#pragma unroll
    for (int c = 0; c < 4; c++) {
        const int f = 4 * fq + c;
        __nv_bfloat162 h0 = __floats2bfloat162_rn(acc[0][c], acc[1][c]);
        __nv_bfloat162 h1 = __floats2bfloat162_rn(acc[2][c], acc[3][c]);
        __nv_bfloat162 l0 = __floats2bfloat162_rn(acc[0][c] - __bfloat162float(h0.x),
                                                  acc[1][c] - __bfloat162float(h0.y));
        __nv_bfloat162 l1 = __floats2bfloat162_rn(acc[2][c] - __bfloat162float(h1.x),
                                                  acc[3][c] - __bfloat162float(h1.y));
        const size_t tidx = ((size_t)b * FOUT + f) * NN + n0;
        uint2 hv, lv;
        hv.x = *(unsigned*)&h0; hv.y = *(unsigned*)&h1;
        lv.x = *(unsigned*)&l0; lv.y = *(unsigned*)&l1;
        *(uint2*)&g_WhT_hi[tidx] = hv;
        *(uint2*)&g_WhT_lo[tidx] = lv;
    }
}

// ---------------------------------------------------------------------------
// Kernel 2: scores + factored exponentials
// ---------------------------------------------------------------------------
__global__ __launch_bounds__(256) void k_scores(const float* __restrict__ a) {
    const int gw = (blockIdx.x * 256 + threadIdx.x) >> 5;
    const int lane = threadIdx.x & 31;

    const float4 v  = ((const float4*)g_Wh)[(size_t)gw * 32 + lane];
    const float4 a1 = ((const float4*)a)[lane];
    const float4 a2 = ((const float4*)a)[32 + lane];

    float s1 = v.x * a1.x + v.y * a1.y + v.z * a1.z + v.w * a1.w;
    float s2 = v.x * a2.x + v.y * a2.y + v.z * a2.z + v.w * a2.w;
#pragma unroll
    for (int o = 16; o; o >>= 1) {
        s1 += __shfl_xor_sync(0xFFFFFFFFu, s1, o);
        s2 += __shfl_xor_sync(0xFFFFFFFFu, s2, o);
    }
    if (lane == 0) {
        g_s1[gw] = s1;
        g_s2[gw] = s2;
        g_E1[gw] = expf(s1);
        g_F1[gw] = expf(0.2f * s1);
        g_E2[gw] = expf(s2);
        g_F2[gw] = expf(0.2f * s2);
    }
}

// ---------------------------------------------------------------------------
// Kernel 3: fused attention via mma.sync bf16 split 3-product, pipelined.
// Grid (16, 8), 256 threads. CTA: 128 i x 128 f, 32 j-tiles of 64.
// Double-buffered smem, 1 sync/tile, adj+WhT prefetched under the MMA phase.
// ---------------------------------------------------------------------------
__global__ __launch_bounds__(256, 1) void k_attn(const int* __restrict__ adj,
                                                 float* __restrict__ out) {
    extern __shared__ char dsm[];
    __shared__ float s_Z[128][2];
    __shared__ float s_Zc[128];
    __shared__ float s_s2[NN], s_E2[NN], s_F2[NN];   // 24 KB

    const int t = threadIdx.x, w = t >> 5, lane = t & 31;
    const int b = blockIdx.y, i0 = blockIdx.x * 128;
    const size_t bn = (size_t)b * NN;

    // prologue: copy per-batch vectors to smem
    {
        const float4* p2 = (const float4*)(g_s2 + bn);
        const float4* pe = (const float4*)(g_E2 + bn);
        const float4* pf = (const float4*)(g_F2 + bn);
#pragma unroll
        for (int i = t; i < NN / 4; i += 256) {
            ((float4*)s_s2)[i] = p2[i];
            ((float4*)s_E2)[i] = pe[i];
            ((float4*)s_F2)[i] = pf[i];
        }
    }

    // ---- c-phase mapping: row = t>>1 (both i and f role), jh = (t&1)*32 ----
    const int row = t >> 1;
    const int jh  = (t & 1) * 32;

    const float s1r = g_s1[bn + i0 + row];
    const float E1r = g_E1[bn + i0 + row];
    const float F1r = g_F1[bn + i0 + row];
    const int* __restrict__ adjrow = adj + (bn + i0 + row) * (size_t)NN;
    const __nv_bfloat16* __restrict__ whh = g_WhT_hi + ((size_t)b * FOUT + row) * NN;
    const __nv_bfloat16* __restrict__ whl = g_WhT_lo + ((size_t)b * FOUT + row) * NN;

    // ---- mma-phase addressing ----
    const int wm = w & 1, wn = w >> 1;
    const uint32_t aRow = (uint32_t)((wm * 64 + (lane & 15)) * (STRIDE * 2) + (lane >> 4) * 16);
    const uint32_t bRow = (uint32_t)((wn * 32 + (lane & 15)) * (STRIDE * 2) + (lane >> 4) * 16);

    float c[4][4][4];
#pragma unroll
    for (int mt = 0; mt < 4; mt++)
#pragma unroll
        for (int nt = 0; nt < 4; nt++)
#pragma unroll
            for (int r = 0; r < 4; r++) c[mt][nt][r] = 0.f;

    float Zreg = 0.f;

    // prefetch registers for tile jt
    int4 radj[8];
    uint4 rwhh[4], rwhl[4];
    {
        const int jg0 = jh;   // tile 0
        const int4* am = (const int4*)(adjrow + jg0);
#pragma unroll
        for (int q = 0; q < 8; q++) radj[q] = am[q];
        const uint4* sh = (const uint4*)(whh + jg0);
        const uint4* sl = (const uint4*)(whl + jg0);
#pragma unroll
        for (int g = 0; g < 4; g++) { rwhh[g] = sh[g]; rwhl[g] = sl[g]; }
    }
    __syncthreads();   // s_s2/s_E2/s_F2 ready

    for (int jt = 0; jt < NTILES; jt++) {
        const int s = jt & 1;
        char* A_hi = dsm + s * STAGE_BYTES;
        char* A_lo = A_hi + TILE_BYTES;
        char* B_hi = A_hi + 2 * TILE_BYTES;
        char* B_lo = A_hi + 3 * TILE_BYTES;
        const int jg0 = jt * JT + jh;

        // ---- store B from prefetched regs ----
        {
            char* bh = B_hi + row * (STRIDE * 2) + jh * 2;
            char* bl = B_lo + row * (STRIDE * 2) + jh * 2;
#pragma unroll
            for (int g = 0; g < 4; g++) {
                *(uint4*)(bh + g * 16) = rwhh[g];
                *(uint4*)(bl + g * 16) = rwhl[g];
            }
        }
        // ---- build c tile (fp32) from prefetched adj + smem vecs, split ----
        {
            float c32[32];
#pragma unroll
            for (int q = 0; q < 8; q++) {
                const int4 m = radj[q];
                const float4 s2 = *(const float4*)&s_s2[jg0 + 4 * q];
                const float4 e2 = *(const float4*)&s_E2[jg0 + 4 * q];
                const float4 f2 = *(const float4*)&s_F2[jg0 + 4 * q];
                c32[4*q+0] = (m.x > 0) ? ((s1r + s2.x > 0.f) ? E1r * e2.x : F1r * f2.x) : 0.f;
                c32[4*q+1] = (m.y > 0) ? ((s1r + s2.y > 0.f) ? E1r * e2.y : F1r * f2.y) : 0.f;
                c32[4*q+2] = (m.z > 0) ? ((s1r + s2.z > 0.f) ? E1r * e2.z : F1r * f2.z) : 0.f;
                c32[4*q+3] = (m.w > 0) ? ((s1r + s2.w > 0.f) ? E1r * e2.w : F1r * f2.w) : 0.f;
            }
#pragma unroll
            for (int k = 0; k < 32; k++) Zreg += c32[k];
            char* ah = A_hi + row * (STRIDE * 2) + jh * 2;
            char* al = A_lo + row * (STRIDE * 2) + jh * 2;
#pragma unroll
            for (int g = 0; g < 4; g++) {
                uint4 hv, lv;
#pragma unroll
                for (int p = 0; p < 4; p++) {
                    const float a0 = c32[g*8 + 2*p], a1 = c32[g*8 + 2*p + 1];
                    __nv_bfloat162 hb = __floats2bfloat162_rn(a0, a1);
                    const float r0 = a0 - __bfloat162float(hb.x);
                    const float r1 = a1 - __bfloat162float(hb.y);
                    __nv_bfloat162 lb = __floats2bfloat162_rn(r0, r1);
                    ((unsigned*)&hv)[p] = *(unsigned*)&hb;
                    ((unsigned*)&lv)[p] = *(unsigned*)&lb;
                }
                *(uint4*)(ah + g * 16) = hv;
                *(uint4*)(al + g * 16) = lv;
            }
        }

        __syncthreads();   // stage s populated; all warps past mma on stage s (jt-2)

        // ---- prefetch next tile (latency hidden under the MMA phase) ----
        if (jt + 1 < NTILES) {
            const int jg1 = (jt + 1) * JT + jh;
            const int4* am = (const int4*)(adjrow + jg1);
#pragma unroll
            for (int q = 0; q < 8; q++) radj[q] = am[q];
            const uint4* sh = (const uint4*)(whh + jg1);
            const uint4* sl = (const uint4*)(whl + jg1);
#pragma unroll
            for (int g = 0; g < 4; g++) { rwhh[g] = sh[g]; rwhl[g] = sl[g]; }
        }

        // ---- mma phase: 4 k-steps of 16 ----
        const uint32_t sA_hi = smem_u32(A_hi);
        const uint32_t sA_lo = smem_u32(A_lo);
        const uint32_t sB_hi = smem_u32(B_hi);
        const uint32_t sB_lo = smem_u32(B_lo);
#pragma unroll
        for (int ks = 0; ks < 4; ks++) {
            const uint32_t kOff = ks * 32;
            uint32_t ah[4][4], al[4][4], bh[4][2], bl[4][2];
#pragma unroll
            for (int mt = 0; mt < 4; mt++) {
                const uint32_t mOff = aRow + mt * 16 * (STRIDE * 2) + kOff;
                LDSM_X4(ah[mt], sA_hi + mOff);
                LDSM_X4(al[mt], sA_lo + mOff);
            }
#pragma unroll
            for (int np = 0; np < 2; np++) {
                const uint32_t nOff = bRow + np * 16 * (STRIDE * 2) + kOff;
                uint32_t q[4];
                LDSM_X4(q, sB_hi + nOff);
                bh[2*np][0] = q[0]; bh[2*np][1] = q[2];
                bh[2*np+1][0] = q[1]; bh[2*np+1][1] = q[3];
                LDSM_X4(q, sB_lo + nOff);
                bl[2*np][0] = q[0]; bl[2*np][1] = q[2];
                bl[2*np+1][0] = q[1]; bl[2*np+1][1] = q[3];
            }
#pragma unroll
            for (int mt = 0; mt < 4; mt++)
#pragma unroll
                for (int nt = 0; nt < 4; nt++) {
                    mma16816(c[mt][nt], ah[mt], bh[nt]);
                    mma16816(c[mt][nt], ah[mt], bl[nt]);
                    mma16816(c[mt][nt], al[mt], bh[nt]);
                }
        }
    }

    // ---- combine Z, then normalize + ELU + store ----
    s_Z[row][t & 1] = Zreg;
    __syncthreads();
    if (t < 128) s_Zc[t] = s_Z[t][0] + s_Z[t][1];
    __syncthreads();

    const int qrow = lane >> 2, qcol = 2 * (lane & 3);
#pragma unroll
    for (int mt = 0; mt < 4; mt++) {
        const int r0 = wm * 64 + mt * 16 + qrow;
        const int r1 = r0 + 8;
        const float zi0 = 1.0f / s_Zc[r0];
        const float zi1 = 1.0f / s_Zc[r1];
        float* op0 = out + (bn + i0 + r0) * (size_t)FOUT;
        float* op1 = out + (bn + i0 + r1) * (size_t)FOUT;
#pragma unroll
        for (int nt = 0; nt < 4; nt++) {
            const int col = wn * 32 + nt * 8 + qcol;
            float x0 = c[mt][nt][0] * zi0;
            float x1 = c[mt][nt][1] * zi0;
            float x2 = c[mt][nt][2] * zi1;
            float x3 = c[mt][nt][3] * zi1;
            float2 v0, v1;
            v0.x = x0 > 0.f ? x0 : expm1f(x0);
            v0.y = x1 > 0.f ? x1 : expm1f(x1);
            v1.x = x2 > 0.f ? x2 : expm1f(x2);
            v1.y = x3 > 0.f ? x3 : expm1f(x3);
            *(float2*)(op0 + col) = v0;
            *(float2*)(op1 + col) = v1;
        }
    }
}

// ---------------------------------------------------------------------------
extern "C" void kernel_launch(void* const* d_in, const int* in_sizes, int n_in,
                              void* d_out, int out_size) {
    const float* h = nullptr; const int* adj = nullptr;
    const float* W = nullptr; const float* a = nullptr;
    for (int i = 0; i < n_in; i++) {
        switch (in_sizes[i]) {
            case 4194304:  h   = (const float*)d_in[i]; break;
            case 33554432: adj = (const int*)d_in[i];   break;
            case 32768:    W   = (const float*)d_in[i]; break;
            case 256:      a   = (const float*)d_in[i]; break;
        }
    }
    float* out = (float*)d_out;

    static bool attr_set = false;
    if (!attr_set) {
        cudaFuncSetAttribute(k_attn, cudaFuncAttributeMaxDynamicSharedMemorySize,
                             DSMEM_BYTES);
        attr_set = true;
    }

    k_wh<<<BN / 16, 128>>>(h, W);
    k_scores<<<(BN * 32) / 256, 256>>>(a);
    k_attn<<<dim3(NN / 128, BB), 256, DSMEM_BYTES>>>(adj, out);
}

// round 6
// speedup vs baseline: 2.7409x; 1.2272x over previous
#include <cuda_runtime.h>
#include <cuda_fp16.h>
#include <cstdint>
#include <math.h>

#define BB 8
#define NN 2048
#define FIN 256
#define FOUT 128
#define BN (BB*NN)   // 16384 rows total

#define JT 64                     // j-tile (K of the attn mma loop)
#define NTILES (NN/JT)            // 32
#define STRIDE 72                 // b16 elems per smem row (144 B) - conflict-free ldmatrix
#define TILE_BYTES (128*STRIDE*2)          // 18432 per tile
#define ATT_STAGE (3*TILE_BYTES)           // A_hi, A_lo, B = 55296
#define ATT_DSMEM (2*ATT_STAGE)            // 110592
#define WH_DSMEM  (4*TILE_BYTES)           // A_hi, A_lo, B_hi, B_lo = 73728

// Scratch (static device arrays; allocation is forbidden)
__device__ __half g_WT_hi[FIN * FOUT];                 // [f][k] W^T split hi
__device__ __half g_WT_lo[FIN * FOUT];                 // [f][k] W^T split lo
__device__ float  g_u1[FIN], g_u2[FIN];                // W@a1, W@a2
__device__ __half g_WhT[(size_t)BB * FOUT * NN];       // [b][f][n] Wh fp16 (single)
__device__ float  g_s1[BN], g_s2[BN], g_E2[BN], g_F2[BN];

// ---------------------------------------------------------------------------
__device__ __forceinline__ uint32_t smem_u32(const void* p) {
    uint32_t a;
    asm("{ .reg .u64 t; cvta.to.shared.u64 t, %1; cvt.u32.u64 %0, t; }"
        : "=r"(a) : "l"(p));
    return a;
}

#define LDSM_X4(r, addr) \
    asm volatile("ldmatrix.sync.aligned.m8n8.x4.shared.b16 {%0,%1,%2,%3}, [%4];" \
        : "=r"((r)[0]), "=r"((r)[1]), "=r"((r)[2]), "=r"((r)[3]) : "r"(addr))

__device__ __forceinline__ void mma16816(float* c, const uint32_t* a, const uint32_t* b) {
    asm volatile(
        "mma.sync.aligned.m16n8k16.row.col.f32.f16.f16.f32 "
        "{%0,%1,%2,%3}, {%4,%5,%6,%7}, {%8,%9}, {%0,%1,%2,%3};"
        : "+f"(c[0]), "+f"(c[1]), "+f"(c[2]), "+f"(c[3])
        : "r"(a[0]), "r"(a[1]), "r"(a[2]), "r"(a[3]), "r"(b[0]), "r"(b[1]));
}

__device__ __forceinline__ uint4 pack8h(__half2 a, __half2 b, __half2 c, __half2 d) {
    uint4 v;
    v.x = *(unsigned*)&a; v.y = *(unsigned*)&b;
    v.z = *(unsigned*)&c; v.w = *(unsigned*)&d;
    return v;
}

// ---------------------------------------------------------------------------
// Kernel 0: prep. Blocks 0-15: W^T split fp16. Block 16: u1 = W@a1, u2 = W@a2.
// ---------------------------------------------------------------------------
__global__ __launch_bounds__(256) void k_prep(const float* __restrict__ W,
                                              const float* __restrict__ a) {
    const int t = threadIdx.x;
    if (blockIdx.x < 16) {
        const int f  = blockIdx.x * 8 + (t >> 5);
        const int k0 = (t & 31) * 8;
        __half2 hi[4], lo[4];
#pragma unroll
        for (int p = 0; p < 4; p++) {
            float w0 = W[(k0 + 2 * p + 0) * FOUT + f];
            float w1 = W[(k0 + 2 * p + 1) * FOUT + f];
            __half2 hh = __floats2half2_rn(w0, w1);
            hi[p] = hh;
            lo[p] = __floats2half2_rn(w0 - __low2float(hh), w1 - __high2float(hh));
        }
        *(uint4*)&g_WT_hi[f * FIN + k0] = pack8h(hi[0], hi[1], hi[2], hi[3]);
        *(uint4*)&g_WT_lo[f * FIN + k0] = pack8h(lo[0], lo[1], lo[2], lo[3]);
    } else {
        __shared__ float sa[2 * FOUT];
        sa[t] = a[t];
        __syncthreads();
        const int k = t;
        const float4* wr = (const float4*)&W[k * FOUT];
        float a1 = 0.f, a2 = 0.f;
#pragma unroll 8
        for (int p = 0; p < FOUT / 4; p++) {
            float4 wv = wr[p];
            a1 += wv.x * sa[4*p] + wv.y * sa[4*p+1] + wv.z * sa[4*p+2] + wv.w * sa[4*p+3];
            a2 += wv.x * sa[FOUT+4*p] + wv.y * sa[FOUT+4*p+1]
                + wv.z * sa[FOUT+4*p+2] + wv.w * sa[FOUT+4*p+3];
        }
        g_u1[k] = a1;
        g_u2[k] = a2;
    }
}

// ---------------------------------------------------------------------------
// Kernel 1: Wh = h @ W via HMMA fp16 split 3-product; fused exact scores
// (s1 = h.u1, s2 = h.u2 in fp32) + exps; writes WhT fp16 [b][f][n].
// Grid 128 CTAs x 256 thr. CTA: 128 rows x 128 cols, K=256 in 4 chunks of 64.
// ---------------------------------------------------------------------------
__global__ __launch_bounds__(256) void k_wh(const float* __restrict__ h) {
    extern __shared__ char wsm[];
    __shared__ float s_u1[FIN], s_u2[FIN];

    const int t = threadIdx.x, w = t >> 5, lane = t & 31;
    const int bx = blockIdx.x;
    const size_t row0 = (size_t)bx * 128;
    const int b  = bx >> 4;
    const int n0 = (bx & 15) * 128;

    char* A_hi = wsm;
    char* A_lo = wsm + TILE_BYTES;
    char* B_hi = wsm + 2 * TILE_BYTES;
    char* B_lo = wsm + 3 * TILE_BYTES;
    const uint32_t sA_hi = smem_u32(A_hi), sA_lo = smem_u32(A_lo);
    const uint32_t sB_hi = smem_u32(B_hi), sB_lo = smem_u32(B_lo);

    s_u1[t] = g_u1[t & 255];
    s_u2[t] = g_u2[t & 255];

    const int row = t >> 1, fq = t & 1;   // staging role: row 0..127, k half
    const float* __restrict__ hrow = h + (row0 + row) * (size_t)FIN + fq * 32;

    const int wm = w & 1, wn = w >> 1;
    const uint32_t aRow = (uint32_t)((wm * 64 + (lane & 15)) * (STRIDE * 2) + (lane >> 4) * 16);
    const uint32_t bRow = (uint32_t)((wn * 32 + (lane & 15)) * (STRIDE * 2) + (lane >> 4) * 16);

    float c[4][4][4];
#pragma unroll
    for (int mt = 0; mt < 4; mt++)
#pragma unroll
        for (int nt = 0; nt < 4; nt++)
#pragma unroll
            for (int r = 0; r < 4; r++) c[mt][nt][r] = 0.f;

    float s1p = 0.f, s2p = 0.f;

    for (int kc = 0; kc < 4; kc++) {
        const int k0 = kc * 64;
        __syncthreads();   // tiles free (prev mma done)

        // ---- load h (32 floats), score partials, convert+store A ----
        float4 hv[8];
        const float4* hp = (const float4*)(hrow + k0);
#pragma unroll
        for (int g = 0; g < 8; g++) hv[g] = hp[g];

        const float4* u1v = (const float4*)&s_u1[k0 + fq * 32];
        const float4* u2v = (const float4*)&s_u2[k0 + fq * 32];
#pragma unroll
        for (int g = 0; g < 8; g++) {
            const float4 u1 = u1v[g], u2 = u2v[g];
            s1p += hv[g].x * u1.x + hv[g].y * u1.y + hv[g].z * u1.z + hv[g].w * u1.w;
            s2p += hv[g].x * u2.x + hv[g].y * u2.y + hv[g].z * u2.z + hv[g].w * u2.w;
        }

        char* ah = A_hi + row * (STRIDE * 2) + fq * 64;
        char* al = A_lo + row * (STRIDE * 2) + fq * 64;
#pragma unroll
        for (int g = 0; g < 4; g++) {
            const float4 v0 = hv[2 * g], v1 = hv[2 * g + 1];
            __half2 h0 = __floats2half2_rn(v0.x, v0.y);
            __half2 h1 = __floats2half2_rn(v0.z, v0.w);
            __half2 h2 = __floats2half2_rn(v1.x, v1.y);
            __half2 h3 = __floats2half2_rn(v1.z, v1.w);
            __half2 l0 = __floats2half2_rn(v0.x - __low2float(h0), v0.y - __high2float(h0));
            __half2 l1 = __floats2half2_rn(v0.z - __low2float(h1), v0.w - __high2float(h1));
            __half2 l2 = __floats2half2_rn(v1.x - __low2float(h2), v1.y - __high2float(h2));
            __half2 l3 = __floats2half2_rn(v1.z - __low2float(h3), v1.w - __high2float(h3));
            *(uint4*)(ah + g * 16) = pack8h(h0, h1, h2, h3);
            *(uint4*)(al + g * 16) = pack8h(l0, l1, l2, l3);
        }

        // ---- stage B (W^T split, preconverted): 32 halfs = 4 uint4 ----
        {
            const uint4* sh = (const uint4*)&g_WT_hi[row * FIN + k0 + fq * 32];
            const uint4* sl = (const uint4*)&g_WT_lo[row * FIN + k0 + fq * 32];
            char* bh = B_hi + row * (STRIDE * 2) + fq * 64;
            char* bl = B_lo + row * (STRIDE * 2) + fq * 64;
#pragma unroll
            for (int g = 0; g < 4; g++) {
                *(uint4*)(bh + g * 16) = sh[g];
                *(uint4*)(bl + g * 16) = sl[g];
            }
        }
        __syncthreads();

        // ---- mma: 4 k-steps of 16, 3 products ----
#pragma unroll
        for (int ks = 0; ks < 4; ks++) {
            const uint32_t kOff = ks * 32;
            uint32_t ah4[4][4], al4[4][4], bh4[4][2], bl4[4][2];
#pragma unroll
            for (int mt = 0; mt < 4; mt++) {
                const uint32_t mOff = aRow + mt * 16 * (STRIDE * 2) + kOff;
                LDSM_X4(ah4[mt], sA_hi + mOff);
                LDSM_X4(al4[mt], sA_lo + mOff);
            }
#pragma unroll
            for (int np = 0; np < 2; np++) {
                const uint32_t nOff = bRow + np * 16 * (STRIDE * 2) + kOff;
                uint32_t q[4];
                LDSM_X4(q, sB_hi + nOff);
                bh4[2*np][0] = q[0]; bh4[2*np][1] = q[2];
                bh4[2*np+1][0] = q[1]; bh4[2*np+1][1] = q[3];
                LDSM_X4(q, sB_lo + nOff);
                bl4[2*np][0] = q[0]; bl4[2*np][1] = q[2];
                bl4[2*np+1][0] = q[1]; bl4[2*np+1][1] = q[3];
            }
#pragma unroll
            for (int mt = 0; mt < 4; mt++)
#pragma unroll
                for (int nt = 0; nt < 4; nt++) {
                    mma16816(c[mt][nt], ah4[mt], bh4[nt]);
                    mma16816(c[mt][nt], ah4[mt], bl4[nt]);
                    mma16816(c[mt][nt], al4[mt], bh4[nt]);
                }
        }
    }

    // ---- scores: pair-reduce and write ----
    s1p += __shfl_xor_sync(0xFFFFFFFFu, s1p, 1);
    s2p += __shfl_xor_sync(0xFFFFFFFFu, s2p, 1);
    if (fq == 0) {
        const size_t r = row0 + row;
        g_s1[r] = s1p;
        g_s2[r] = s2p;
        g_E2[r] = expf(s2p);
        g_F2[r] = expf(0.2f * s2p);
    }

    // ---- WhT fp16 transposed store via smem ----
    __syncthreads();
    __half* s_T = (__half*)wsm;   // [128 f][136]
    const int qrow = lane >> 2, qcol = 2 * (lane & 3);
#pragma unroll
    for (int mt = 0; mt < 4; mt++) {
        const int r0 = wm * 64 + mt * 16 + qrow;
        const int r1 = r0 + 8;
#pragma unroll
        for (int nt = 0; nt < 4; nt++) {
            const int c0 = wn * 32 + nt * 8 + qcol;
            s_T[c0 * 136 + r0]       = __float2half_rn(c[mt][nt][0]);
            s_T[(c0 + 1) * 136 + r0] = __float2half_rn(c[mt][nt][1]);
            s_T[c0 * 136 + r1]       = __float2half_rn(c[mt][nt][2]);
            s_T[(c0 + 1) * 136 + r1] = __float2half_rn(c[mt][nt][3]);
        }
    }
    __syncthreads();
    {
        const int f = t >> 1, part = t & 1;
        const uint4* src = (const uint4*)&s_T[f * 136 + part * 64];
        uint4* dst = (uint4*)&g_WhT[((size_t)(b * FOUT + f)) * NN + n0 + part * 64];
#pragma unroll
        for (int i = 0; i < 8; i++) dst[i] = src[i];
    }
}

// ---------------------------------------------------------------------------
// Kernel 2: fused attention. A = row-normalized weights fp16 split (hi/lo),
// B = Wh fp16 single -> 2 mma products per (mt,nt). Pipelined.
// ---------------------------------------------------------------------------
__global__ __launch_bounds__(256, 1) void k_attn(const int* __restrict__ adj,
                                                 float* __restrict__ out) {
    extern __shared__ char dsm[];
    __shared__ float s_Z[128][2];
    __shared__ float s_Zc[128];
    __shared__ float s_s2[NN], s_E2[NN], s_F2[NN];   // 24 KB
    __shared__ float s_red[8];

    const int t = threadIdx.x, w = t >> 5, lane = t & 31;
    const int b = blockIdx.y, i0 = blockIdx.x * 128;
    const size_t bn = (size_t)b * NN;

    // prologue: stage per-batch vectors, track max(s2)
    float mloc = -1e30f;
    {
        const float4* p2 = (const float4*)(g_s2 + bn);
        const float4* pe = (const float4*)(g_E2 + bn);
        const float4* pf = (const float4*)(g_F2 + bn);
#pragma unroll
        for (int i = t; i < NN / 4; i += 256) {
            const float4 v2 = p2[i];
            ((float4*)s_s2)[i] = v2;
            ((float4*)s_E2)[i] = pe[i];
            ((float4*)s_F2)[i] = pf[i];
            mloc = fmaxf(mloc, fmaxf(fmaxf(v2.x, v2.y), fmaxf(v2.z, v2.w)));
        }
    }
#pragma unroll
    for (int o = 16; o; o >>= 1) mloc = fmaxf(mloc, __shfl_xor_sync(0xFFFFFFFFu, mloc, o));
    if (lane == 0) s_red[w] = mloc;
    __syncthreads();
    float M2 = s_red[0];
#pragma unroll
    for (int i = 1; i < 8; i++) M2 = fmaxf(M2, s_red[i]);

    // ---- c-phase mapping: row = t>>1, jh = (t&1)*32 ----
    const int row = t >> 1;
    const int jh  = (t & 1) * 32;

    const float s1r = g_s1[bn + i0 + row];
    const float xm  = s1r + M2;
    const float m   = xm > 0.f ? xm : 0.2f * xm;
    const float E1n = expf(s1r - m);
    const float F1n = expf(0.2f * s1r - m);
    const int* __restrict__ adjrow = adj + (bn + i0 + row) * (size_t)NN;
    const __half* __restrict__ whp = g_WhT + ((size_t)b * FOUT + row) * NN;

    const int wm = w & 1, wn = w >> 1;
    const uint32_t aRow = (uint32_t)((wm * 64 + (lane & 15)) * (STRIDE * 2) + (lane >> 4) * 16);
    const uint32_t bRow = (uint32_t)((wn * 32 + (lane & 15)) * (STRIDE * 2) + (lane >> 4) * 16);

    float c[4][4][4];
#pragma unroll
    for (int mt = 0; mt < 4; mt++)
#pragma unroll
        for (int nt = 0; nt < 4; nt++)
#pragma unroll
            for (int r = 0; r < 4; r++) c[mt][nt][r] = 0.f;

    float Zreg = 0.f;

    // prefetch tile 0
    int4 radj[8];
    uint4 rwh[4];
    {
        const int4* am = (const int4*)(adjrow + jh);
#pragma unroll
        for (int q = 0; q < 8; q++) radj[q] = am[q];
        const uint4* sh = (const uint4*)(whp + jh);
#pragma unroll
        for (int g = 0; g < 4; g++) rwh[g] = sh[g];
    }
    __syncthreads();

    for (int jt = 0; jt < NTILES; jt++) {
        const int s = jt & 1;
        char* A_hi = dsm + s * ATT_STAGE;
        char* A_lo = A_hi + TILE_BYTES;
        char* B_t  = A_hi + 2 * TILE_BYTES;
        const int jg0 = jt * JT + jh;

        // ---- store B (fp16 Wh) from prefetch ----
        {
            char* bp = B_t + row * (STRIDE * 2) + jh * 2;
#pragma unroll
            for (int g = 0; g < 4; g++) *(uint4*)(bp + g * 16) = rwh[g];
        }
        // ---- build normalized c tile, split to fp16 pair ----
        {
            float c32[32];
#pragma unroll
            for (int q = 0; q < 8; q++) {
                const int4 mv = radj[q];
                const float4 s2 = *(const float4*)&s_s2[jg0 + 4 * q];
                const float4 e2 = *(const float4*)&s_E2[jg0 + 4 * q];
                const float4 f2 = *(const float4*)&s_F2[jg0 + 4 * q];
                c32[4*q+0] = (mv.x > 0) ? ((s1r + s2.x > 0.f) ? E1n * e2.x : F1n * f2.x) : 0.f;
                c32[4*q+1] = (mv.y > 0) ? ((s1r + s2.y > 0.f) ? E1n * e2.y : F1n * f2.y) : 0.f;
                c32[4*q+2] = (mv.z > 0) ? ((s1r + s2.z > 0.f) ? E1n * e2.z : F1n * f2.z) : 0.f;
                c32[4*q+3] = (mv.w > 0) ? ((s1r + s2.w > 0.f) ? E1n * e2.w : F1n * f2.w) : 0.f;
            }
#pragma unroll
            for (int k = 0; k < 32; k++) Zreg += c32[k];
            char* ah = A_hi + row * (STRIDE * 2) + jh * 2;
            char* al = A_lo + row * (STRIDE * 2) + jh * 2;
#pragma unroll
            for (int g = 0; g < 4; g++) {
                __half2 h0 = __floats2half2_rn(c32[g*8+0], c32[g*8+1]);
                __half2 h1 = __floats2half2_rn(c32[g*8+2], c32[g*8+3]);
                __half2 h2 = __floats2half2_rn(c32[g*8+4], c32[g*8+5]);
                __half2 h3 = __floats2half2_rn(c32[g*8+6], c32[g*8+7]);
                __half2 l0 = __floats2half2_rn(c32[g*8+0] - __low2float(h0),
                                               c32[g*8+1] - __high2float(h0));
                __half2 l1 = __floats2half2_rn(c32[g*8+2] - __low2float(h1),
                                               c32[g*8+3] - __high2float(h1));
                __half2 l2 = __floats2half2_rn(c32[g*8+4] - __low2float(h2),
                                               c32[g*8+5] - __high2float(h2));
                __half2 l3 = __floats2half2_rn(c32[g*8+6] - __low2float(h3),
                                               c32[g*8+7] - __high2float(h3));
                *(uint4*)(ah + g * 16) = pack8h(h0, h1, h2, h3);
                *(uint4*)(al + g * 16) = pack8h(l0, l1, l2, l3);
            }
        }

        __syncthreads();

        // ---- prefetch next tile under the mma phase ----
        if (jt + 1 < NTILES) {
            const int jg1 = (jt + 1) * JT + jh;
            const int4* am = (const int4*)(adjrow + jg1);
#pragma unroll
            for (int q = 0; q < 8; q++) radj[q] = am[q];
            const uint4* sh = (const uint4*)(whp + jg1);
#pragma unroll
            for (int g = 0; g < 4; g++) rwh[g] = sh[g];
        }

        // ---- mma: 4 k-steps, 2 products ----
        const uint32_t sA_hi = smem_u32(A_hi);
        const uint32_t sA_lo = smem_u32(A_lo);
        const uint32_t sB    = smem_u32(B_t);
#pragma unroll
        for (int ks = 0; ks < 4; ks++) {
            const uint32_t kOff = ks * 32;
            uint32_t ah4[4][4], al4[4][4], bh4[4][2];
#pragma unroll
            for (int mt = 0; mt < 4; mt++) {
                const uint32_t mOff = aRow + mt * 16 * (STRIDE * 2) + kOff;
                LDSM_X4(ah4[mt], sA_hi + mOff);
                LDSM_X4(al4[mt], sA_lo + mOff);
            }
#pragma unroll
            for (int np = 0; np < 2; np++) {
                const uint32_t nOff = bRow + np * 16 * (STRIDE * 2) + kOff;
                uint32_t q[4];
                LDSM_X4(q, sB + nOff);
                bh4[2*np][0] = q[0]; bh4[2*np][1] = q[2];
                bh4[2*np+1][0] = q[1]; bh4[2*np+1][1] = q[3];
            }
#pragma unroll
            for (int mt = 0; mt < 4; mt++)
#pragma unroll
                for (int nt = 0; nt < 4; nt++) {
                    mma16816(c[mt][nt], ah4[mt], bh4[nt]);
                    mma16816(c[mt][nt], al4[mt], bh4[nt]);
                }
        }
    }

    // ---- combine Z, normalize + ELU + store ----
    s_Z[row][t & 1] = Zreg;
    __syncthreads();
    if (t < 128) s_Zc[t] = s_Z[t][0] + s_Z[t][1];
    __syncthreads();

    const int qrow = lane >> 2, qcol = 2 * (lane & 3);
#pragma unroll
    for (int mt = 0; mt < 4; mt++) {
        const int r0 = wm * 64 + mt * 16 + qrow;
        const int r1 = r0 + 8;
        const float zi0 = 1.0f / s_Zc[r0];
        const float zi1 = 1.0f / s_Zc[r1];
        float* op0 = out + (bn + i0 + r0) * (size_t)FOUT;
        float* op1 = out + (bn + i0 + r1) * (size_t)FOUT;
#pragma unroll
        for (int nt = 0; nt < 4; nt++) {
            const int col = wn * 32 + nt * 8 + qcol;
            float x0 = c[mt][nt][0] * zi0;
            float x1 = c[mt][nt][1] * zi0;
            float x2 = c[mt][nt][2] * zi1;
            float x3 = c[mt][nt][3] * zi1;
            float2 v0, v1;
            v0.x = x0 > 0.f ? x0 : expm1f(x0);
            v0.y = x1 > 0.f ? x1 : expm1f(x1);
            v1.x = x2 > 0.f ? x2 : expm1f(x2);
            v1.y = x3 > 0.f ? x3 : expm1f(x3);
            *(float2*)(op0 + col) = v0;
            *(float2*)(op1 + col) = v1;
        }
    }
}

// ---------------------------------------------------------------------------
extern "C" void kernel_launch(void* const* d_in, const int* in_sizes, int n_in,
                              void* d_out, int out_size) {
    const float* h = nullptr; const int* adj = nullptr;
    const float* W = nullptr; const float* a = nullptr;
    for (int i = 0; i < n_in; i++) {
        switch (in_sizes[i]) {
            case 4194304:  h   = (const float*)d_in[i]; break;
            case 33554432: adj = (const int*)d_in[i];   break;
            case 32768:    W   = (const float*)d_in[i]; break;
            case 256:      a   = (const float*)d_in[i]; break;
        }
    }
    float* out = (float*)d_out;

    static bool attr_set = false;
    if (!attr_set) {
        cudaFuncSetAttribute(k_wh, cudaFuncAttributeMaxDynamicSharedMemorySize,
                             WH_DSMEM);
        cudaFuncSetAttribute(k_attn, cudaFuncAttributeMaxDynamicSharedMemorySize,
                             ATT_DSMEM);
        attr_set = true;
    }

    k_prep<<<17, 256>>>(W, a);
    k_wh<<<BN / 128, 256, WH_DSMEM>>>(h);
    k_attn<<<dim3(NN / 128, BB), 256, ATT_DSMEM>>>(adj, out);
}

// round 7
// speedup vs baseline: 3.3201x; 1.2113x over previous
#include <cuda_runtime.h>
#include <cuda_fp16.h>
#include <cstdint>
#include <math.h>

#define BB 8
#define NN 2048
#define FIN 256
#define FOUT 128
#define BN (BB*NN)   // 16384 rows total

#define JT 64                     // j-tile (K of the attn mma loop)
#define NTILES (NN/JT)            // 32
#define STRIDE 72                 // b16 elems per smem row (144 B) - conflict-free ldmatrix
#define TILE_BYTES (128*STRIDE*2)          // 18432 per tile
#define ATT_STAGE (2*TILE_BYTES)           // A, B = 36864
#define ATT_DSMEM (2*ATT_STAGE)            // 73728
#define WH_DSMEM  (3*TILE_BYTES)           // A, B_hi, B_lo = 55296

// Scratch (static device arrays; allocation is forbidden)
__device__ __half g_WT_hi[FIN * FOUT];                 // [f][k] W^T split hi
__device__ __half g_WT_lo[FIN * FOUT];                 // [f][k] W^T split lo
__device__ float  g_u1[FIN], g_u2[FIN];                // W@a1, W@a2
__device__ __half g_WhT[(size_t)BB * FOUT * NN];       // [b][f][n] Wh fp16 (single)
__device__ float  g_s1[BN], g_s2[BN], g_E2[BN], g_F2[BN];

// ---------------------------------------------------------------------------
__device__ __forceinline__ uint32_t smem_u32(const void* p) {
    uint32_t a;
    asm("{ .reg .u64 t; cvta.to.shared.u64 t, %1; cvt.u32.u64 %0, t; }"
        : "=r"(a) : "l"(p));
    return a;
}

#define LDSM_X4(r, addr) \
    asm volatile("ldmatrix.sync.aligned.m8n8.x4.shared.b16 {%0,%1,%2,%3}, [%4];" \
        : "=r"((r)[0]), "=r"((r)[1]), "=r"((r)[2]), "=r"((r)[3]) : "r"(addr))

__device__ __forceinline__ void mma16816(float* c, const uint32_t* a, const uint32_t* b) {
    asm volatile(
        "mma.sync.aligned.m16n8k16.row.col.f32.f16.f16.f32 "
        "{%0,%1,%2,%3}, {%4,%5,%6,%7}, {%8,%9}, {%0,%1,%2,%3};"
        : "+f"(c[0]), "+f"(c[1]), "+f"(c[2]), "+f"(c[3])
        : "r"(a[0]), "r"(a[1]), "r"(a[2]), "r"(a[3]), "r"(b[0]), "r"(b[1]));
}

__device__ __forceinline__ uint4 pack8h(__half2 a, __half2 b, __half2 c, __half2 d) {
    uint4 v;
    v.x = *(unsigned*)&a; v.y = *(unsigned*)&b;
    v.z = *(unsigned*)&c; v.w = *(unsigned*)&d;
    return v;
}

// ---------------------------------------------------------------------------
// Kernel 0: prep. Blocks 0-15: W^T split fp16. Block 16: u1 = W@a1, u2 = W@a2.
// ---------------------------------------------------------------------------
__global__ __launch_bounds__(256) void k_prep(const float* __restrict__ W,
                                              const float* __restrict__ a) {
    const int t = threadIdx.x;
    if (blockIdx.x < 16) {
        const int f  = blockIdx.x * 8 + (t >> 5);
        const int k0 = (t & 31) * 8;
        __half2 hi[4], lo[4];
#pragma unroll
        for (int p = 0; p < 4; p++) {
            float w0 = W[(k0 + 2 * p + 0) * FOUT + f];
            float w1 = W[(k0 + 2 * p + 1) * FOUT + f];
            __half2 hh = __floats2half2_rn(w0, w1);
            hi[p] = hh;
            lo[p] = __floats2half2_rn(w0 - __low2float(hh), w1 - __high2float(hh));
        }
        *(uint4*)&g_WT_hi[f * FIN + k0] = pack8h(hi[0], hi[1], hi[2], hi[3]);
        *(uint4*)&g_WT_lo[f * FIN + k0] = pack8h(lo[0], lo[1], lo[2], lo[3]);
    } else {
        __shared__ float sa[2 * FOUT];
        sa[t] = a[t];
        __syncthreads();
        const int k = t;
        const float4* wr = (const float4*)&W[k * FOUT];
        float a1 = 0.f, a2 = 0.f;
#pragma unroll 8
        for (int p = 0; p < FOUT / 4; p++) {
            float4 wv = wr[p];
            a1 += wv.x * sa[4*p] + wv.y * sa[4*p+1] + wv.z * sa[4*p+2] + wv.w * sa[4*p+3];
            a2 += wv.x * sa[FOUT+4*p] + wv.y * sa[FOUT+4*p+1]
                + wv.z * sa[FOUT+4*p+2] + wv.w * sa[FOUT+4*p+3];
        }
        g_u1[k] = a1;
        g_u2[k] = a2;
    }
}

// ---------------------------------------------------------------------------
// Kernel 1: Wh = h @ W via HMMA, A = fp16(h) single, B = W^T split (2 products).
// Fused exact scores (s1 = h.u1, s2 = h.u2 in fp32) + exps; WhT fp16 out.
// Grid 128 CTAs x 256 thr. CTA: 128 rows x 128 cols, K=256 in 4 chunks of 64.
// ---------------------------------------------------------------------------
__global__ __launch_bounds__(256) void k_wh(const float* __restrict__ h) {
    extern __shared__ char wsm[];
    __shared__ float s_u1[FIN], s_u2[FIN];

    const int t = threadIdx.x, w = t >> 5, lane = t & 31;
    const int bx = blockIdx.x;
    const size_t row0 = (size_t)bx * 128;
    const int b  = bx >> 4;
    const int n0 = (bx & 15) * 128;

    char* A_t  = wsm;
    char* B_hi = wsm + TILE_BYTES;
    char* B_lo = wsm + 2 * TILE_BYTES;
    const uint32_t sA = smem_u32(A_t);
    const uint32_t sB_hi = smem_u32(B_hi), sB_lo = smem_u32(B_lo);

    s_u1[t] = g_u1[t & 255];
    s_u2[t] = g_u2[t & 255];

    const int row = t >> 1, fq = t & 1;   // staging role: row 0..127, k half
    const float* __restrict__ hrow = h + (row0 + row) * (size_t)FIN + fq * 32;

    const int wm = w & 1, wn = w >> 1;
    const uint32_t aRow = (uint32_t)((wm * 64 + (lane & 15)) * (STRIDE * 2) + (lane >> 4) * 16);
    const uint32_t bRow = (uint32_t)((wn * 32 + (lane & 15)) * (STRIDE * 2) + (lane >> 4) * 16);

    float c[4][4][4];
#pragma unroll
    for (int mt = 0; mt < 4; mt++)
#pragma unroll
        for (int nt = 0; nt < 4; nt++)
#pragma unroll
            for (int r = 0; r < 4; r++) c[mt][nt][r] = 0.f;

    float s1p = 0.f, s2p = 0.f;

    for (int kc = 0; kc < 4; kc++) {
        const int k0 = kc * 64;
        __syncthreads();   // tiles free (prev mma done)

        // ---- load h (32 floats), score partials, convert+store A (fp16) ----
        float4 hv[8];
        const float4* hp = (const float4*)(hrow + k0);
#pragma unroll
        for (int g = 0; g < 8; g++) hv[g] = hp[g];

        const float4* u1v = (const float4*)&s_u1[k0 + fq * 32];
        const float4* u2v = (const float4*)&s_u2[k0 + fq * 32];
#pragma unroll
        for (int g = 0; g < 8; g++) {
            const float4 u1 = u1v[g], u2 = u2v[g];
            s1p += hv[g].x * u1.x + hv[g].y * u1.y + hv[g].z * u1.z + hv[g].w * u1.w;
            s2p += hv[g].x * u2.x + hv[g].y * u2.y + hv[g].z * u2.z + hv[g].w * u2.w;
        }

        char* ap = A_t + row * (STRIDE * 2) + fq * 64;
#pragma unroll
        for (int g = 0; g < 4; g++) {
            const float4 v0 = hv[2 * g], v1 = hv[2 * g + 1];
            *(uint4*)(ap + g * 16) = pack8h(__floats2half2_rn(v0.x, v0.y),
                                            __floats2half2_rn(v0.z, v0.w),
                                            __floats2half2_rn(v1.x, v1.y),
                                            __floats2half2_rn(v1.z, v1.w));
        }

        // ---- stage B (W^T split, preconverted): 32 halfs = 4 uint4 ----
        {
            const uint4* sh = (const uint4*)&g_WT_hi[row * FIN + k0 + fq * 32];
            const uint4* sl = (const uint4*)&g_WT_lo[row * FIN + k0 + fq * 32];
            char* bh = B_hi + row * (STRIDE * 2) + fq * 64;
            char* bl = B_lo + row * (STRIDE * 2) + fq * 64;
#pragma unroll
            for (int g = 0; g < 4; g++) {
                *(uint4*)(bh + g * 16) = sh[g];
                *(uint4*)(bl + g * 16) = sl[g];
            }
        }
        __syncthreads();

        // ---- mma: 4 k-steps of 16, 2 products ----
#pragma unroll
        for (int ks = 0; ks < 4; ks++) {
            const uint32_t kOff = ks * 32;
            uint32_t a4[4][4], bh4[4][2], bl4[4][2];
#pragma unroll
            for (int mt = 0; mt < 4; mt++) {
                const uint32_t mOff = aRow + mt * 16 * (STRIDE * 2) + kOff;
                LDSM_X4(a4[mt], sA + mOff);
            }
#pragma unroll
            for (int np = 0; np < 2; np++) {
                const uint32_t nOff = bRow + np * 16 * (STRIDE * 2) + kOff;
                uint32_t q[4];
                LDSM_X4(q, sB_hi + nOff);
                bh4[2*np][0] = q[0]; bh4[2*np][1] = q[2];
                bh4[2*np+1][0] = q[1]; bh4[2*np+1][1] = q[3];
                LDSM_X4(q, sB_lo + nOff);
                bl4[2*np][0] = q[0]; bl4[2*np][1] = q[2];
                bl4[2*np+1][0] = q[1]; bl4[2*np+1][1] = q[3];
            }
#pragma unroll
            for (int mt = 0; mt < 4; mt++)
#pragma unroll
                for (int nt = 0; nt < 4; nt++) {
                    mma16816(c[mt][nt], a4[mt], bh4[nt]);
                    mma16816(c[mt][nt], a4[mt], bl4[nt]);
                }
        }
    }

    // ---- scores: pair-reduce and write ----
    s1p += __shfl_xor_sync(0xFFFFFFFFu, s1p, 1);
    s2p += __shfl_xor_sync(0xFFFFFFFFu, s2p, 1);
    if (fq == 0) {
        const size_t r = row0 + row;
        g_s1[r] = s1p;
        g_s2[r] = s2p;
        g_E2[r] = expf(s2p);
        g_F2[r] = expf(0.2f * s2p);
    }

    // ---- WhT fp16 transposed store via smem ----
    __syncthreads();
    __half* s_T = (__half*)wsm;   // [128 f][136]
    const int qrow = lane >> 2, qcol = 2 * (lane & 3);
#pragma unroll
    for (int mt = 0; mt < 4; mt++) {
        const int r0 = wm * 64 + mt * 16 + qrow;
        const int r1 = r0 + 8;
#pragma unroll
        for (int nt = 0; nt < 4; nt++) {
            const int c0 = wn * 32 + nt * 8 + qcol;
            s_T[c0 * 136 + r0]       = __float2half_rn(c[mt][nt][0]);
            s_T[(c0 + 1) * 136 + r0] = __float2half_rn(c[mt][nt][1]);
            s_T[c0 * 136 + r1]       = __float2half_rn(c[mt][nt][2]);
            s_T[(c0 + 1) * 136 + r1] = __float2half_rn(c[mt][nt][3]);
        }
    }
    __syncthreads();
    {
        const int f = t >> 1, part = t & 1;
        const uint4* src = (const uint4*)&s_T[f * 136 + part * 64];
        uint4* dst = (uint4*)&g_WhT[((size_t)(b * FOUT + f)) * NN + n0 + part * 64];
#pragma unroll
        for (int i = 0; i < 8; i++) dst[i] = src[i];
    }
}

// ---------------------------------------------------------------------------
// Kernel 2: fused attention. A = row-normalized weights single fp16,
// B = Wh fp16 single -> 1 mma product per (mt,nt). Pipelined.
// ---------------------------------------------------------------------------
__global__ __launch_bounds__(256, 1) void k_attn(const int* __restrict__ adj,
                                                 float* __restrict__ out) {
    extern __shared__ char dsm[];
    __shared__ float s_Z[128][2];
    __shared__ float s_Zc[128];
    __shared__ float s_s2[NN], s_E2[NN], s_F2[NN];   // 24 KB
    __shared__ float s_red[8];

    const int t = threadIdx.x, w = t >> 5, lane = t & 31;
    const int b = blockIdx.y, i0 = blockIdx.x * 128;
    const size_t bn = (size_t)b * NN;

    // prologue: stage per-batch vectors, track max(s2)
    float mloc = -1e30f;
    {
        const float4* p2 = (const float4*)(g_s2 + bn);
        const float4* pe = (const float4*)(g_E2 + bn);
        const float4* pf = (const float4*)(g_F2 + bn);
#pragma unroll
        for (int i = t; i < NN / 4; i += 256) {
            const float4 v2 = p2[i];
            ((float4*)s_s2)[i] = v2;
            ((float4*)s_E2)[i] = pe[i];
            ((float4*)s_F2)[i] = pf[i];
            mloc = fmaxf(mloc, fmaxf(fmaxf(v2.x, v2.y), fmaxf(v2.z, v2.w)));
        }
    }
#pragma unroll
    for (int o = 16; o; o >>= 1) mloc = fmaxf(mloc, __shfl_xor_sync(0xFFFFFFFFu, mloc, o));
    if (lane == 0) s_red[w] = mloc;
    __syncthreads();
    float M2 = s_red[0];
#pragma unroll
    for (int i = 1; i < 8; i++) M2 = fmaxf(M2, s_red[i]);

    // ---- c-phase mapping: row = t>>1, jh = (t&1)*32 ----
    const int row = t >> 1;
    const int jh  = (t & 1) * 32;

    const float s1r = g_s1[bn + i0 + row];
    const float xm  = s1r + M2;
    const float m   = xm > 0.f ? xm : 0.2f * xm;
    const float E1n = expf(s1r - m);
    const float F1n = expf(0.2f * s1r - m);
    const int* __restrict__ adjrow = adj + (bn + i0 + row) * (size_t)NN;
    const __half* __restrict__ whp = g_WhT + ((size_t)b * FOUT + row) * NN;

    const int wm = w & 1, wn = w >> 1;
    const uint32_t aRow = (uint32_t)((wm * 64 + (lane & 15)) * (STRIDE * 2) + (lane >> 4) * 16);
    const uint32_t bRow = (uint32_t)((wn * 32 + (lane & 15)) * (STRIDE * 2) + (lane >> 4) * 16);

    float c[4][4][4];
#pragma unroll
    for (int mt = 0; mt < 4; mt++)
#pragma unroll
        for (int nt = 0; nt < 4; nt++)
#pragma unroll
            for (int r = 0; r < 4; r++) c[mt][nt][r] = 0.f;

    float Zreg = 0.f;

    // prefetch tile 0
    int4 radj[8];
    uint4 rwh[4];
    {
        const int4* am = (const int4*)(adjrow + jh);
#pragma unroll
        for (int q = 0; q < 8; q++) radj[q] = am[q];
        const uint4* sh = (const uint4*)(whp + jh);
#pragma unroll
        for (int g = 0; g < 4; g++) rwh[g] = sh[g];
    }
    __syncthreads();

    for (int jt = 0; jt < NTILES; jt++) {
        const int s = jt & 1;
        char* A_t = dsm + s * ATT_STAGE;
        char* B_t = A_t + TILE_BYTES;
        const int jg0 = jt * JT + jh;

        // ---- store B (fp16 Wh) from prefetch ----
        {
            char* bp = B_t + row * (STRIDE * 2) + jh * 2;
#pragma unroll
            for (int g = 0; g < 4; g++) *(uint4*)(bp + g * 16) = rwh[g];
        }
        // ---- build normalized c tile, fp16 single ----
        {
            float c32[32];
#pragma unroll
            for (int q = 0; q < 8; q++) {
                const int4 mv = radj[q];
                const float4 s2 = *(const float4*)&s_s2[jg0 + 4 * q];
                const float4 e2 = *(const float4*)&s_E2[jg0 + 4 * q];
                const float4 f2 = *(const float4*)&s_F2[jg0 + 4 * q];
                c32[4*q+0] = (mv.x > 0) ? ((s1r + s2.x > 0.f) ? E1n * e2.x : F1n * f2.x) : 0.f;
                c32[4*q+1] = (mv.y > 0) ? ((s1r + s2.y > 0.f) ? E1n * e2.y : F1n * f2.y) : 0.f;
                c32[4*q+2] = (mv.z > 0) ? ((s1r + s2.z > 0.f) ? E1n * e2.z : F1n * f2.z) : 0.f;
                c32[4*q+3] = (mv.w > 0) ? ((s1r + s2.w > 0.f) ? E1n * e2.w : F1n * f2.w) : 0.f;
            }
#pragma unroll
            for (int k = 0; k < 32; k++) Zreg += c32[k];
            char* ap = A_t + row * (STRIDE * 2) + jh * 2;
#pragma unroll
            for (int g = 0; g < 4; g++) {
                *(uint4*)(ap + g * 16) = pack8h(
                    __floats2half2_rn(c32[g*8+0], c32[g*8+1]),
                    __floats2half2_rn(c32[g*8+2], c32[g*8+3]),
                    __floats2half2_rn(c32[g*8+4], c32[g*8+5]),
                    __floats2half2_rn(c32[g*8+6], c32[g*8+7]));
            }
        }

        __syncthreads();

        // ---- prefetch next tile under the mma phase ----
        if (jt + 1 < NTILES) {
            const int jg1 = (jt + 1) * JT + jh;
            const int4* am = (const int4*)(adjrow + jg1);
#pragma unroll
            for (int q = 0; q < 8; q++) radj[q] = am[q];
            const uint4* sh = (const uint4*)(whp + jg1);
#pragma unroll
            for (int g = 0; g < 4; g++) rwh[g] = sh[g];
        }

        // ---- mma: 4 k-steps, 1 product ----
        const uint32_t sA = smem_u32(A_t);
        const uint32_t sB = smem_u32(B_t);
#pragma unroll
        for (int ks = 0; ks < 4; ks++) {
            const uint32_t kOff = ks * 32;
            uint32_t a4[4][4], b4[4][2];
#pragma unroll
            for (int mt = 0; mt < 4; mt++) {
                const uint32_t mOff = aRow + mt * 16 * (STRIDE * 2) + kOff;
                LDSM_X4(a4[mt], sA + mOff);
            }
#pragma unroll
            for (int np = 0; np < 2; np++) {
                const uint32_t nOff = bRow + np * 16 * (STRIDE * 2) + kOff;
                uint32_t q[4];
                LDSM_X4(q, sB + nOff);
                b4[2*np][0] = q[0]; b4[2*np][1] = q[2];
                b4[2*np+1][0] = q[1]; b4[2*np+1][1] = q[3];
            }
#pragma unroll
            for (int mt = 0; mt < 4; mt++)
#pragma unroll
                for (int nt = 0; nt < 4; nt++)
                    mma16816(c[mt][nt], a4[mt], b4[nt]);
        }
    }

    // ---- combine Z, normalize + ELU + store ----
    s_Z[row][t & 1] = Zreg;
    __syncthreads();
    if (t < 128) s_Zc[t] = s_Z[t][0] + s_Z[t][1];
    __syncthreads();

    const int qrow = lane >> 2, qcol = 2 * (lane & 3);
#pragma unroll
    for (int mt = 0; mt < 4; mt++) {
        const int r0 = wm * 64 + mt * 16 + qrow;
        const int r1 = r0 + 8;
        const float zi0 = 1.0f / s_Zc[r0];
        const float zi1 = 1.0f / s_Zc[r1];
        float* op0 = out + (bn + i0 + r0) * (size_t)FOUT;
        float* op1 = out + (bn + i0 + r1) * (size_t)FOUT;
#pragma unroll
        for (int nt = 0; nt < 4; nt++) {
            const int col = wn * 32 + nt * 8 + qcol;
            float x0 = c[mt][nt][0] * zi0;
            float x1 = c[mt][nt][1] * zi0;
            float x2 = c[mt][nt][2] * zi1;
            float x3 = c[mt][nt][3] * zi1;
            float2 v0, v1;
            v0.x = x0 > 0.f ? x0 : expm1f(x0);
            v0.y = x1 > 0.f ? x1 : expm1f(x1);
            v1.x = x2 > 0.f ? x2 : expm1f(x2);
            v1.y = x3 > 0.f ? x3 : expm1f(x3);
            *(float2*)(op0 + col) = v0;
            *(float2*)(op1 + col) = v1;
        }
    }
}

// ---------------------------------------------------------------------------
extern "C" void kernel_launch(void* const* d_in, const int* in_sizes, int n_in,
                              void* d_out, int out_size) {
    const float* h = nullptr; const int* adj = nullptr;
    const float* W = nullptr; const float* a = nullptr;
    for (int i = 0; i < n_in; i++) {
        switch (in_sizes[i]) {
            case 4194304:  h   = (const float*)d_in[i]; break;
            case 33554432: adj = (const int*)d_in[i];   break;
            case 32768:    W   = (const float*)d_in[i]; break;
            case 256:      a   = (const float*)d_in[i]; break;
        }
    }
    float* out = (float*)d_out;

    static bool attr_set = false;
    if (!attr_set) {
        cudaFuncSetAttribute(k_wh, cudaFuncAttributeMaxDynamicSharedMemorySize,
                             WH_DSMEM);
        cudaFuncSetAttribute(k_attn, cudaFuncAttributeMaxDynamicSharedMemorySize,
                             ATT_DSMEM);
        attr_set = true;
    }

    k_prep<<<17, 256>>>(W, a);
    k_wh<<<BN / 128, 256, WH_DSMEM>>>(h);
    k_attn<<<dim3(NN / 128, BB), 256, ATT_DSMEM>>>(adj, out);
}

// round 8
// speedup vs baseline: 3.9033x; 1.1757x over previous
#include <cuda_runtime.h>
#include <cuda_fp16.h>
#include <cstdint>
#include <math.h>

#define BB 8
#define NN 2048
#define FIN 256
#define FOUT 128
#define BN (BB*NN)   // 16384 rows total

#define JT 64                     // j-tile (K of the attn mma loop)
#define NTILES (NN/JT)            // 32
#define STRIDE 72                 // b16 elems per smem row (144 B) - conflict-free ldmatrix
#define TILE_BYTES (128*STRIDE*2)          // 18432 per tile
#define ATT_STAGE (2*TILE_BYTES)           // A, B = 36864
#define ATT_DSMEM (2*ATT_STAGE)            // 73728
#define WH_DSMEM  (3*TILE_BYTES)           // A, B_hi, B_lo = 55296

// Scratch (static device arrays; allocation is forbidden)
__device__ __half g_WT_hi[FIN * FOUT];                 // [f][k] W^T split hi
__device__ __half g_WT_lo[FIN * FOUT];                 // [f][k] W^T split lo
__device__ float  g_u1[FIN], g_u2[FIN];                // W@a1, W@a2
__device__ __half g_WhT[(size_t)BB * FOUT * NN];       // [b][f][n] Wh fp16 (single)
__device__ float  g_s1[BN], g_s2[BN], g_E2[BN], g_F2[BN];

// ---------------------------------------------------------------------------
__device__ __forceinline__ uint32_t smem_u32(const void* p) {
    uint32_t a;
    asm("{ .reg .u64 t; cvta.to.shared.u64 t, %1; cvt.u32.u64 %0, t; }"
        : "=r"(a) : "l"(p));
    return a;
}

#define LDSM_X4(r, addr) \
    asm volatile("ldmatrix.sync.aligned.m8n8.x4.shared.b16 {%0,%1,%2,%3}, [%4];" \
        : "=r"((r)[0]), "=r"((r)[1]), "=r"((r)[2]), "=r"((r)[3]) : "r"(addr))

__device__ __forceinline__ void mma16816(float* c, const uint32_t* a, const uint32_t* b) {
    asm volatile(
        "mma.sync.aligned.m16n8k16.row.col.f32.f16.f16.f32 "
        "{%0,%1,%2,%3}, {%4,%5,%6,%7}, {%8,%9}, {%0,%1,%2,%3};"
        : "+f"(c[0]), "+f"(c[1]), "+f"(c[2]), "+f"(c[3])
        : "r"(a[0]), "r"(a[1]), "r"(a[2]), "r"(a[3]), "r"(b[0]), "r"(b[1]));
}

__device__ __forceinline__ uint4 pack8h(__half2 a, __half2 b, __half2 c, __half2 d) {
    uint4 v;
    v.x = *(unsigned*)&a; v.y = *(unsigned*)&b;
    v.z = *(unsigned*)&c; v.w = *(unsigned*)&d;
    return v;
}

// ---------------------------------------------------------------------------
// Kernel 0: prep. Blocks 0-15: W^T split fp16. Block 16: u1 = W@a1, u2 = W@a2.
// ---------------------------------------------------------------------------
__global__ __launch_bounds__(256) void k_prep(const float* __restrict__ W,
                                              const float* __restrict__ a) {
    const int t = threadIdx.x;
    if (blockIdx.x < 16) {
        const int f  = blockIdx.x * 8 + (t >> 5);
        const int k0 = (t & 31) * 8;
        __half2 hi[4], lo[4];
#pragma unroll
        for (int p = 0; p < 4; p++) {
            float w0 = W[(k0 + 2 * p + 0) * FOUT + f];
            float w1 = W[(k0 + 2 * p + 1) * FOUT + f];
            __half2 hh = __floats2half2_rn(w0, w1);
            hi[p] = hh;
            lo[p] = __floats2half2_rn(w0 - __low2float(hh), w1 - __high2float(hh));
        }
        *(uint4*)&g_WT_hi[f * FIN + k0] = pack8h(hi[0], hi[1], hi[2], hi[3]);
        *(uint4*)&g_WT_lo[f * FIN + k0] = pack8h(lo[0], lo[1], lo[2], lo[3]);
    } else {
        __shared__ float sa[2 * FOUT];
        sa[t] = a[t];
        __syncthreads();
        const int k = t;
        const float4* wr = (const float4*)&W[k * FOUT];
        float a1 = 0.f, a2 = 0.f;
#pragma unroll 8
        for (int p = 0; p < FOUT / 4; p++) {
            float4 wv = wr[p];
            a1 += wv.x * sa[4*p] + wv.y * sa[4*p+1] + wv.z * sa[4*p+2] + wv.w * sa[4*p+3];
            a2 += wv.x * sa[FOUT+4*p] + wv.y * sa[FOUT+4*p+1]
                + wv.z * sa[FOUT+4*p+2] + wv.w * sa[FOUT+4*p+3];
        }
        g_u1[k] = a1;
        g_u2[k] = a2;
    }
}

// ---------------------------------------------------------------------------
// Kernel 1: Wh = h @ W via HMMA, A = fp16(h) single, B = W^T split (2 products).
// Fused exact scores (s1 = h.u1, s2 = h.u2 in fp32) + exps; WhT fp16 out.
// ---------------------------------------------------------------------------
__global__ __launch_bounds__(256) void k_wh(const float* __restrict__ h) {
    extern __shared__ char wsm[];
    __shared__ float s_u1[FIN], s_u2[FIN];

    const int t = threadIdx.x, w = t >> 5, lane = t & 31;
    const int bx = blockIdx.x;
    const size_t row0 = (size_t)bx * 128;
    const int b  = bx >> 4;
    const int n0 = (bx & 15) * 128;

    char* A_t  = wsm;
    char* B_hi = wsm + TILE_BYTES;
    char* B_lo = wsm + 2 * TILE_BYTES;
    const uint32_t sA = smem_u32(A_t);
    const uint32_t sB_hi = smem_u32(B_hi), sB_lo = smem_u32(B_lo);

    s_u1[t] = g_u1[t & 255];
    s_u2[t] = g_u2[t & 255];

    const int row = t >> 1, fq = t & 1;   // staging role: row 0..127, k half
    const float* __restrict__ hrow = h + (row0 + row) * (size_t)FIN + fq * 32;

    const int wm = w & 1, wn = w >> 1;
    const uint32_t aRow = (uint32_t)((wm * 64 + (lane & 15)) * (STRIDE * 2) + (lane >> 4) * 16);
    const uint32_t bRow = (uint32_t)((wn * 32 + (lane & 15)) * (STRIDE * 2) + (lane >> 4) * 16);

    float c[4][4][4];
#pragma unroll
    for (int mt = 0; mt < 4; mt++)
#pragma unroll
        for (int nt = 0; nt < 4; nt++)
#pragma unroll
            for (int r = 0; r < 4; r++) c[mt][nt][r] = 0.f;

    float s1p = 0.f, s2p = 0.f;

    for (int kc = 0; kc < 4; kc++) {
        const int k0 = kc * 64;
        __syncthreads();   // tiles free (prev mma done)

        // ---- load h (32 floats), score partials, convert+store A (fp16) ----
        float4 hv[8];
        const float4* hp = (const float4*)(hrow + k0);
#pragma unroll
        for (int g = 0; g < 8; g++) hv[g] = hp[g];

        const float4* u1v = (const float4*)&s_u1[k0 + fq * 32];
        const float4* u2v = (const float4*)&s_u2[k0 + fq * 32];
#pragma unroll
        for (int g = 0; g < 8; g++) {
            const float4 u1 = u1v[g], u2 = u2v[g];
            s1p += hv[g].x * u1.x + hv[g].y * u1.y + hv[g].z * u1.z + hv[g].w * u1.w;
            s2p += hv[g].x * u2.x + hv[g].y * u2.y + hv[g].z * u2.z + hv[g].w * u2.w;
        }

        char* ap = A_t + row * (STRIDE * 2) + fq * 64;
#pragma unroll
        for (int g = 0; g < 4; g++) {
            const float4 v0 = hv[2 * g], v1 = hv[2 * g + 1];
            *(uint4*)(ap + g * 16) = pack8h(__floats2half2_rn(v0.x, v0.y),
                                            __floats2half2_rn(v0.z, v0.w),
                                            __floats2half2_rn(v1.x, v1.y),
                                            __floats2half2_rn(v1.z, v1.w));
        }

        // ---- stage B (W^T split, preconverted): 32 halfs = 4 uint4 ----
        {
            const uint4* sh = (const uint4*)&g_WT_hi[row * FIN + k0 + fq * 32];
            const uint4* sl = (const uint4*)&g_WT_lo[row * FIN + k0 + fq * 32];
            char* bh = B_hi + row * (STRIDE * 2) + fq * 64;
            char* bl = B_lo + row * (STRIDE * 2) + fq * 64;
#pragma unroll
            for (int g = 0; g < 4; g++) {
                *(uint4*)(bh + g * 16) = sh[g];
                *(uint4*)(bl + g * 16) = sl[g];
            }
        }
        __syncthreads();

        // ---- mma: 4 k-steps of 16, 2 products ----
#pragma unroll
        for (int ks = 0; ks < 4; ks++) {
            const uint32_t kOff = ks * 32;
            uint32_t a4[4][4], bh4[4][2], bl4[4][2];
#pragma unroll
            for (int mt = 0; mt < 4; mt++) {
                const uint32_t mOff = aRow + mt * 16 * (STRIDE * 2) + kOff;
                LDSM_X4(a4[mt], sA + mOff);
            }
#pragma unroll
            for (int np = 0; np < 2; np++) {
                const uint32_t nOff = bRow + np * 16 * (STRIDE * 2) + kOff;
                uint32_t q[4];
                LDSM_X4(q, sB_hi + nOff);
                bh4[2*np][0] = q[0]; bh4[2*np][1] = q[2];
                bh4[2*np+1][0] = q[1]; bh4[2*np+1][1] = q[3];
                LDSM_X4(q, sB_lo + nOff);
                bl4[2*np][0] = q[0]; bl4[2*np][1] = q[2];
                bl4[2*np+1][0] = q[1]; bl4[2*np+1][1] = q[3];
            }
#pragma unroll
            for (int mt = 0; mt < 4; mt++)
#pragma unroll
                for (int nt = 0; nt < 4; nt++) {
                    mma16816(c[mt][nt], a4[mt], bh4[nt]);
                    mma16816(c[mt][nt], a4[mt], bl4[nt]);
                }
        }
    }

    // ---- scores: pair-reduce and write ----
    s1p += __shfl_xor_sync(0xFFFFFFFFu, s1p, 1);
    s2p += __shfl_xor_sync(0xFFFFFFFFu, s2p, 1);
    if (fq == 0) {
        const size_t r = row0 + row;
        g_s1[r] = s1p;
        g_s2[r] = s2p;
        g_E2[r] = expf(s2p);
        g_F2[r] = expf(0.2f * s2p);
    }

    // ---- WhT fp16 transposed store via smem ----
    __syncthreads();
    __half* s_T = (__half*)wsm;   // [128 f][136]
    const int qrow = lane >> 2, qcol = 2 * (lane & 3);
#pragma unroll
    for (int mt = 0; mt < 4; mt++) {
        const int r0 = wm * 64 + mt * 16 + qrow;
        const int r1 = r0 + 8;
#pragma unroll
        for (int nt = 0; nt < 4; nt++) {
            const int c0 = wn * 32 + nt * 8 + qcol;
            s_T[c0 * 136 + r0]       = __float2half_rn(c[mt][nt][0]);
            s_T[(c0 + 1) * 136 + r0] = __float2half_rn(c[mt][nt][1]);
            s_T[c0 * 136 + r1]       = __float2half_rn(c[mt][nt][2]);
            s_T[(c0 + 1) * 136 + r1] = __float2half_rn(c[mt][nt][3]);
        }
    }
    __syncthreads();
    {
        const int f = t >> 1, part = t & 1;
        const uint4* src = (const uint4*)&s_T[f * 136 + part * 64];
        uint4* dst = (uint4*)&g_WhT[((size_t)(b * FOUT + f)) * NN + n0 + part * 64];
#pragma unroll
        for (int i = 0; i < 8; i++) dst[i] = src[i];
    }
}

// ---------------------------------------------------------------------------
// Kernel 2: fused attention, 512 threads (16 warps).
// A = row-normalized weights single fp16, B = Wh fp16 single, 1 product.
// c-phase: row = t>>2, jq = (t&3)*16 (16 j's per thread).
// mma: wm = w&3 (32-row block), wn = w>>2 (32-col block); warp tile 32x32.
// ---------------------------------------------------------------------------
__global__ __launch_bounds__(512, 1) void k_attn(const int* __restrict__ adj,
                                                 float* __restrict__ out) {
    extern __shared__ char dsm[];
    __shared__ float s_Z[128][4];
    __shared__ float s_Zc[128];
    __shared__ float s_s2[NN], s_E2[NN], s_F2[NN];   // 24 KB
    __shared__ float s_red[16];

    const int t = threadIdx.x, w = t >> 5, lane = t & 31;
    const int b = blockIdx.y, i0 = blockIdx.x * 128;
    const size_t bn = (size_t)b * NN;

    // prologue: stage per-batch vectors, track max(s2)
    float mloc = -1e30f;
    {
        const float4* p2 = (const float4*)(g_s2 + bn);
        const float4* pe = (const float4*)(g_E2 + bn);
        const float4* pf = (const float4*)(g_F2 + bn);
        const float4 v2 = p2[t];
        ((float4*)s_s2)[t] = v2;
        ((float4*)s_E2)[t] = pe[t];
        ((float4*)s_F2)[t] = pf[t];
        mloc = fmaxf(fmaxf(v2.x, v2.y), fmaxf(v2.z, v2.w));
    }
#pragma unroll
    for (int o = 16; o; o >>= 1) mloc = fmaxf(mloc, __shfl_xor_sync(0xFFFFFFFFu, mloc, o));
    if (lane == 0) s_red[w] = mloc;
    __syncthreads();
    float M2 = s_red[0];
#pragma unroll
    for (int i = 1; i < 16; i++) M2 = fmaxf(M2, s_red[i]);

    // ---- c-phase mapping ----
    const int row = t >> 2;
    const int jq  = (t & 3) * 16;

    const float s1r = g_s1[bn + i0 + row];
    const float xm  = s1r + M2;
    const float m   = xm > 0.f ? xm : 0.2f * xm;
    const float E1n = expf(s1r - m);
    const float F1n = expf(0.2f * s1r - m);
    const int* __restrict__ adjrow = adj + (bn + i0 + row) * (size_t)NN;
    const __half* __restrict__ whp = g_WhT + ((size_t)b * FOUT + row) * NN;

    // ---- mma-phase addressing: warp tile 32(m) x 32(n) ----
    const int wm = w & 3, wn = w >> 2;
    const uint32_t aRow = (uint32_t)((wm * 32 + (lane & 15)) * (STRIDE * 2) + (lane >> 4) * 16);
    const uint32_t bRow = (uint32_t)((wn * 32 + (lane & 15)) * (STRIDE * 2) + (lane >> 4) * 16);

    float c[2][4][4];
#pragma unroll
    for (int mt = 0; mt < 2; mt++)
#pragma unroll
        for (int nt = 0; nt < 4; nt++)
#pragma unroll
            for (int r = 0; r < 4; r++) c[mt][nt][r] = 0.f;

    float Zreg = 0.f;

    // prefetch tile 0
    int4 radj[4];
    uint4 rwh[2];
    {
        const int4* am = (const int4*)(adjrow + jq);
#pragma unroll
        for (int q = 0; q < 4; q++) radj[q] = am[q];
        const uint4* sh = (const uint4*)(whp + jq);
        rwh[0] = sh[0]; rwh[1] = sh[1];
    }
    __syncthreads();

    for (int jt = 0; jt < NTILES; jt++) {
        const int s = jt & 1;
        char* A_t = dsm + s * ATT_STAGE;
        char* B_t = A_t + TILE_BYTES;
        const int jg0 = jt * JT + jq;

        // ---- store B (fp16 Wh) from prefetch ----
        {
            char* bp = B_t + row * (STRIDE * 2) + jq * 2;
            *(uint4*)(bp)      = rwh[0];
            *(uint4*)(bp + 16) = rwh[1];
        }
        // ---- build normalized c tile (16 weights), fp16 single ----
        {
            float c16[16];
#pragma unroll
            for (int q = 0; q < 4; q++) {
                const int4 mv = radj[q];
                const float4 s2 = *(const float4*)&s_s2[jg0 + 4 * q];
                const float4 e2 = *(const float4*)&s_E2[jg0 + 4 * q];
                const float4 f2 = *(const float4*)&s_F2[jg0 + 4 * q];
                c16[4*q+0] = (mv.x > 0) ? ((s1r + s2.x > 0.f) ? E1n * e2.x : F1n * f2.x) : 0.f;
                c16[4*q+1] = (mv.y > 0) ? ((s1r + s2.y > 0.f) ? E1n * e2.y : F1n * f2.y) : 0.f;
                c16[4*q+2] = (mv.z > 0) ? ((s1r + s2.z > 0.f) ? E1n * e2.z : F1n * f2.z) : 0.f;
                c16[4*q+3] = (mv.w > 0) ? ((s1r + s2.w > 0.f) ? E1n * e2.w : F1n * f2.w) : 0.f;
            }
#pragma unroll
            for (int k = 0; k < 16; k++) Zreg += c16[k];
            char* ap = A_t + row * (STRIDE * 2) + jq * 2;
            *(uint4*)(ap) = pack8h(
                __floats2half2_rn(c16[0], c16[1]),
                __floats2half2_rn(c16[2], c16[3]),
                __floats2half2_rn(c16[4], c16[5]),
                __floats2half2_rn(c16[6], c16[7]));
            *(uint4*)(ap + 16) = pack8h(
                __floats2half2_rn(c16[8],  c16[9]),
                __floats2half2_rn(c16[10], c16[11]),
                __floats2half2_rn(c16[12], c16[13]),
                __floats2half2_rn(c16[14], c16[15]));
        }

        __syncthreads();

        // ---- prefetch next tile under the mma phase ----
        if (jt + 1 < NTILES) {
            const int jg1 = (jt + 1) * JT + jq;
            const int4* am = (const int4*)(adjrow + jg1);
#pragma unroll
            for (int q = 0; q < 4; q++) radj[q] = am[q];
            const uint4* sh = (const uint4*)(whp + jg1);
            rwh[0] = sh[0]; rwh[1] = sh[1];
        }

        // ---- mma: 4 k-steps, warp tile 32x32 ----
        const uint32_t sA = smem_u32(A_t);
        const uint32_t sB = smem_u32(B_t);
#pragma unroll
        for (int ks = 0; ks < 4; ks++) {
            const uint32_t kOff = ks * 32;
            uint32_t a4[2][4], b4[4][2];
#pragma unroll
            for (int mt = 0; mt < 2; mt++) {
                const uint32_t mOff = aRow + mt * 16 * (STRIDE * 2) + kOff;
                LDSM_X4(a4[mt], sA + mOff);
            }
#pragma unroll
            for (int np = 0; np < 2; np++) {
                const uint32_t nOff = bRow + np * 16 * (STRIDE * 2) + kOff;
                uint32_t q[4];
                LDSM_X4(q, sB + nOff);
                b4[2*np][0] = q[0]; b4[2*np][1] = q[2];
                b4[2*np+1][0] = q[1]; b4[2*np+1][1] = q[3];
            }
#pragma unroll
            for (int mt = 0; mt < 2; mt++)
#pragma unroll
                for (int nt = 0; nt < 4; nt++)
                    mma16816(c[mt][nt], a4[mt], b4[nt]);
        }
    }

    // ---- combine Z, normalize + ELU + store ----
    s_Z[row][t & 3] = Zreg;
    __syncthreads();
    if (t < 128) s_Zc[t] = (s_Z[t][0] + s_Z[t][1]) + (s_Z[t][2] + s_Z[t][3]);
    __syncthreads();

    const int qrow = lane >> 2, qcol = 2 * (lane & 3);
#pragma unroll
    for (int mt = 0; mt < 2; mt++) {
        const int r0 = wm * 32 + mt * 16 + qrow;
        const int r1 = r0 + 8;
        const float zi0 = 1.0f / s_Zc[r0];
        const float zi1 = 1.0f / s_Zc[r1];
        float* op0 = out + (bn + i0 + r0) * (size_t)FOUT;
        float* op1 = out + (bn + i0 + r1) * (size_t)FOUT;
#pragma unroll
        for (int nt = 0; nt < 4; nt++) {
            const int col = wn * 32 + nt * 8 + qcol;
            float x0 = c[mt][nt][0] * zi0;
            float x1 = c[mt][nt][1] * zi0;
            float x2 = c[mt][nt][2] * zi1;
            float x3 = c[mt][nt][3] * zi1;
            float2 v0, v1;
            v0.x = x0 > 0.f ? x0 : expm1f(x0);
            v0.y = x1 > 0.f ? x1 : expm1f(x1);
            v1.x = x2 > 0.f ? x2 : expm1f(x2);
            v1.y = x3 > 0.f ? x3 : expm1f(x3);
            *(float2*)(op0 + col) = v0;
            *(float2*)(op1 + col) = v1;
        }
    }
}

// ---------------------------------------------------------------------------
extern "C" void kernel_launch(void* const* d_in, const int* in_sizes, int n_in,
                              void* d_out, int out_size) {
    const float* h = nullptr; const int* adj = nullptr;
    const float* W = nullptr; const float* a = nullptr;
    for (int i = 0; i < n_in; i++) {
        switch (in_sizes[i]) {
            case 4194304:  h   = (const float*)d_in[i]; break;
            case 33554432: adj = (const int*)d_in[i];   break;
            case 32768:    W   = (const float*)d_in[i]; break;
            case 256:      a   = (const float*)d_in[i]; break;
        }
    }
    float* out = (float*)d_out;

    static bool attr_set = false;
    if (!attr_set) {
        cudaFuncSetAttribute(k_wh, cudaFuncAttributeMaxDynamicSharedMemorySize,
                             WH_DSMEM);
        cudaFuncSetAttribute(k_attn, cudaFuncAttributeMaxDynamicSharedMemorySize,
                             ATT_DSMEM);
        attr_set = true;
    }

    k_prep<<<17, 256>>>(W, a);
    k_wh<<<BN / 128, 256, WH_DSMEM>>>(h);
    k_attn<<<dim3(NN / 128, BB), 512, ATT_DSMEM>>>(adj, out);
}

// round 9
// speedup vs baseline: 4.1894x; 1.0733x over previous
#include <cuda_runtime.h>
#include <cuda_fp16.h>
#include <cstdint>
#include <math.h>

#define BB 8
#define NN 2048
#define FIN 256
#define FOUT 128
#define BN (BB*NN)   // 16384 rows total

#define JT 64                     // j-tile (K of the attn mma loop)
#define NTILES (NN/JT)            // 32
#define STRIDE 72                 // b16 elems per smem row (144 B) - conflict-free ldmatrix
#define TILE_BYTES (128*STRIDE*2)          // 18432 per tile
#define ATT_STAGE (2*TILE_BYTES)           // A, B = 36864
#define ATT_DSMEM (2*ATT_STAGE)            // 73728

#define WT_STRIDE 264                      // halfs per s_W row (528 B), LDSM conflict-free
#define WT_BYTES (FOUT*WT_STRIDE*2)        // 67584
#define WH_DSMEM (2*TILE_BYTES + WT_BYTES) // A0, A1, s_W = 104448

// Scratch (static device arrays; allocation is forbidden)
__device__ __half g_WhT[(size_t)BB * FOUT * NN];       // [b][f][n] Wh fp16 (single)
__device__ float  g_s1[BN], g_s2[BN], g_E2[BN], g_F2[BN];

// ---------------------------------------------------------------------------
__device__ __forceinline__ uint32_t smem_u32(const void* p) {
    uint32_t a;
    asm("{ .reg .u64 t; cvta.to.shared.u64 t, %1; cvt.u32.u64 %0, t; }"
        : "=r"(a) : "l"(p));
    return a;
}

#define LDSM_X4(r, addr) \
    asm volatile("ldmatrix.sync.aligned.m8n8.x4.shared.b16 {%0,%1,%2,%3}, [%4];" \
        : "=r"((r)[0]), "=r"((r)[1]), "=r"((r)[2]), "=r"((r)[3]) : "r"(addr))

__device__ __forceinline__ void mma16816(float* c, const uint32_t* a, const uint32_t* b) {
    asm volatile(
        "mma.sync.aligned.m16n8k16.row.col.f32.f16.f16.f32 "
        "{%0,%1,%2,%3}, {%4,%5,%6,%7}, {%8,%9}, {%0,%1,%2,%3};"
        : "+f"(c[0]), "+f"(c[1]), "+f"(c[2]), "+f"(c[3])
        : "r"(a[0]), "r"(a[1]), "r"(a[2]), "r"(a[3]), "r"(b[0]), "r"(b[1]));
}

__device__ __forceinline__ uint4 pack8h(__half2 a, __half2 b, __half2 c, __half2 d) {
    uint4 v;
    v.x = *(unsigned*)&a; v.y = *(unsigned*)&b;
    v.z = *(unsigned*)&c; v.w = *(unsigned*)&d;
    return v;
}

// ---------------------------------------------------------------------------
// Kernel 1: Wh = h @ W via HMMA, single fp16 product. Self-contained:
// prologue transposes W to fp16 smem + computes u1/u2 (fp32 exact).
// Fused exact scores (s1 = h.u1, s2 = h.u2) + exps; WhT fp16 out.
// Grid 128 CTAs x 256 thr. CTA: 128 rows x 128 cols, K=256 in 4 chunks of 64.
// ---------------------------------------------------------------------------
__global__ __launch_bounds__(256) void k_wh(const float* __restrict__ h,
                                            const float* __restrict__ W,
                                            const float* __restrict__ a) {
    extern __shared__ char wsm[];
    __shared__ float s_u1[FIN], s_u2[FIN];
    __shared__ float s_a[2 * FOUT];

    const int t = threadIdx.x, w = t >> 5, lane = t & 31;
    const int bx = blockIdx.x;
    const size_t row0 = (size_t)bx * 128;
    const int b  = bx >> 4;
    const int n0 = (bx & 15) * 128;

    char* A0  = wsm;                       // A double buffer
    char* s_Wc = wsm + 2 * TILE_BYTES;     // persistent W^T fp16
    __half* sW = (__half*)s_Wc;
    const uint32_t sWu = smem_u32(s_Wc);

    // ---- prologue: load a; transpose W -> fp16 smem; u1/u2 fp32 ----
    s_a[t] = a[t];
    __syncthreads();
    {
        const int kk = w * 32;     // warp's 32 k-rows
#pragma unroll 4
        for (int i = 0; i < 32; i++) {
            const int k = kk + i;
            float wv[4];
#pragma unroll
            for (int p = 0; p < 4; p++) wv[p] = W[k * FOUT + lane + p * 32];
            float u1p = 0.f, u2p = 0.f;
#pragma unroll
            for (int p = 0; p < 4; p++) {
                u1p += wv[p] * s_a[lane + p * 32];
                u2p += wv[p] * s_a[FOUT + lane + p * 32];
            }
#pragma unroll
            for (int p = 0; p < 4; p++)
                sW[(lane + p * 32) * WT_STRIDE + k] = __float2half_rn(wv[p]);
#pragma unroll
            for (int o = 16; o; o >>= 1) {
                u1p += __shfl_xor_sync(0xFFFFFFFFu, u1p, o);
                u2p += __shfl_xor_sync(0xFFFFFFFFu, u2p, o);
            }
            if (lane == 0) { s_u1[k] = u1p; s_u2[k] = u2p; }
        }
    }

    const int row = t >> 1, fq = t & 1;   // staging role: row 0..127, k half
    const float* __restrict__ hrow = h + (row0 + row) * (size_t)FIN + fq * 32;

    const int wm = w & 1, wn = w >> 1;
    const uint32_t aRow = (uint32_t)((wm * 64 + (lane & 15)) * (STRIDE * 2) + (lane >> 4) * 16);
    const uint32_t bRowW = (uint32_t)((wn * 32 + (lane & 15)) * (WT_STRIDE * 2) + (lane >> 4) * 16);

    float c[4][4][4];
#pragma unroll
    for (int mt = 0; mt < 4; mt++)
#pragma unroll
        for (int nt = 0; nt < 4; nt++)
#pragma unroll
            for (int r = 0; r < 4; r++) c[mt][nt][r] = 0.f;

    float s1p = 0.f, s2p = 0.f;

    // prefetch h chunk 0
    float4 hv[8];
    {
        const float4* hp = (const float4*)(hrow);
#pragma unroll
        for (int g = 0; g < 8; g++) hv[g] = hp[g];
    }
    __syncthreads();   // s_W, s_u ready

    for (int kc = 0; kc < 4; kc++) {
        const int k0 = kc * 64;
        const int s = kc & 1;
        char* A_t = A0 + s * TILE_BYTES;

        // ---- score partials + convert/store A (fp16) from prefetched h ----
        {
            const float4* u1v = (const float4*)&s_u1[k0 + fq * 32];
            const float4* u2v = (const float4*)&s_u2[k0 + fq * 32];
#pragma unroll
            for (int g = 0; g < 8; g++) {
                const float4 u1 = u1v[g], u2 = u2v[g];
                s1p += hv[g].x * u1.x + hv[g].y * u1.y + hv[g].z * u1.z + hv[g].w * u1.w;
                s2p += hv[g].x * u2.x + hv[g].y * u2.y + hv[g].z * u2.z + hv[g].w * u2.w;
            }
            char* ap = A_t + row * (STRIDE * 2) + fq * 64;
#pragma unroll
            for (int g = 0; g < 4; g++) {
                const float4 v0 = hv[2 * g], v1 = hv[2 * g + 1];
                *(uint4*)(ap + g * 16) = pack8h(__floats2half2_rn(v0.x, v0.y),
                                                __floats2half2_rn(v0.z, v0.w),
                                                __floats2half2_rn(v1.x, v1.y),
                                                __floats2half2_rn(v1.z, v1.w));
            }
        }
        __syncthreads();

        // ---- prefetch next h chunk under the mma ----
        if (kc < 3) {
            const float4* hp = (const float4*)(hrow + (kc + 1) * 64);
#pragma unroll
            for (int g = 0; g < 8; g++) hv[g] = hp[g];
        }

        // ---- mma: 4 k-steps of 16, 1 product; B from persistent s_W ----
        const uint32_t sA = smem_u32(A_t);
#pragma unroll
        for (int ks = 0; ks < 4; ks++) {
            const uint32_t kOffA = ks * 32;
            const uint32_t kOffB = (uint32_t)(k0 * 2 + ks * 32);
            uint32_t a4[4][4], b4[4][2];
#pragma unroll
            for (int mt = 0; mt < 4; mt++) {
                const uint32_t mOff = aRow + mt * 16 * (STRIDE * 2) + kOffA;
                LDSM_X4(a4[mt], sA + mOff);
            }
#pragma unroll
            for (int np = 0; np < 2; np++) {
                const uint32_t nOff = bRowW + np * 16 * (WT_STRIDE * 2) + kOffB;
                uint32_t q[4];
                LDSM_X4(q, sWu + nOff);
                b4[2*np][0] = q[0]; b4[2*np][1] = q[2];
                b4[2*np+1][0] = q[1]; b4[2*np+1][1] = q[3];
            }
#pragma unroll
            for (int mt = 0; mt < 4; mt++)
#pragma unroll
                for (int nt = 0; nt < 4; nt++)
                    mma16816(c[mt][nt], a4[mt], b4[nt]);
        }
    }

    // ---- scores: pair-reduce and write ----
    s1p += __shfl_xor_sync(0xFFFFFFFFu, s1p, 1);
    s2p += __shfl_xor_sync(0xFFFFFFFFu, s2p, 1);
    if (fq == 0) {
        const size_t r = row0 + row;
        g_s1[r] = s1p;
        g_s2[r] = s2p;
        g_E2[r] = expf(s2p);
        g_F2[r] = expf(0.2f * s2p);
    }

    // ---- WhT fp16 transposed store via smem (reuses A buffers) ----
    __syncthreads();
    __half* s_T = (__half*)wsm;   // [128 f][136]
    const int qrow = lane >> 2, qcol = 2 * (lane & 3);
#pragma unroll
    for (int mt = 0; mt < 4; mt++) {
        const int r0 = wm * 64 + mt * 16 + qrow;
        const int r1 = r0 + 8;
#pragma unroll
        for (int nt = 0; nt < 4; nt++) {
            const int c0 = wn * 32 + nt * 8 + qcol;
            s_T[c0 * 136 + r0]       = __float2half_rn(c[mt][nt][0]);
            s_T[(c0 + 1) * 136 + r0] = __float2half_rn(c[mt][nt][1]);
            s_T[c0 * 136 + r1]       = __float2half_rn(c[mt][nt][2]);
            s_T[(c0 + 1) * 136 + r1] = __float2half_rn(c[mt][nt][3]);
        }
    }
    __syncthreads();
    {
        const int f = t >> 1, part = t & 1;
        const uint4* src = (const uint4*)&s_T[f * 136 + part * 64];
        uint4* dst = (uint4*)&g_WhT[((size_t)(b * FOUT + f)) * NN + n0 + part * 64];
#pragma unroll
        for (int i = 0; i < 8; i++) dst[i] = src[i];
    }
}

// ---------------------------------------------------------------------------
// Kernel 2: fused attention, 512 threads (16 warps).
// A = row-normalized weights single fp16, B = Wh fp16 single, 1 product.
// ---------------------------------------------------------------------------
__global__ __launch_bounds__(512, 1) void k_attn(const int* __restrict__ adj,
                                                 float* __restrict__ out) {
    extern __shared__ char dsm[];
    __shared__ float s_Z[128][4];
    __shared__ float s_Zc[128];
    __shared__ float s_s2[NN], s_E2[NN], s_F2[NN];   // 24 KB
    __shared__ float s_red[16];

    const int t = threadIdx.x, w = t >> 5, lane = t & 31;
    const int b = blockIdx.y, i0 = blockIdx.x * 128;
    const size_t bn = (size_t)b * NN;

    // prologue: stage per-batch vectors, track max(s2)
    float mloc = -1e30f;
    {
        const float4* p2 = (const float4*)(g_s2 + bn);
        const float4* pe = (const float4*)(g_E2 + bn);
        const float4* pf = (const float4*)(g_F2 + bn);
        const float4 v2 = p2[t];
        ((float4*)s_s2)[t] = v2;
        ((float4*)s_E2)[t] = pe[t];
        ((float4*)s_F2)[t] = pf[t];
        mloc = fmaxf(fmaxf(v2.x, v2.y), fmaxf(v2.z, v2.w));
    }
#pragma unroll
    for (int o = 16; o; o >>= 1) mloc = fmaxf(mloc, __shfl_xor_sync(0xFFFFFFFFu, mloc, o));
    if (lane == 0) s_red[w] = mloc;
    __syncthreads();
    float M2 = s_red[0];
#pragma unroll
    for (int i = 1; i < 16; i++) M2 = fmaxf(M2, s_red[i]);

    // ---- c-phase mapping ----
    const int row = t >> 2;
    const int jq  = (t & 3) * 16;

    const float s1r = g_s1[bn + i0 + row];
    const float xm  = s1r + M2;
    const float m   = xm > 0.f ? xm : 0.2f * xm;
    const float E1n = expf(s1r - m);
    const float F1n = expf(0.2f * s1r - m);
    const int* __restrict__ adjrow = adj + (bn + i0 + row) * (size_t)NN;
    const __half* __restrict__ whp = g_WhT + ((size_t)b * FOUT + row) * NN;

    // ---- mma-phase addressing: warp tile 32(m) x 32(n) ----
    const int wm = w & 3, wn = w >> 2;
    const uint32_t aRow = (uint32_t)((wm * 32 + (lane & 15)) * (STRIDE * 2) + (lane >> 4) * 16);
    const uint32_t bRow = (uint32_t)((wn * 32 + (lane & 15)) * (STRIDE * 2) + (lane >> 4) * 16);

    float c[2][4][4];
#pragma unroll
    for (int mt = 0; mt < 2; mt++)
#pragma unroll
        for (int nt = 0; nt < 4; nt++)
#pragma unroll
            for (int r = 0; r < 4; r++) c[mt][nt][r] = 0.f;

    float Zreg = 0.f;

    // prefetch tile 0
    int4 radj[4];
    uint4 rwh[2];
    {
        const int4* am = (const int4*)(adjrow + jq);
#pragma unroll
        for (int q = 0; q < 4; q++) radj[q] = am[q];
        const uint4* sh = (const uint4*)(whp + jq);
        rwh[0] = sh[0]; rwh[1] = sh[1];
    }
    __syncthreads();

    for (int jt = 0; jt < NTILES; jt++) {
        const int s = jt & 1;
        char* A_t = dsm + s * ATT_STAGE;
        char* B_t = A_t + TILE_BYTES;
        const int jg0 = jt * JT + jq;

        // ---- store B (fp16 Wh) from prefetch ----
        {
            char* bp = B_t + row * (STRIDE * 2) + jq * 2;
            *(uint4*)(bp)      = rwh[0];
            *(uint4*)(bp + 16) = rwh[1];
        }
        // ---- build normalized c tile (16 weights), fp16 single ----
        {
            float c16[16];
#pragma unroll
            for (int q = 0; q < 4; q++) {
                const int4 mv = radj[q];
                const float4 s2 = *(const float4*)&s_s2[jg0 + 4 * q];
                const float4 e2 = *(const float4*)&s_E2[jg0 + 4 * q];
                const float4 f2 = *(const float4*)&s_F2[jg0 + 4 * q];
                c16[4*q+0] = (mv.x > 0) ? ((s1r + s2.x > 0.f) ? E1n * e2.x : F1n * f2.x) : 0.f;
                c16[4*q+1] = (mv.y > 0) ? ((s1r + s2.y > 0.f) ? E1n * e2.y : F1n * f2.y) : 0.f;
                c16[4*q+2] = (mv.z > 0) ? ((s1r + s2.z > 0.f) ? E1n * e2.z : F1n * f2.z) : 0.f;
                c16[4*q+3] = (mv.w > 0) ? ((s1r + s2.w > 0.f) ? E1n * e2.w : F1n * f2.w) : 0.f;
            }
#pragma unroll
            for (int k = 0; k < 16; k++) Zreg += c16[k];
            char* ap = A_t + row * (STRIDE * 2) + jq * 2;
            *(uint4*)(ap) = pack8h(
                __floats2half2_rn(c16[0], c16[1]),
                __floats2half2_rn(c16[2], c16[3]),
                __floats2half2_rn(c16[4], c16[5]),
                __floats2half2_rn(c16[6], c16[7]));
            *(uint4*)(ap + 16) = pack8h(
                __floats2half2_rn(c16[8],  c16[9]),
                __floats2half2_rn(c16[10], c16[11]),
                __floats2half2_rn(c16[12], c16[13]),
                __floats2half2_rn(c16[14], c16[15]));
        }

        __syncthreads();

        // ---- prefetch next tile under the mma phase ----
        if (jt + 1 < NTILES) {
            const int jg1 = (jt + 1) * JT + jq;
            const int4* am = (const int4*)(adjrow + jg1);
#pragma unroll
            for (int q = 0; q < 4; q++) radj[q] = am[q];
            const uint4* sh = (const uint4*)(whp + jg1);
            rwh[0] = sh[0]; rwh[1] = sh[1];
        }

        // ---- mma: 4 k-steps, warp tile 32x32 ----
        const uint32_t sA = smem_u32(A_t);
        const uint32_t sB = smem_u32(B_t);
#pragma unroll
        for (int ks = 0; ks < 4; ks++) {
            const uint32_t kOff = ks * 32;
            uint32_t a4[2][4], b4[4][2];
#pragma unroll
            for (int mt = 0; mt < 2; mt++) {
                const uint32_t mOff = aRow + mt * 16 * (STRIDE * 2) + kOff;
                LDSM_X4(a4[mt], sA + mOff);
            }
#pragma unroll
            for (int np = 0; np < 2; np++) {
                const uint32_t nOff = bRow + np * 16 * (STRIDE * 2) + kOff;
                uint32_t q[4];
                LDSM_X4(q, sB + nOff);
                b4[2*np][0] = q[0]; b4[2*np][1] = q[2];
                b4[2*np+1][0] = q[1]; b4[2*np+1][1] = q[3];
            }
#pragma unroll
            for (int mt = 0; mt < 2; mt++)
#pragma unroll
                for (int nt = 0; nt < 4; nt++)
                    mma16816(c[mt][nt], a4[mt], b4[nt]);
        }
    }

    // ---- combine Z, normalize + ELU + store ----
    s_Z[row][t & 3] = Zreg;
    __syncthreads();
    if (t < 128) s_Zc[t] = (s_Z[t][0] + s_Z[t][1]) + (s_Z[t][2] + s_Z[t][3]);
    __syncthreads();

    const int qrow = lane >> 2, qcol = 2 * (lane & 3);
#pragma unroll
    for (int mt = 0; mt < 2; mt++) {
        const int r0 = wm * 32 + mt * 16 + qrow;
        const int r1 = r0 + 8;
        const float zi0 = 1.0f / s_Zc[r0];
        const float zi1 = 1.0f / s_Zc[r1];
        float* op0 = out + (bn + i0 + r0) * (size_t)FOUT;
        float* op1 = out + (bn + i0 + r1) * (size_t)FOUT;
#pragma unroll
        for (int nt = 0; nt < 4; nt++) {
            const int col = wn * 32 + nt * 8 + qcol;
            float x0 = c[mt][nt][0] * zi0;
            float x1 = c[mt][nt][1] * zi0;
            float x2 = c[mt][nt][2] * zi1;
            float x3 = c[mt][nt][3] * zi1;
            float2 v0, v1;
            v0.x = x0 > 0.f ? x0 : expm1f(x0);
            v0.y = x1 > 0.f ? x1 : expm1f(x1);
            v1.x = x2 > 0.f ? x2 : expm1f(x2);
            v1.y = x3 > 0.f ? x3 : expm1f(x3);
            *(float2*)(op0 + col) = v0;
            *(float2*)(op1 + col) = v1;
        }
    }
}

// ---------------------------------------------------------------------------
extern "C" void kernel_launch(void* const* d_in, const int* in_sizes, int n_in,
                              void* d_out, int out_size) {
    const float* h = nullptr; const int* adj = nullptr;
    const float* W = nullptr; const float* a = nullptr;
    for (int i = 0; i < n_in; i++) {
        switch (in_sizes[i]) {
            case 4194304:  h   = (const float*)d_in[i]; break;
            case 33554432: adj = (const int*)d_in[i];   break;
            case 32768:    W   = (const float*)d_in[i]; break;
            case 256:      a   = (const float*)d_in[i]; break;
        }
    }
    float* out = (float*)d_out;

    static bool attr_set = false;
    if (!attr_set) {
        cudaFuncSetAttribute(k_wh, cudaFuncAttributeMaxDynamicSharedMemorySize,
                             WH_DSMEM);
        cudaFuncSetAttribute(k_attn, cudaFuncAttributeMaxDynamicSharedMemorySize,
                             ATT_DSMEM);
        attr_set = true;
    }

    k_wh<<<BN / 128, 256, WH_DSMEM>>>(h, W, a);
    k_attn<<<dim3(NN / 128, BB), 512, ATT_DSMEM>>>(adj, out);
}

// round 10
// speedup vs baseline: 4.4685x; 1.0666x over previous
#include <cuda_runtime.h>
#include <cuda_fp16.h>
#include <cstdint>
#include <math.h>

#define BB 8
#define NN 2048
#define FIN 256
#define FOUT 128
#define BN (BB*NN)   // 16384 rows total

#define JT 64                     // j-tile (K of the attn mma loop)
#define NTILES (NN/JT)            // 32
#define STRIDE 72                 // b16 elems per smem row (144 B) - conflict-free ldmatrix
#define TILE_BYTES (128*STRIDE*2)          // 18432 per tile
#define ATT_STAGE (2*TILE_BYTES)           // A, B = 36864
#define ATT_DSMEM (2*ATT_STAGE)            // 73728

#define WT_STRIDE 264                      // halfs per s_W row (528 B), LDSM conflict-free
#define WT_BYTES (FOUT*WT_STRIDE*2)        // 67584
#define WH_DSMEM (2*TILE_BYTES + WT_BYTES) // A0, A1, s_W = 104448

// Scratch (static device arrays; allocation is forbidden)
__device__ __half g_WhT[(size_t)BB * FOUT * NN];       // [b][f][n] Wh fp16 (single)
__device__ float  g_s1[BN], g_s2[BN];

// ---------------------------------------------------------------------------
__device__ __forceinline__ uint32_t smem_u32(const void* p) {
    uint32_t a;
    asm("{ .reg .u64 t; cvta.to.shared.u64 t, %1; cvt.u32.u64 %0, t; }"
        : "=r"(a) : "l"(p));
    return a;
}

#define LDSM_X4(r, addr) \
    asm volatile("ldmatrix.sync.aligned.m8n8.x4.shared.b16 {%0,%1,%2,%3}, [%4];" \
        : "=r"((r)[0]), "=r"((r)[1]), "=r"((r)[2]), "=r"((r)[3]) : "r"(addr))

#define CP_ASYNC16(dst, src) \
    asm volatile("cp.async.cg.shared.global [%0], [%1], 16;" :: "r"(dst), "l"(src) : "memory")
#define CP_COMMIT() asm volatile("cp.async.commit_group;" ::: "memory")
#define CP_WAIT0()  asm volatile("cp.async.wait_group 0;" ::: "memory")

__device__ __forceinline__ void mma16816(float* c, const uint32_t* a, const uint32_t* b) {
    asm volatile(
        "mma.sync.aligned.m16n8k16.row.col.f32.f16.f16.f32 "
        "{%0,%1,%2,%3}, {%4,%5,%6,%7}, {%8,%9}, {%0,%1,%2,%3};"
        : "+f"(c[0]), "+f"(c[1]), "+f"(c[2]), "+f"(c[3])
        : "r"(a[0]), "r"(a[1]), "r"(a[2]), "r"(a[3]), "r"(b[0]), "r"(b[1]));
}

__device__ __forceinline__ uint4 pack8h(__half2 a, __half2 b, __half2 c, __half2 d) {
    uint4 v;
    v.x = *(unsigned*)&a; v.y = *(unsigned*)&b;
    v.z = *(unsigned*)&c; v.w = *(unsigned*)&d;
    return v;
}

// ---------------------------------------------------------------------------
// Kernel 1: Wh = h @ W via HMMA, single fp16 product. Self-contained:
// prologue transposes W to fp16 smem + computes u1/u2 (fp32 exact).
// Fused exact scores (s1 = h.u1, s2 = h.u2) + writes; WhT fp16 out.
// ---------------------------------------------------------------------------
__global__ __launch_bounds__(256) void k_wh(const float* __restrict__ h,
                                            const float* __restrict__ W,
                                            const float* __restrict__ a) {
    extern __shared__ char wsm[];
    __shared__ float s_u1[FIN], s_u2[FIN];
    __shared__ float s_a[2 * FOUT];

    const int t = threadIdx.x, w = t >> 5, lane = t & 31;
    const int bx = blockIdx.x;
    const size_t row0 = (size_t)bx * 128;
    const int b  = bx >> 4;
    const int n0 = (bx & 15) * 128;

    char* A0  = wsm;                       // A double buffer
    char* s_Wc = wsm + 2 * TILE_BYTES;     // persistent W^T fp16
    __half* sW = (__half*)s_Wc;
    const uint32_t sWu = smem_u32(s_Wc);

    // ---- prologue: load a; transpose W -> fp16 smem; u1/u2 fp32 ----
    s_a[t] = a[t];
    __syncthreads();
    {
        const int kk = w * 32;     // warp's 32 k-rows
#pragma unroll 4
        for (int i = 0; i < 32; i++) {
            const int k = kk + i;
            float wv[4];
#pragma unroll
            for (int p = 0; p < 4; p++) wv[p] = W[k * FOUT + lane + p * 32];
            float u1p = 0.f, u2p = 0.f;
#pragma unroll
            for (int p = 0; p < 4; p++) {
                u1p += wv[p] * s_a[lane + p * 32];
                u2p += wv[p] * s_a[FOUT + lane + p * 32];
            }
#pragma unroll
            for (int p = 0; p < 4; p++)
                sW[(lane + p * 32) * WT_STRIDE + k] = __float2half_rn(wv[p]);
#pragma unroll
            for (int o = 16; o; o >>= 1) {
                u1p += __shfl_xor_sync(0xFFFFFFFFu, u1p, o);
                u2p += __shfl_xor_sync(0xFFFFFFFFu, u2p, o);
            }
            if (lane == 0) { s_u1[k] = u1p; s_u2[k] = u2p; }
        }
    }

    const int row = t >> 1, fq = t & 1;   // staging role: row 0..127, k half
    const float* __restrict__ hrow = h + (row0 + row) * (size_t)FIN + fq * 32;

    const int wm = w & 1, wn = w >> 1;
    const uint32_t aRow = (uint32_t)((wm * 64 + (lane & 15)) * (STRIDE * 2) + (lane >> 4) * 16);
    const uint32_t bRowW = (uint32_t)((wn * 32 + (lane & 15)) * (WT_STRIDE * 2) + (lane >> 4) * 16);

    float c[4][4][4];
#pragma unroll
    for (int mt = 0; mt < 4; mt++)
#pragma unroll
        for (int nt = 0; nt < 4; nt++)
#pragma unroll
            for (int r = 0; r < 4; r++) c[mt][nt][r] = 0.f;

    float s1p = 0.f, s2p = 0.f;

    // prefetch h chunk 0
    float4 hv[8];
    {
        const float4* hp = (const float4*)(hrow);
#pragma unroll
        for (int g = 0; g < 8; g++) hv[g] = hp[g];
    }
    __syncthreads();   // s_W, s_u ready

    for (int kc = 0; kc < 4; kc++) {
        const int k0 = kc * 64;
        const int s = kc & 1;
        char* A_t = A0 + s * TILE_BYTES;

        // ---- score partials + convert/store A (fp16) from prefetched h ----
        {
            const float4* u1v = (const float4*)&s_u1[k0 + fq * 32];
            const float4* u2v = (const float4*)&s_u2[k0 + fq * 32];
#pragma unroll
            for (int g = 0; g < 8; g++) {
                const float4 u1 = u1v[g], u2 = u2v[g];
                s1p += hv[g].x * u1.x + hv[g].y * u1.y + hv[g].z * u1.z + hv[g].w * u1.w;
                s2p += hv[g].x * u2.x + hv[g].y * u2.y + hv[g].z * u2.z + hv[g].w * u2.w;
            }
            char* ap = A_t + row * (STRIDE * 2) + fq * 64;
#pragma unroll
            for (int g = 0; g < 4; g++) {
                const float4 v0 = hv[2 * g], v1 = hv[2 * g + 1];
                *(uint4*)(ap + g * 16) = pack8h(__floats2half2_rn(v0.x, v0.y),
                                                __floats2half2_rn(v0.z, v0.w),
                                                __floats2half2_rn(v1.x, v1.y),
                                                __floats2half2_rn(v1.z, v1.w));
            }
        }
        __syncthreads();

        // ---- prefetch next h chunk under the mma ----
        if (kc < 3) {
            const float4* hp = (const float4*)(hrow + (kc + 1) * 64);
#pragma unroll
            for (int g = 0; g < 8; g++) hv[g] = hp[g];
        }

        // ---- mma: 4 k-steps of 16, 1 product; B from persistent s_W ----
        const uint32_t sA = smem_u32(A_t);
#pragma unroll
        for (int ks = 0; ks < 4; ks++) {
            const uint32_t kOffA = ks * 32;
            const uint32_t kOffB = (uint32_t)(k0 * 2 + ks * 32);
            uint32_t a4[4][4], b4[4][2];
#pragma unroll
            for (int mt = 0; mt < 4; mt++) {
                const uint32_t mOff = aRow + mt * 16 * (STRIDE * 2) + kOffA;
                LDSM_X4(a4[mt], sA + mOff);
            }
#pragma unroll
            for (int np = 0; np < 2; np++) {
                const uint32_t nOff = bRowW + np * 16 * (WT_STRIDE * 2) + kOffB;
                uint32_t q[4];
                LDSM_X4(q, sWu + nOff);
                b4[2*np][0] = q[0]; b4[2*np][1] = q[2];
                b4[2*np+1][0] = q[1]; b4[2*np+1][1] = q[3];
            }
#pragma unroll
            for (int mt = 0; mt < 4; mt++)
#pragma unroll
                for (int nt = 0; nt < 4; nt++)
                    mma16816(c[mt][nt], a4[mt], b4[nt]);
        }
    }

    // ---- scores: pair-reduce and write ----
    s1p += __shfl_xor_sync(0xFFFFFFFFu, s1p, 1);
    s2p += __shfl_xor_sync(0xFFFFFFFFu, s2p, 1);
    if (fq == 0) {
        const size_t r = row0 + row;
        g_s1[r] = s1p;
        g_s2[r] = s2p;
    }

    // ---- WhT fp16 transposed store via smem (reuses A buffers) ----
    __syncthreads();
    __half* s_T = (__half*)wsm;   // [128 f][136]
    const int qrow = lane >> 2, qcol = 2 * (lane & 3);
#pragma unroll
    for (int mt = 0; mt < 4; mt++) {
        const int r0 = wm * 64 + mt * 16 + qrow;
        const int r1 = r0 + 8;
#pragma unroll
        for (int nt = 0; nt < 4; nt++) {
            const int c0 = wn * 32 + nt * 8 + qcol;
            s_T[c0 * 136 + r0]       = __float2half_rn(c[mt][nt][0]);
            s_T[(c0 + 1) * 136 + r0] = __float2half_rn(c[mt][nt][1]);
            s_T[c0 * 136 + r1]       = __float2half_rn(c[mt][nt][2]);
            s_T[(c0 + 1) * 136 + r1] = __float2half_rn(c[mt][nt][3]);
        }
    }
    __syncthreads();
    {
        const int f = t >> 1, part = t & 1;
        const uint4* src = (const uint4*)&s_T[f * 136 + part * 64];
        uint4* dst = (uint4*)&g_WhT[((size_t)(b * FOUT + f)) * NN + n0 + part * 64];
#pragma unroll
        for (int i = 0; i < 8; i++) dst[i] = src[i];
    }
}

// ---------------------------------------------------------------------------
// Kernel 2: fused attention, 512 threads (16 warps).
// Weights via max identity: exp(leaky(x)) = max(exp(x), exp(0.2x)),
// j-side factors prepacked as half2 in smem; B tile via cp.async.
// ---------------------------------------------------------------------------
__global__ __launch_bounds__(512, 1) void k_attn(const int* __restrict__ adj,
                                                 float* __restrict__ out) {
    extern __shared__ char dsm[];
    __shared__ float s_Z[128][4];
    __shared__ float s_Zc[128];
    __shared__ __half2 s_EF[NN];          // 8 KB: (exp(s2-M2), exp(0.2(s2-M2)))
    __shared__ float s_red[16];

    const int t = threadIdx.x, w = t >> 5, lane = t & 31;
    const int b = blockIdx.y, i0 = blockIdx.x * 128;
    const size_t bn = (size_t)b * NN;
    const uint32_t dsm_u = smem_u32(dsm);

    // ---- prologue: read s2, reduce M2, build s_EF ----
    const float4 v2 = ((const float4*)(g_s2 + bn))[t];
    float mloc = fmaxf(fmaxf(v2.x, v2.y), fmaxf(v2.z, v2.w));
#pragma unroll
    for (int o = 16; o; o >>= 1) mloc = fmaxf(mloc, __shfl_xor_sync(0xFFFFFFFFu, mloc, o));
    if (lane == 0) s_red[w] = mloc;
    __syncthreads();
    float M2 = s_red[0];
#pragma unroll
    for (int i = 1; i < 16; i++) M2 = fmaxf(M2, s_red[i]);

    s_EF[4 * t + 0] = __floats2half2_rn(expf(v2.x - M2), expf(0.2f * (v2.x - M2)));
    s_EF[4 * t + 1] = __floats2half2_rn(expf(v2.y - M2), expf(0.2f * (v2.y - M2)));
    s_EF[4 * t + 2] = __floats2half2_rn(expf(v2.z - M2), expf(0.2f * (v2.z - M2)));
    s_EF[4 * t + 3] = __floats2half2_rn(expf(v2.w - M2), expf(0.2f * (v2.w - M2)));

    // ---- c-phase mapping ----
    const int row = t >> 2;
    const int jq  = (t & 3) * 16;

    const float s1r = g_s1[bn + i0 + row];
    const float xm  = s1r + M2;
    const float m   = xm > 0.f ? xm : 0.2f * xm;
    const __half2 E1F1 = __floats2half2_rn(expf(xm - m), expf(0.2f * xm - m));
    const int* __restrict__ adjrow = adj + (bn + i0 + row) * (size_t)NN;
    const __half* __restrict__ whp = g_WhT + ((size_t)b * FOUT + row) * NN;

    // ---- mma-phase addressing: warp tile 32(m) x 32(n) ----
    const int wm = w & 3, wn = w >> 2;
    const uint32_t aRow = (uint32_t)((wm * 32 + (lane & 15)) * (STRIDE * 2) + (lane >> 4) * 16);
    const uint32_t bRow = (uint32_t)((wn * 32 + (lane & 15)) * (STRIDE * 2) + (lane >> 4) * 16);

    float c[2][4][4];
#pragma unroll
    for (int mt = 0; mt < 2; mt++)
#pragma unroll
        for (int nt = 0; nt < 4; nt++)
#pragma unroll
            for (int r = 0; r < 4; r++) c[mt][nt][r] = 0.f;

    float Zreg = 0.f;

    // B tile 0 via cp.async; adj tile 0 into regs
    {
        const uint32_t bd = dsm_u + TILE_BYTES + row * (STRIDE * 2) + jq * 2;
        CP_ASYNC16(bd,      whp + jq);
        CP_ASYNC16(bd + 16, whp + jq + 8);
        CP_COMMIT();
    }
    int4 radj[4];
    {
        const int4* am = (const int4*)(adjrow + jq);
#pragma unroll
        for (int q = 0; q < 4; q++) radj[q] = am[q];
    }
    __syncthreads();   // s_EF ready

    for (int jt = 0; jt < NTILES; jt++) {
        const int s = jt & 1;
        char* A_t = dsm + s * ATT_STAGE;
        const int jg0 = jt * JT + jq;

        // ---- build normalized c tile (16 weights), fp16, max identity ----
        {
            __half ch[16];
#pragma unroll
            for (int q = 0; q < 4; q++) {
                const int4 mv = radj[q];
                const uint4 efw = *(const uint4*)&s_EF[jg0 + 4 * q];
                const unsigned efa[4] = { efw.x, efw.y, efw.z, efw.w };
                const int mk[4] = { mv.x, mv.y, mv.z, mv.w };
#pragma unroll
                for (int j = 0; j < 4; j++) {
                    __half2 ef = *(const __half2*)&efa[j];
                    __half2 pr = __hmul2(E1F1, ef);
                    __half cj = __hmax(__low2half(pr), __high2half(pr));
                    unsigned short cb = __half_as_ushort(cj);
                    cb = (mk[j] > 0) ? cb : (unsigned short)0;
                    cj = __ushort_as_half(cb);
                    Zreg += __half2float(cj);
                    ch[4 * q + j] = cj;
                }
            }
            char* ap = A_t + row * (STRIDE * 2) + jq * 2;
            *(uint4*)(ap) = pack8h(__halves2half2(ch[0], ch[1]),
                                   __halves2half2(ch[2], ch[3]),
                                   __halves2half2(ch[4], ch[5]),
                                   __halves2half2(ch[6], ch[7]));
            *(uint4*)(ap + 16) = pack8h(__halves2half2(ch[8],  ch[9]),
                                        __halves2half2(ch[10], ch[11]),
                                        __halves2half2(ch[12], ch[13]),
                                        __halves2half2(ch[14], ch[15]));
        }

        CP_WAIT0();        // this tile's B arrived (this thread's copies)
        __syncthreads();   // everyone's B + A visible; prev mma done

        // ---- issue next B (cp.async into other stage) + prefetch adj ----
        if (jt + 1 < NTILES) {
            const int jg1 = (jt + 1) * JT + jq;
            const uint32_t bd = dsm_u + (s ^ 1) * ATT_STAGE + TILE_BYTES
                              + row * (STRIDE * 2) + jq * 2;
            CP_ASYNC16(bd,      whp + jg1);
            CP_ASYNC16(bd + 16, whp + jg1 + 8);
            const int4* am = (const int4*)(adjrow + jg1);
#pragma unroll
            for (int q = 0; q < 4; q++) radj[q] = am[q];
        }
        CP_COMMIT();

        // ---- mma: 4 k-steps, warp tile 32x32 ----
        const uint32_t sA = dsm_u + s * ATT_STAGE;
        const uint32_t sB = sA + TILE_BYTES;
#pragma unroll
        for (int ks = 0; ks < 4; ks++) {
            const uint32_t kOff = ks * 32;
            uint32_t a4[2][4], b4[4][2];
#pragma unroll
            for (int mt = 0; mt < 2; mt++) {
                const uint32_t mOff = aRow + mt * 16 * (STRIDE * 2) + kOff;
                LDSM_X4(a4[mt], sA + mOff);
            }
#pragma unroll
            for (int np = 0; np < 2; np++) {
                const uint32_t nOff = bRow + np * 16 * (STRIDE * 2) + kOff;
                uint32_t q[4];
                LDSM_X4(q, sB + nOff);
                b4[2*np][0] = q[0]; b4[2*np][1] = q[2];
                b4[2*np+1][0] = q[1]; b4[2*np+1][1] = q[3];
            }
#pragma unroll
            for (int mt = 0; mt < 2; mt++)
#pragma unroll
                for (int nt = 0; nt < 4; nt++)
                    mma16816(c[mt][nt], a4[mt], b4[nt]);
        }
    }

    // ---- combine Z, normalize + ELU + store ----
    s_Z[row][t & 3] = Zreg;
    __syncthreads();
    if (t < 128) s_Zc[t] = (s_Z[t][0] + s_Z[t][1]) + (s_Z[t][2] + s_Z[t][3]);
    __syncthreads();

    const int qrow = lane >> 2, qcol = 2 * (lane & 3);
#pragma unroll
    for (int mt = 0; mt < 2; mt++) {
        const int r0 = wm * 32 + mt * 16 + qrow;
        const int r1 = r0 + 8;
        const float zi0 = 1.0f / s_Zc[r0];
        const float zi1 = 1.0f / s_Zc[r1];
        float* op0 = out + (bn + i0 + r0) * (size_t)FOUT;
        float* op1 = out + (bn + i0 + r1) * (size_t)FOUT;
#pragma unroll
        for (int nt = 0; nt < 4; nt++) {
            const int col = wn * 32 + nt * 8 + qcol;
            float x0 = c[mt][nt][0] * zi0;
            float x1 = c[mt][nt][1] * zi0;
            float x2 = c[mt][nt][2] * zi1;
            float x3 = c[mt][nt][3] * zi1;
            float2 v0, v1;
            v0.x = x0 > 0.f ? x0 : expm1f(x0);
            v0.y = x1 > 0.f ? x1 : expm1f(x1);
            v1.x = x2 > 0.f ? x2 : expm1f(x2);
            v1.y = x3 > 0.f ? x3 : expm1f(x3);
            *(float2*)(op0 + col) = v0;
            *(float2*)(op1 + col) = v1;
        }
    }
}

// ---------------------------------------------------------------------------
extern "C" void kernel_launch(void* const* d_in, const int* in_sizes, int n_in,
                              void* d_out, int out_size) {
    const float* h = nullptr; const int* adj = nullptr;
    const float* W = nullptr; const float* a = nullptr;
    for (int i = 0; i < n_in; i++) {
        switch (in_sizes[i]) {
            case 4194304:  h   = (const float*)d_in[i]; break;
            case 33554432: adj = (const int*)d_in[i];   break;
            case 32768:    W   = (const float*)d_in[i]; break;
            case 256:      a   = (const float*)d_in[i]; break;
        }
    }
    float* out = (float*)d_out;

    static bool attr_set = false;
    if (!attr_set) {
        cudaFuncSetAttribute(k_wh, cudaFuncAttributeMaxDynamicSharedMemorySize,
                             WH_DSMEM);
        cudaFuncSetAttribute(k_attn, cudaFuncAttributeMaxDynamicSharedMemorySize,
                             ATT_DSMEM);
        attr_set = true;
    }

    k_wh<<<BN / 128, 256, WH_DSMEM>>>(h, W, a);
    k_attn<<<dim3(NN / 128, BB), 512, ATT_DSMEM>>>(adj, out);
}

// round 11
// speedup vs baseline: 4.6247x; 1.0350x over previous
#include <cuda_runtime.h>
#include <cuda_fp16.h>
#include <cstdint>
#include <math.h>

#define BB 8
#define NN 2048
#define FIN 256
#define FOUT 128
#define BN (BB*NN)   // 16384 rows total

#define JT 64                     // j-tile (K of the attn mma loop)
#define NTILES (NN/JT)            // 32
#define STRIDE 72                 // b16 elems per smem row (144 B) - conflict-free ldmatrix
#define TILE_BYTES (128*STRIDE*2)          // 18432 (128-row tile)

#define ATT_A_BYTES (64*STRIDE*2)          // 9216  (64-row A tile)
#define ATT_B_BYTES (128*STRIDE*2)         // 18432 (128-row B tile)
#define ATT_STAGE (ATT_A_BYTES + ATT_B_BYTES)   // 27648
#define ATT_DSMEM (2*ATT_STAGE)            // 55296

#define WT_STRIDE 264                      // halfs per s_W row (528 B), LDSM conflict-free
#define WT_BYTES (FOUT*WT_STRIDE*2)        // 67584
#define WH_DSMEM (2*TILE_BYTES + WT_BYTES) // A0, A1, s_W = 104448

// Scratch (static device arrays; allocation is forbidden)
__device__ __half g_WhT[(size_t)BB * FOUT * NN];       // [b][f][n] Wh fp16 (single)
__device__ float  g_s1[BN], g_s2[BN];

// ---------------------------------------------------------------------------
__device__ __forceinline__ uint32_t smem_u32(const void* p) {
    uint32_t a;
    asm("{ .reg .u64 t; cvta.to.shared.u64 t, %1; cvt.u32.u64 %0, t; }"
        : "=r"(a) : "l"(p));
    return a;
}

#define LDSM_X4(r, addr) \
    asm volatile("ldmatrix.sync.aligned.m8n8.x4.shared.b16 {%0,%1,%2,%3}, [%4];" \
        : "=r"((r)[0]), "=r"((r)[1]), "=r"((r)[2]), "=r"((r)[3]) : "r"(addr))

#define CP_ASYNC16(dst, src) \
    asm volatile("cp.async.cg.shared.global [%0], [%1], 16;" :: "r"(dst), "l"(src) : "memory")
#define CP_COMMIT() asm volatile("cp.async.commit_group;" ::: "memory")
#define CP_WAIT0()  asm volatile("cp.async.wait_group 0;" ::: "memory")

__device__ __forceinline__ void mma16816(float* c, const uint32_t* a, const uint32_t* b) {
    asm volatile(
        "mma.sync.aligned.m16n8k16.row.col.f32.f16.f16.f32 "
        "{%0,%1,%2,%3}, {%4,%5,%6,%7}, {%8,%9}, {%0,%1,%2,%3};"
        : "+f"(c[0]), "+f"(c[1]), "+f"(c[2]), "+f"(c[3])
        : "r"(a[0]), "r"(a[1]), "r"(a[2]), "r"(a[3]), "r"(b[0]), "r"(b[1]));
}

__device__ __forceinline__ uint4 pack8h(__half2 a, __half2 b, __half2 c, __half2 d) {
    uint4 v;
    v.x = *(unsigned*)&a; v.y = *(unsigned*)&b;
    v.z = *(unsigned*)&c; v.w = *(unsigned*)&d;
    return v;
}

// ---------------------------------------------------------------------------
// Kernel 1: Wh = h @ W via HMMA, single fp16 product. Self-contained:
// prologue transposes W to fp16 smem + computes u1/u2 (fp32 exact).
// Fused exact scores (s1 = h.u1, s2 = h.u2) + writes; WhT fp16 out.
// ---------------------------------------------------------------------------
__global__ __launch_bounds__(256) void k_wh(const float* __restrict__ h,
                                            const float* __restrict__ W,
                                            const float* __restrict__ a) {
    extern __shared__ char wsm[];
    __shared__ float s_u1[FIN], s_u2[FIN];
    __shared__ float s_a[2 * FOUT];

    const int t = threadIdx.x, w = t >> 5, lane = t & 31;
    const int bx = blockIdx.x;
    const size_t row0 = (size_t)bx * 128;
    const int b  = bx >> 4;
    const int n0 = (bx & 15) * 128;

    char* A0  = wsm;                       // A double buffer
    char* s_Wc = wsm + 2 * TILE_BYTES;     // persistent W^T fp16
    __half* sW = (__half*)s_Wc;
    const uint32_t sWu = smem_u32(s_Wc);

    // ---- prologue: load a; transpose W -> fp16 smem; u1/u2 fp32 ----
    s_a[t] = a[t];
    __syncthreads();
    {
        const int kk = w * 32;     // warp's 32 k-rows
#pragma unroll 4
        for (int i = 0; i < 32; i++) {
            const int k = kk + i;
            float wv[4];
#pragma unroll
            for (int p = 0; p < 4; p++) wv[p] = W[k * FOUT + lane + p * 32];
            float u1p = 0.f, u2p = 0.f;
#pragma unroll
            for (int p = 0; p < 4; p++) {
                u1p += wv[p] * s_a[lane + p * 32];
                u2p += wv[p] * s_a[FOUT + lane + p * 32];
            }
#pragma unroll
            for (int p = 0; p < 4; p++)
                sW[(lane + p * 32) * WT_STRIDE + k] = __float2half_rn(wv[p]);
#pragma unroll
            for (int o = 16; o; o >>= 1) {
                u1p += __shfl_xor_sync(0xFFFFFFFFu, u1p, o);
                u2p += __shfl_xor_sync(0xFFFFFFFFu, u2p, o);
            }
            if (lane == 0) { s_u1[k] = u1p; s_u2[k] = u2p; }
        }
    }

    const int row = t >> 1, fq = t & 1;   // staging role: row 0..127, k half
    const float* __restrict__ hrow = h + (row0 + row) * (size_t)FIN + fq * 32;

    const int wm = w & 1, wn = w >> 1;
    const uint32_t aRow = (uint32_t)((wm * 64 + (lane & 15)) * (STRIDE * 2) + (lane >> 4) * 16);
    const uint32_t bRowW = (uint32_t)((wn * 32 + (lane & 15)) * (WT_STRIDE * 2) + (lane >> 4) * 16);

    float c[4][4][4];
#pragma unroll
    for (int mt = 0; mt < 4; mt++)
#pragma unroll
        for (int nt = 0; nt < 4; nt++)
#pragma unroll
            for (int r = 0; r < 4; r++) c[mt][nt][r] = 0.f;

    float s1p = 0.f, s2p = 0.f;

    // prefetch h chunk 0
    float4 hv[8];
    {
        const float4* hp = (const float4*)(hrow);
#pragma unroll
        for (int g = 0; g < 8; g++) hv[g] = hp[g];
    }
    __syncthreads();   // s_W, s_u ready

    for (int kc = 0; kc < 4; kc++) {
        const int k0 = kc * 64;
        const int s = kc & 1;
        char* A_t = A0 + s * TILE_BYTES;

        // ---- score partials + convert/store A (fp16) from prefetched h ----
        {
            const float4* u1v = (const float4*)&s_u1[k0 + fq * 32];
            const float4* u2v = (const float4*)&s_u2[k0 + fq * 32];
#pragma unroll
            for (int g = 0; g < 8; g++) {
                const float4 u1 = u1v[g], u2 = u2v[g];
                s1p += hv[g].x * u1.x + hv[g].y * u1.y + hv[g].z * u1.z + hv[g].w * u1.w;
                s2p += hv[g].x * u2.x + hv[g].y * u2.y + hv[g].z * u2.z + hv[g].w * u2.w;
            }
            char* ap = A_t + row * (STRIDE * 2) + fq * 64;
#pragma unroll
            for (int g = 0; g < 4; g++) {
                const float4 v0 = hv[2 * g], v1 = hv[2 * g + 1];
                *(uint4*)(ap + g * 16) = pack8h(__floats2half2_rn(v0.x, v0.y),
                                                __floats2half2_rn(v0.z, v0.w),
                                                __floats2half2_rn(v1.x, v1.y),
                                                __floats2half2_rn(v1.z, v1.w));
            }
        }
        __syncthreads();

        // ---- prefetch next h chunk under the mma ----
        if (kc < 3) {
            const float4* hp = (const float4*)(hrow + (kc + 1) * 64);
#pragma unroll
            for (int g = 0; g < 8; g++) hv[g] = hp[g];
        }

        // ---- mma: 4 k-steps of 16, 1 product; B from persistent s_W ----
        const uint32_t sA = smem_u32(A_t);
#pragma unroll
        for (int ks = 0; ks < 4; ks++) {
            const uint32_t kOffA = ks * 32;
            const uint32_t kOffB = (uint32_t)(k0 * 2 + ks * 32);
            uint32_t a4[4][4], b4[4][2];
#pragma unroll
            for (int mt = 0; mt < 4; mt++) {
                const uint32_t mOff = aRow + mt * 16 * (STRIDE * 2) + kOffA;
                LDSM_X4(a4[mt], sA + mOff);
            }
#pragma unroll
            for (int np = 0; np < 2; np++) {
                const uint32_t nOff = bRowW + np * 16 * (WT_STRIDE * 2) + kOffB;
                uint32_t q[4];
                LDSM_X4(q, sWu + nOff);
                b4[2*np][0] = q[0]; b4[2*np][1] = q[2];
                b4[2*np+1][0] = q[1]; b4[2*np+1][1] = q[3];
            }
#pragma unroll
            for (int mt = 0; mt < 4; mt++)
#pragma unroll
                for (int nt = 0; nt < 4; nt++)
                    mma16816(c[mt][nt], a4[mt], b4[nt]);
        }
    }

    // ---- scores: pair-reduce and write ----
    s1p += __shfl_xor_sync(0xFFFFFFFFu, s1p, 1);
    s2p += __shfl_xor_sync(0xFFFFFFFFu, s2p, 1);
    if (fq == 0) {
        const size_t r = row0 + row;
        g_s1[r] = s1p;
        g_s2[r] = s2p;
    }

    // ---- WhT fp16 transposed store via smem (reuses A buffers) ----
    __syncthreads();
    __half* s_T = (__half*)wsm;   // [128 f][136]
    const int qrow = lane >> 2, qcol = 2 * (lane & 3);
#pragma unroll
    for (int mt = 0; mt < 4; mt++) {
        const int r0 = wm * 64 + mt * 16 + qrow;
        const int r1 = r0 + 8;
#pragma unroll
        for (int nt = 0; nt < 4; nt++) {
            const int c0 = wn * 32 + nt * 8 + qcol;
            s_T[c0 * 136 + r0]       = __float2half_rn(c[mt][nt][0]);
            s_T[(c0 + 1) * 136 + r0] = __float2half_rn(c[mt][nt][1]);
            s_T[c0 * 136 + r1]       = __float2half_rn(c[mt][nt][2]);
            s_T[(c0 + 1) * 136 + r1] = __float2half_rn(c[mt][nt][3]);
        }
    }
    __syncthreads();
    {
        const int f = t >> 1, part = t & 1;
        const uint4* src = (const uint4*)&s_T[f * 136 + part * 64];
        uint4* dst = (uint4*)&g_WhT[((size_t)(b * FOUT + f)) * NN + n0 + part * 64];
#pragma unroll
        for (int i = 0; i < 8; i++) dst[i] = src[i];
    }
}

// ---------------------------------------------------------------------------
// Kernel 2: fused attention, 256 threads (8 warps), CTA = 64 i x 128 f.
// 2 CTAs/SM for phase overlap. Max-identity weights; B via cp.async.
// c-phase: row = t>>2 (0..63), jq = (t&3)*16.
// B copy: fB = t>>1 (0..127), partB = t&1 (32 halfs each).
// mma: wm = w&1 (32-row), wn = w>>1 (32-col); warp tile 32x32.
// ---------------------------------------------------------------------------
__global__ __launch_bounds__(256, 2) void k_attn(const int* __restrict__ adj,
                                                 float* __restrict__ out) {
    extern __shared__ char dsm[];
    __shared__ float s_Z[64][4];
    __shared__ float s_Zc[64];
    __shared__ __half2 s_EF[NN];          // 8 KB
    __shared__ float s_red[8];

    const int t = threadIdx.x, w = t >> 5, lane = t & 31;
    const int b = blockIdx.y, i0 = blockIdx.x * 64;
    const size_t bn = (size_t)b * NN;
    const uint32_t dsm_u = smem_u32(dsm);

    // ---- prologue: read s2 (8 per thread), reduce M2, build s_EF ----
    const float4 v2a = ((const float4*)(g_s2 + bn))[2 * t];
    const float4 v2b = ((const float4*)(g_s2 + bn))[2 * t + 1];
    float mloc = fmaxf(fmaxf(fmaxf(v2a.x, v2a.y), fmaxf(v2a.z, v2a.w)),
                       fmaxf(fmaxf(v2b.x, v2b.y), fmaxf(v2b.z, v2b.w)));
#pragma unroll
    for (int o = 16; o; o >>= 1) mloc = fmaxf(mloc, __shfl_xor_sync(0xFFFFFFFFu, mloc, o));
    if (lane == 0) s_red[w] = mloc;
    __syncthreads();
    float M2 = s_red[0];
#pragma unroll
    for (int i = 1; i < 8; i++) M2 = fmaxf(M2, s_red[i]);

    {
        const float sv[8] = { v2a.x, v2a.y, v2a.z, v2a.w, v2b.x, v2b.y, v2b.z, v2b.w };
#pragma unroll
        for (int j = 0; j < 8; j++)
            s_EF[8 * t + j] = __floats2half2_rn(expf(sv[j] - M2),
                                                expf(0.2f * (sv[j] - M2)));
    }

    // ---- c-phase mapping ----
    const int row = t >> 2;           // 0..63
    const int jq  = (t & 3) * 16;

    const float s1r = g_s1[bn + i0 + row];
    const float xm  = s1r + M2;
    const float m   = xm > 0.f ? xm : 0.2f * xm;
    const __half2 E1F1 = __floats2half2_rn(expf(xm - m), expf(0.2f * xm - m));
    const int* __restrict__ adjrow = adj + (bn + i0 + row) * (size_t)NN;

    // ---- B-copy mapping ----
    const int fB = t >> 1, partB = t & 1;
    const __half* __restrict__ whpB = g_WhT + ((size_t)b * FOUT + fB) * NN + partB * 32;
    const uint32_t bDst = (uint32_t)(ATT_A_BYTES + fB * (STRIDE * 2) + partB * 64);

    // ---- mma-phase addressing: warp tile 32(m) x 32(n) ----
    const int wm = w & 1, wn = w >> 1;
    const uint32_t aRow = (uint32_t)((wm * 32 + (lane & 15)) * (STRIDE * 2) + (lane >> 4) * 16);
    const uint32_t bRow = (uint32_t)(ATT_A_BYTES
                         + (wn * 32 + (lane & 15)) * (STRIDE * 2) + (lane >> 4) * 16);

    float c[2][4][4];
#pragma unroll
    for (int mt = 0; mt < 2; mt++)
#pragma unroll
        for (int nt = 0; nt < 4; nt++)
#pragma unroll
            for (int r = 0; r < 4; r++) c[mt][nt][r] = 0.f;

    float Zreg = 0.f;

    // B tile 0 via cp.async; adj tile 0 into regs
    {
        const uint32_t bd = dsm_u + bDst;
        CP_ASYNC16(bd,      whpB);
        CP_ASYNC16(bd + 16, whpB + 8);
        CP_ASYNC16(bd + 32, whpB + 16);
        CP_ASYNC16(bd + 48, whpB + 24);
        CP_COMMIT();
    }
    int4 radj[4];
    {
        const int4* am = (const int4*)(adjrow + jq);
#pragma unroll
        for (int q = 0; q < 4; q++) radj[q] = am[q];
    }
    __syncthreads();   // s_EF ready

    for (int jt = 0; jt < NTILES; jt++) {
        const int s = jt & 1;
        char* A_t = dsm + s * ATT_STAGE;
        const int jg0 = jt * JT + jq;

        // ---- build c tile (16 weights), fp16, max identity ----
        {
            __half ch[16];
#pragma unroll
            for (int q = 0; q < 4; q++) {
                const int4 mv = radj[q];
                const uint4 efw = *(const uint4*)&s_EF[jg0 + 4 * q];
                const unsigned efa[4] = { efw.x, efw.y, efw.z, efw.w };
                const int mk[4] = { mv.x, mv.y, mv.z, mv.w };
#pragma unroll
                for (int j = 0; j < 4; j++) {
                    __half2 ef = *(const __half2*)&efa[j];
                    __half2 pr = __hmul2(E1F1, ef);
                    __half cj = __hmax(__low2half(pr), __high2half(pr));
                    unsigned short cb = __half_as_ushort(cj);
                    cb = (mk[j] > 0) ? cb : (unsigned short)0;
                    cj = __ushort_as_half(cb);
                    Zreg += __half2float(cj);
                    ch[4 * q + j] = cj;
                }
            }
            char* ap = A_t + row * (STRIDE * 2) + jq * 2;
            *(uint4*)(ap) = pack8h(__halves2half2(ch[0], ch[1]),
                                   __halves2half2(ch[2], ch[3]),
                                   __halves2half2(ch[4], ch[5]),
                                   __halves2half2(ch[6], ch[7]));
            *(uint4*)(ap + 16) = pack8h(__halves2half2(ch[8],  ch[9]),
                                        __halves2half2(ch[10], ch[11]),
                                        __halves2half2(ch[12], ch[13]),
                                        __halves2half2(ch[14], ch[15]));
        }

        CP_WAIT0();        // this tile's B arrived (this thread's copies)
        __syncthreads();   // everyone's B + A visible; prev mma done

        // ---- issue next B (cp.async into other stage) + prefetch adj ----
        if (jt + 1 < NTILES) {
            const int jg1B = (jt + 1) * JT;
            const uint32_t bd = dsm_u + (s ^ 1) * ATT_STAGE + bDst;
            const __half* src = whpB + jg1B;
            CP_ASYNC16(bd,      src);
            CP_ASYNC16(bd + 16, src + 8);
            CP_ASYNC16(bd + 32, src + 16);
            CP_ASYNC16(bd + 48, src + 24);
            const int4* am = (const int4*)(adjrow + (jt + 1) * JT + jq);
#pragma unroll
            for (int q = 0; q < 4; q++) radj[q] = am[q];
        }
        CP_COMMIT();

        // ---- mma: 4 k-steps, warp tile 32x32 ----
        const uint32_t sA = dsm_u + s * ATT_STAGE;
#pragma unroll
        for (int ks = 0; ks < 4; ks++) {
            const uint32_t kOff = ks * 32;
            uint32_t a4[2][4], b4[4][2];
#pragma unroll
            for (int mt = 0; mt < 2; mt++) {
                const uint32_t mOff = aRow + mt * 16 * (STRIDE * 2) + kOff;
                LDSM_X4(a4[mt], sA + mOff);
            }
#pragma unroll
            for (int np = 0; np < 2; np++) {
                const uint32_t nOff = bRow + np * 16 * (STRIDE * 2) + kOff;
                uint32_t q[4];
                LDSM_X4(q, sA + nOff);
                b4[2*np][0] = q[0]; b4[2*np][1] = q[2];
                b4[2*np+1][0] = q[1]; b4[2*np+1][1] = q[3];
            }
#pragma unroll
            for (int mt = 0; mt < 2; mt++)
#pragma unroll
                for (int nt = 0; nt < 4; nt++)
                    mma16816(c[mt][nt], a4[mt], b4[nt]);
        }
    }

    // ---- combine Z, normalize + ELU + store ----
    s_Z[row][t & 3] = Zreg;
    __syncthreads();
    if (t < 64) s_Zc[t] = (s_Z[t][0] + s_Z[t][1]) + (s_Z[t][2] + s_Z[t][3]);
    __syncthreads();

    const int qrow = lane >> 2, qcol = 2 * (lane & 3);
#pragma unroll
    for (int mt = 0; mt < 2; mt++) {
        const int r0 = wm * 32 + mt * 16 + qrow;
        const int r1 = r0 + 8;
        const float zi0 = 1.0f / s_Zc[r0];
        const float zi1 = 1.0f / s_Zc[r1];
        float* op0 = out + (bn + i0 + r0) * (size_t)FOUT;
        float* op1 = out + (bn + i0 + r1) * (size_t)FOUT;
#pragma unroll
        for (int nt = 0; nt < 4; nt++) {
            const int col = wn * 32 + nt * 8 + qcol;
            float x0 = c[mt][nt][0] * zi0;
            float x1 = c[mt][nt][1] * zi0;
            float x2 = c[mt][nt][2] * zi1;
            float x3 = c[mt][nt][3] * zi1;
            float2 v0, v1;
            v0.x = x0 > 0.f ? x0 : expm1f(x0);
            v0.y = x1 > 0.f ? x1 : expm1f(x1);
            v1.x = x2 > 0.f ? x2 : expm1f(x2);
            v1.y = x3 > 0.f ? x3 : expm1f(x3);
            *(float2*)(op0 + col) = v0;
            *(float2*)(op1 + col) = v1;
        }
    }
}

// ---------------------------------------------------------------------------
extern "C" void kernel_launch(void* const* d_in, const int* in_sizes, int n_in,
                              void* d_out, int out_size) {
    const float* h = nullptr; const int* adj = nullptr;
    const float* W = nullptr; const float* a = nullptr;
    for (int i = 0; i < n_in; i++) {
        switch (in_sizes[i]) {
            case 4194304:  h   = (const float*)d_in[i]; break;
            case 33554432: adj = (const int*)d_in[i];   break;
            case 32768:    W   = (const float*)d_in[i]; break;
            case 256:      a   = (const float*)d_in[i]; break;
        }
    }
    float* out = (float*)d_out;

    static bool attr_set = false;
    if (!attr_set) {
        cudaFuncSetAttribute(k_wh, cudaFuncAttributeMaxDynamicSharedMemorySize,
                             WH_DSMEM);
        cudaFuncSetAttribute(k_attn, cudaFuncAttributeMaxDynamicSharedMemorySize,
                             ATT_DSMEM);
        attr_set = true;
    }

    k_wh<<<BN / 128, 256, WH_DSMEM>>>(h, W, a);
    k_attn<<<dim3(NN / 64, BB), 256, ATT_DSMEM>>>(adj, out);
}

// round 12
// speedup vs baseline: 4.7725x; 1.0320x over previous
#include <cuda_runtime.h>
#include <cuda_fp16.h>
#include <cstdint>
#include <math.h>

#define BB 8
#define NN 2048
#define FIN 256
#define FOUT 128
#define BN (BB*NN)   // 16384 rows total

#define JT 64                     // j-tile (K of the attn mma loop)
#define NTILES (NN/JT)            // 32
#define STRIDE 72                 // b16 elems per smem row (144 B) - conflict-free ldmatrix
#define TILE_BYTES (128*STRIDE*2)          // 18432 (128-row tile)

#define ATT_A_BYTES (64*STRIDE*2)          // 9216  (64-row A tile)
#define ATT_B_BYTES (128*STRIDE*2)         // 18432 (128-row B tile)
#define ATT_STAGE (ATT_A_BYTES + ATT_B_BYTES)   // 27648
#define ATT_DSMEM (2*ATT_STAGE)            // 55296

#define WT_STRIDE 264                      // halfs per s_W row (528 B), LDSM conflict-free
#define WT_BYTES (FOUT*WT_STRIDE*2)        // 67584
#define WH_DSMEM (2*TILE_BYTES + WT_BYTES) // A0, A1, s_W = 104448

// Scratch (static device arrays; allocation is forbidden)
__device__ __half g_WhT[(size_t)BB * FOUT * NN];       // [b][f][n] Wh fp16 (single)
__device__ float  g_s1[BN], g_s2[BN];

// ---------------------------------------------------------------------------
__device__ __forceinline__ uint32_t smem_u32(const void* p) {
    uint32_t a;
    asm("{ .reg .u64 t; cvta.to.shared.u64 t, %1; cvt.u32.u64 %0, t; }"
        : "=r"(a) : "l"(p));
    return a;
}

#define LDSM_X4(r, addr) \
    asm volatile("ldmatrix.sync.aligned.m8n8.x4.shared.b16 {%0,%1,%2,%3}, [%4];" \
        : "=r"((r)[0]), "=r"((r)[1]), "=r"((r)[2]), "=r"((r)[3]) : "r"(addr))

#define CP_ASYNC16(dst, src) \
    asm volatile("cp.async.cg.shared.global [%0], [%1], 16;" :: "r"(dst), "l"(src) : "memory")
#define CP_COMMIT() asm volatile("cp.async.commit_group;" ::: "memory")
#define CP_WAIT0()  asm volatile("cp.async.wait_group 0;" ::: "memory")

__device__ __forceinline__ void mma16816(float* c, const uint32_t* a, const uint32_t* b) {
    asm volatile(
        "mma.sync.aligned.m16n8k16.row.col.f32.f16.f16.f32 "
        "{%0,%1,%2,%3}, {%4,%5,%6,%7}, {%8,%9}, {%0,%1,%2,%3};"
        : "+f"(c[0]), "+f"(c[1]), "+f"(c[2]), "+f"(c[3])
        : "r"(a[0]), "r"(a[1]), "r"(a[2]), "r"(a[3]), "r"(b[0]), "r"(b[1]));
}

__device__ __forceinline__ uint4 pack8h(__half2 a, __half2 b, __half2 c, __half2 d) {
    uint4 v;
    v.x = *(unsigned*)&a; v.y = *(unsigned*)&b;
    v.z = *(unsigned*)&c; v.w = *(unsigned*)&d;
    return v;
}

// ---------------------------------------------------------------------------
// Kernel 1: Wh = h @ W via HMMA, single fp16 product. Self-contained:
// prologue transposes W to fp16 smem + computes u1/u2 (fp32 exact).
// Fused exact scores (s1 = h.u1, s2 = h.u2) + writes; WhT fp16 out.
// ---------------------------------------------------------------------------
__global__ __launch_bounds__(256) void k_wh(const float* __restrict__ h,
                                            const float* __restrict__ W,
                                            const float* __restrict__ a) {
    extern __shared__ char wsm[];
    __shared__ float s_u1[FIN], s_u2[FIN];
    __shared__ float s_a[2 * FOUT];

    const int t = threadIdx.x, w = t >> 5, lane = t & 31;
    const int bx = blockIdx.x;
    const size_t row0 = (size_t)bx * 128;
    const int b  = bx >> 4;
    const int n0 = (bx & 15) * 128;

    char* A0  = wsm;                       // A double buffer
    char* s_Wc = wsm + 2 * TILE_BYTES;     // persistent W^T fp16
    __half* sW = (__half*)s_Wc;
    const uint32_t sWu = smem_u32(s_Wc);

    // ---- prologue: load a; transpose W -> fp16 smem; u1/u2 fp32 ----
    s_a[t] = a[t];
    __syncthreads();
    {
        const int kk = w * 32;     // warp's 32 k-rows
#pragma unroll 4
        for (int i = 0; i < 32; i++) {
            const int k = kk + i;
            float wv[4];
#pragma unroll
            for (int p = 0; p < 4; p++) wv[p] = W[k * FOUT + lane + p * 32];
            float u1p = 0.f, u2p = 0.f;
#pragma unroll
            for (int p = 0; p < 4; p++) {
                u1p += wv[p] * s_a[lane + p * 32];
                u2p += wv[p] * s_a[FOUT + lane + p * 32];
            }
#pragma unroll
            for (int p = 0; p < 4; p++)
                sW[(lane + p * 32) * WT_STRIDE + k] = __float2half_rn(wv[p]);
#pragma unroll
            for (int o = 16; o; o >>= 1) {
                u1p += __shfl_xor_sync(0xFFFFFFFFu, u1p, o);
                u2p += __shfl_xor_sync(0xFFFFFFFFu, u2p, o);
            }
            if (lane == 0) { s_u1[k] = u1p; s_u2[k] = u2p; }
        }
    }

    const int row = t >> 1, fq = t & 1;   // staging role: row 0..127, k half
    const float* __restrict__ hrow = h + (row0 + row) * (size_t)FIN + fq * 32;

    const int wm = w & 1, wn = w >> 1;
    const uint32_t aRow = (uint32_t)((wm * 64 + (lane & 15)) * (STRIDE * 2) + (lane >> 4) * 16);
    const uint32_t bRowW = (uint32_t)((wn * 32 + (lane & 15)) * (WT_STRIDE * 2) + (lane >> 4) * 16);

    float c[4][4][4];
#pragma unroll
    for (int mt = 0; mt < 4; mt++)
#pragma unroll
        for (int nt = 0; nt < 4; nt++)
#pragma unroll
            for (int r = 0; r < 4; r++) c[mt][nt][r] = 0.f;

    float s1p = 0.f, s2p = 0.f;

    // prefetch h chunk 0
    float4 hv[8];
    {
        const float4* hp = (const float4*)(hrow);
#pragma unroll
        for (int g = 0; g < 8; g++) hv[g] = hp[g];
    }
    __syncthreads();   // s_W, s_u ready

    for (int kc = 0; kc < 4; kc++) {
        const int k0 = kc * 64;
        const int s = kc & 1;
        char* A_t = A0 + s * TILE_BYTES;

        // ---- score partials + convert/store A (fp16) from prefetched h ----
        {
            const float4* u1v = (const float4*)&s_u1[k0 + fq * 32];
            const float4* u2v = (const float4*)&s_u2[k0 + fq * 32];
#pragma unroll
            for (int g = 0; g < 8; g++) {
                const float4 u1 = u1v[g], u2 = u2v[g];
                s1p += hv[g].x * u1.x + hv[g].y * u1.y + hv[g].z * u1.z + hv[g].w * u1.w;
                s2p += hv[g].x * u2.x + hv[g].y * u2.y + hv[g].z * u2.z + hv[g].w * u2.w;
            }
            char* ap = A_t + row * (STRIDE * 2) + fq * 64;
#pragma unroll
            for (int g = 0; g < 4; g++) {
                const float4 v0 = hv[2 * g], v1 = hv[2 * g + 1];
                *(uint4*)(ap + g * 16) = pack8h(__floats2half2_rn(v0.x, v0.y),
                                                __floats2half2_rn(v0.z, v0.w),
                                                __floats2half2_rn(v1.x, v1.y),
                                                __floats2half2_rn(v1.z, v1.w));
            }
        }
        __syncthreads();

        // ---- prefetch next h chunk under the mma ----
        if (kc < 3) {
            const float4* hp = (const float4*)(hrow + (kc + 1) * 64);
#pragma unroll
            for (int g = 0; g < 8; g++) hv[g] = hp[g];
        }

        // ---- mma: 4 k-steps of 16, 1 product; B from persistent s_W ----
        const uint32_t sA = smem_u32(A_t);
#pragma unroll
        for (int ks = 0; ks < 4; ks++) {
            const uint32_t kOffA = ks * 32;
            const uint32_t kOffB = (uint32_t)(k0 * 2 + ks * 32);
            uint32_t a4[4][4], b4[4][2];
#pragma unroll
            for (int mt = 0; mt < 4; mt++) {
                const uint32_t mOff = aRow + mt * 16 * (STRIDE * 2) + kOffA;
                LDSM_X4(a4[mt], sA + mOff);
            }
#pragma unroll
            for (int np = 0; np < 2; np++) {
                const uint32_t nOff = bRowW + np * 16 * (WT_STRIDE * 2) + kOffB;
                uint32_t q[4];
                LDSM_X4(q, sWu + nOff);
                b4[2*np][0] = q[0]; b4[2*np][1] = q[2];
                b4[2*np+1][0] = q[1]; b4[2*np+1][1] = q[3];
            }
#pragma unroll
            for (int mt = 0; mt < 4; mt++)
#pragma unroll
                for (int nt = 0; nt < 4; nt++)
                    mma16816(c[mt][nt], a4[mt], b4[nt]);
        }
    }

    // ---- scores: pair-reduce and write ----
    s1p += __shfl_xor_sync(0xFFFFFFFFu, s1p, 1);
    s2p += __shfl_xor_sync(0xFFFFFFFFu, s2p, 1);
    if (fq == 0) {
        const size_t r = row0 + row;
        g_s1[r] = s1p;
        g_s2[r] = s2p;
    }

    // ---- WhT fp16 transposed store via smem (reuses A buffers) ----
    __syncthreads();
    __half* s_T = (__half*)wsm;   // [128 f][136]
    const int qrow = lane >> 2, qcol = 2 * (lane & 3);
#pragma unroll
    for (int mt = 0; mt < 4; mt++) {
        const int r0 = wm * 64 + mt * 16 + qrow;
        const int r1 = r0 + 8;
#pragma unroll
        for (int nt = 0; nt < 4; nt++) {
            const int c0 = wn * 32 + nt * 8 + qcol;
            s_T[c0 * 136 + r0]       = __float2half_rn(c[mt][nt][0]);
            s_T[(c0 + 1) * 136 + r0] = __float2half_rn(c[mt][nt][1]);
            s_T[c0 * 136 + r1]       = __float2half_rn(c[mt][nt][2]);
            s_T[(c0 + 1) * 136 + r1] = __float2half_rn(c[mt][nt][3]);
        }
    }
    __syncthreads();
    {
        const int f = t >> 1, part = t & 1;
        const uint4* src = (const uint4*)&s_T[f * 136 + part * 64];
        uint4* dst = (uint4*)&g_WhT[((size_t)(b * FOUT + f)) * NN + n0 + part * 64];
#pragma unroll
        for (int i = 0; i < 8; i++) dst[i] = src[i];
    }
}

// ---------------------------------------------------------------------------
// Kernel 2: fused attention, 256 threads, CTA = 64 i x 128 f, 2 CTAs/SM.
// Weights: SIMD pair hmax2(hmul2(E1,e2), hmul2(F1,f2)), masked by 32-bit AND.
// Z comes free from an extra ones-column HMMA on warps wn==0.
// ---------------------------------------------------------------------------
__global__ __launch_bounds__(256, 2) void k_attn(const int* __restrict__ adj,
                                                 float* __restrict__ out) {
    extern __shared__ char dsm[];
    __shared__ float s_Zc[64];
    __shared__ __half s_E2h[NN];          // 4 KB
    __shared__ __half s_F2h[NN];          // 4 KB
    __shared__ float s_red[8];

    const int t = threadIdx.x, w = t >> 5, lane = t & 31;
    const int b = blockIdx.y, i0 = blockIdx.x * 64;
    const size_t bn = (size_t)b * NN;
    const uint32_t dsm_u = smem_u32(dsm);

    // ---- prologue: read s2 (8 per thread), reduce M2, build s_E2h/s_F2h ----
    const float4 v2a = ((const float4*)(g_s2 + bn))[2 * t];
    const float4 v2b = ((const float4*)(g_s2 + bn))[2 * t + 1];
    float mloc = fmaxf(fmaxf(fmaxf(v2a.x, v2a.y), fmaxf(v2a.z, v2a.w)),
                       fmaxf(fmaxf(v2b.x, v2b.y), fmaxf(v2b.z, v2b.w)));
#pragma unroll
    for (int o = 16; o; o >>= 1) mloc = fmaxf(mloc, __shfl_xor_sync(0xFFFFFFFFu, mloc, o));
    if (lane == 0) s_red[w] = mloc;
    __syncthreads();
    float M2 = s_red[0];
#pragma unroll
    for (int i = 1; i < 8; i++) M2 = fmaxf(M2, s_red[i]);

    {
        const float sv[8] = { v2a.x, v2a.y, v2a.z, v2a.w, v2b.x, v2b.y, v2b.z, v2b.w };
        uint4 ev, fv;
#pragma unroll
        for (int k = 0; k < 4; k++) {
            const float d0 = sv[2*k] - M2, d1 = sv[2*k+1] - M2;
            ((__half2*)&ev)[k] = __floats2half2_rn(expf(d0), expf(d1));
            ((__half2*)&fv)[k] = __floats2half2_rn(expf(0.2f * d0), expf(0.2f * d1));
        }
        *(uint4*)&s_E2h[8 * t] = ev;
        *(uint4*)&s_F2h[8 * t] = fv;
    }

    // ---- c-phase mapping ----
    const int row = t >> 2;           // 0..63
    const int jq  = (t & 3) * 16;

    const float s1r = g_s1[bn + i0 + row];
    const float xm  = s1r + M2;
    const float m   = xm > 0.f ? xm : 0.2f * xm;
    const __half2 E1E1 = __half2half2(__float2half_rn(expf(xm - m)));
    const __half2 F1F1 = __half2half2(__float2half_rn(expf(0.2f * xm - m)));
    const int* __restrict__ adjrow = adj + (bn + i0 + row) * (size_t)NN;

    // ---- B-copy mapping ----
    const int fB = t >> 1, partB = t & 1;
    const __half* __restrict__ whpB = g_WhT + ((size_t)b * FOUT + fB) * NN + partB * 32;
    const uint32_t bDst = (uint32_t)(ATT_A_BYTES + fB * (STRIDE * 2) + partB * 64);

    // ---- mma-phase addressing: warp tile 32(m) x 32(n) ----
    const int wm = w & 1, wn = w >> 1;
    const uint32_t aRow = (uint32_t)((wm * 32 + (lane & 15)) * (STRIDE * 2) + (lane >> 4) * 16);
    const uint32_t bRow = (uint32_t)(ATT_A_BYTES
                         + (wn * 32 + (lane & 15)) * (STRIDE * 2) + (lane >> 4) * 16);

    float c[2][4][4];
#pragma unroll
    for (int mt = 0; mt < 2; mt++)
#pragma unroll
        for (int nt = 0; nt < 4; nt++)
#pragma unroll
            for (int r = 0; r < 4; r++) c[mt][nt][r] = 0.f;

    // Z accumulators (ones-column mma; only wn==0 warps use them)
    float cz[2][4];
#pragma unroll
    for (int mt = 0; mt < 2; mt++)
#pragma unroll
        for (int r = 0; r < 4; r++) cz[mt][r] = 0.f;
    const uint32_t ones_b[2] = { 0x3C003C00u, 0x3C003C00u };

    // B tile 0 via cp.async; adj tile 0 into regs
    {
        const uint32_t bd = dsm_u + bDst;
        CP_ASYNC16(bd,      whpB);
        CP_ASYNC16(bd + 16, whpB + 8);
        CP_ASYNC16(bd + 32, whpB + 16);
        CP_ASYNC16(bd + 48, whpB + 24);
        CP_COMMIT();
    }
    int4 radj[4];
    {
        const int4* am = (const int4*)(adjrow + jq);
#pragma unroll
        for (int q = 0; q < 4; q++) radj[q] = am[q];
    }
    __syncthreads();   // s_E2h/s_F2h ready

    for (int jt = 0; jt < NTILES; jt++) {
        const int s = jt & 1;
        char* A_t = dsm + s * ATT_STAGE;
        const int jg0 = jt * JT + jq;

        // ---- build c tile (16 weights = 8 half2), SIMD max identity ----
        {
            const uint4 e0 = *(const uint4*)&s_E2h[jg0];
            const uint4 e1 = *(const uint4*)&s_E2h[jg0 + 8];
            const uint4 f0 = *(const uint4*)&s_F2h[jg0];
            const uint4 f1 = *(const uint4*)&s_F2h[jg0 + 8];
            const unsigned ea[8] = { e0.x, e0.y, e0.z, e0.w, e1.x, e1.y, e1.z, e1.w };
            const unsigned fa[8] = { f0.x, f0.y, f0.z, f0.w, f1.x, f1.y, f1.z, f1.w };
            unsigned cw[8];
#pragma unroll
            for (int q = 0; q < 4; q++) {
                const int4 mv = radj[q];
                // pair 2q: (mv.x, mv.y), pair 2q+1: (mv.z, mv.w)
                {
                    __half2 pe = __hmul2(E1E1, *(const __half2*)&ea[2*q]);
                    __half2 pf = __hmul2(F1F1, *(const __half2*)&fa[2*q]);
                    __half2 cm = __hmax2(pe, pf);
                    unsigned msk = (mv.x > 0 ? 0x0000FFFFu : 0u)
                                 | (mv.y > 0 ? 0xFFFF0000u : 0u);
                    cw[2*q] = (*(unsigned*)&cm) & msk;
                }
                {
                    __half2 pe = __hmul2(E1E1, *(const __half2*)&ea[2*q+1]);
                    __half2 pf = __hmul2(F1F1, *(const __half2*)&fa[2*q+1]);
                    __half2 cm = __hmax2(pe, pf);
                    unsigned msk = (mv.z > 0 ? 0x0000FFFFu : 0u)
                                 | (mv.w > 0 ? 0xFFFF0000u : 0u);
                    cw[2*q+1] = (*(unsigned*)&cm) & msk;
                }
            }
            char* ap = A_t + row * (STRIDE * 2) + jq * 2;
            uint4 v0, v1;
            v0.x = cw[0]; v0.y = cw[1]; v0.z = cw[2]; v0.w = cw[3];
            v1.x = cw[4]; v1.y = cw[5]; v1.z = cw[6]; v1.w = cw[7];
            *(uint4*)(ap)      = v0;
            *(uint4*)(ap + 16) = v1;
        }

        CP_WAIT0();        // this tile's B arrived (this thread's copies)
        __syncthreads();   // everyone's B + A visible; prev mma done

        // ---- issue next B (cp.async into other stage) + prefetch adj ----
        if (jt + 1 < NTILES) {
            const int jg1B = (jt + 1) * JT;
            const uint32_t bd = dsm_u + (s ^ 1) * ATT_STAGE + bDst;
            const __half* src = whpB + jg1B;
            CP_ASYNC16(bd,      src);
            CP_ASYNC16(bd + 16, src + 8);
            CP_ASYNC16(bd + 32, src + 16);
            CP_ASYNC16(bd + 48, src + 24);
            const int4* am = (const int4*)(adjrow + (jt + 1) * JT + jq);
#pragma unroll
            for (int q = 0; q < 4; q++) radj[q] = am[q];
        }
        CP_COMMIT();

        // ---- mma: 4 k-steps, warp tile 32x32 (+ ones column on wn==0) ----
        const uint32_t sA = dsm_u + s * ATT_STAGE;
#pragma unroll
        for (int ks = 0; ks < 4; ks++) {
            const uint32_t kOff = ks * 32;
            uint32_t a4[2][4], b4[4][2];
#pragma unroll
            for (int mt = 0; mt < 2; mt++) {
                const uint32_t mOff = aRow + mt * 16 * (STRIDE * 2) + kOff;
                LDSM_X4(a4[mt], sA + mOff);
            }
#pragma unroll
            for (int np = 0; np < 2; np++) {
                const uint32_t nOff = bRow + np * 16 * (STRIDE * 2) + kOff;
                uint32_t q[4];
                LDSM_X4(q, sA + nOff);
                b4[2*np][0] = q[0]; b4[2*np][1] = q[2];
                b4[2*np+1][0] = q[1]; b4[2*np+1][1] = q[3];
            }
#pragma unroll
            for (int mt = 0; mt < 2; mt++)
#pragma unroll
                for (int nt = 0; nt < 4; nt++)
                    mma16816(c[mt][nt], a4[mt], b4[nt]);
            if (wn == 0) {
#pragma unroll
                for (int mt = 0; mt < 2; mt++)
                    mma16816(cz[mt], a4[mt], ones_b);
            }
        }
    }

    // ---- Z from ones-column accumulators ----
    const int qrow = lane >> 2, qcol = 2 * (lane & 3);
    if (wn == 0 && (lane & 3) == 0) {
#pragma unroll
        for (int mt = 0; mt < 2; mt++) {
            s_Zc[wm * 32 + mt * 16 + qrow]     = cz[mt][0];
            s_Zc[wm * 32 + mt * 16 + qrow + 8] = cz[mt][2];
        }
    }
    __syncthreads();

    // ---- normalize + ELU + store ----
#pragma unroll
    for (int mt = 0; mt < 2; mt++) {
        const int r0 = wm * 32 + mt * 16 + qrow;
        const int r1 = r0 + 8;
        const float zi0 = 1.0f / s_Zc[r0];
        const float zi1 = 1.0f / s_Zc[r1];
        float* op0 = out + (bn + i0 + r0) * (size_t)FOUT;
        float* op1 = out + (bn + i0 + r1) * (size_t)FOUT;
#pragma unroll
        for (int nt = 0; nt < 4; nt++) {
            const int col = wn * 32 + nt * 8 + qcol;
            float x0 = c[mt][nt][0] * zi0;
            float x1 = c[mt][nt][1] * zi0;
            float x2 = c[mt][nt][2] * zi1;
            float x3 = c[mt][nt][3] * zi1;
            float2 v0, v1;
            v0.x = x0 > 0.f ? x0 : expm1f(x0);
            v0.y = x1 > 0.f ? x1 : expm1f(x1);
            v1.x = x2 > 0.f ? x2 : expm1f(x2);
            v1.y = x3 > 0.f ? x3 : expm1f(x3);
            *(float2*)(op0 + col) = v0;
            *(float2*)(op1 + col) = v1;
        }
    }
}

// ---------------------------------------------------------------------------
extern "C" void kernel_launch(void* const* d_in, const int* in_sizes, int n_in,
                              void* d_out, int out_size) {
    const float* h = nullptr; const int* adj = nullptr;
    const float* W = nullptr; const float* a = nullptr;
    for (int i = 0; i < n_in; i++) {
        switch (in_sizes[i]) {
            case 4194304:  h   = (const float*)d_in[i]; break;
            case 33554432: adj = (const int*)d_in[i];   break;
            case 32768:    W   = (const float*)d_in[i]; break;
            case 256:      a   = (const float*)d_in[i]; break;
        }
    }
    float* out = (float*)d_out;

    static bool attr_set = false;
    if (!attr_set) {
        cudaFuncSetAttribute(k_wh, cudaFuncAttributeMaxDynamicSharedMemorySize,
                             WH_DSMEM);
        cudaFuncSetAttribute(k_attn, cudaFuncAttributeMaxDynamicSharedMemorySize,
                             ATT_DSMEM);
        attr_set = true;
    }

    k_wh<<<BN / 128, 256, WH_DSMEM>>>(h, W, a);
    k_attn<<<dim3(NN / 64, BB), 256, ATT_DSMEM>>>(adj, out);
}